// round 1
// baseline (speedup 1.0000x reference)
#include <cuda_runtime.h>
#include <math.h>

#define NN 10000
#define EE 320000

// ---------------- device scratch (no allocation allowed) ----------------
__device__ float g_bufA[NN * 128];
__device__ float g_bufB[NN * 128];
__device__ float g_bufC[NN * 128];
__device__ float g_af1[NN * 32];
__device__ float g_af2[NN * 32];
__device__ float g_deg[NN];
__device__ float g_dinv[NN];
__device__ unsigned g_keymin, g_keymax;
__device__ unsigned g_hist[16 * 32];       // strided by 32 (128B) to spread LTS
__device__ float g_meanraw[2][32];
__device__ float g_gc[32];
__device__ float g_pool[2][32];            // p1, p2
__device__ float g_A[32 * 16];
__device__ float g_c[16];
__device__ float g_sAcc[2][16];            // s1, s2 sums (pre-mean)
__device__ float g_s0[16];

// ---------------- helpers ----------------
__device__ __forceinline__ unsigned fkey(float f) {
    unsigned u = __float_as_uint(f);
    return (u & 0x80000000u) ? ~u : (u | 0x80000000u);
}
__device__ __forceinline__ float fdec(unsigned k) {
    return (k & 0x80000000u) ? __uint_as_float(k ^ 0x80000000u)
                             : __uint_as_float(~k);
}

// ---------------- reset accumulators ----------------
__global__ void k_reset() {
    int t = threadIdx.x;
    if (t < 16 * 32) g_hist[t] = 0u;
    if (t < 32) {
        g_meanraw[0][t] = 0.f; g_meanraw[1][t] = 0.f;
        g_pool[0][t] = 0.f;    g_pool[1][t] = 0.f;
    }
    if (t < 16) { g_sAcc[0][t] = 0.f; g_sAcc[1][t] = 0.f; }
    if (t == 0) { g_keymin = 0xFFFFFFFFu; g_keymax = 0u; }
}

// ---------------- degree ----------------
__global__ void k_deg_init() {
    int i = blockIdx.x * 256 + threadIdx.x;
    if (i < NN) g_deg[i] = 1.0f;
}
__global__ void k_deg_count(const int* __restrict__ ei) {
    int e = blockIdx.x * 256 + threadIdx.x;
    if (e < EE) atomicAdd(&g_deg[ei[EE + e]], 1.0f);
}
__global__ void k_dinv() {
    int i = blockIdx.x * 256 + threadIdx.x;
    if (i < NN) g_dinv[i] = rsqrtf(g_deg[i]);
}

// ---------------- GCN GEMM: H = relu?(X) @ W ----------------
__global__ void k_gemm(const float* __restrict__ X, const float* __restrict__ W,
                       float* __restrict__ H, int Fin, int Fout, int reluIn) {
    __shared__ float Ws[32 * 128];
    int tid = threadIdx.x;
    int idx = blockIdx.x * 256 + tid;
    int row = idx / Fout;
    int col = idx - row * Fout;
    float acc = 0.f;
    const float* xr = X + (size_t)row * Fin;
    for (int k0 = 0; k0 < Fin; k0 += 32) {
        for (int i = tid; i < 32 * Fout; i += 256)
            Ws[i] = W[(size_t)(k0 + i / Fout) * Fout + (i % Fout)];
        __syncthreads();
        if (row < NN) {
#pragma unroll 8
            for (int k = 0; k < 32; k++) {
                float x = xr[k0 + k];
                if (reluIn) x = fmaxf(x, 0.f);
                acc += x * Ws[k * Fout + col];
            }
        }
        __syncthreads();
    }
    if (row < NN) H[(size_t)row * Fout + col] = acc;
}

// out = h/deg + b  (self-loop term + bias, accumulator init)
__global__ void k_selfinit(const float* __restrict__ H, const float* __restrict__ b,
                           float* __restrict__ out, int Fout) {
    int idx = blockIdx.x * 256 + threadIdx.x;
    if (idx >= NN * Fout) return;
    int row = idx / Fout;
    int f = idx - row * Fout;
    out[idx] = H[idx] * (1.0f / g_deg[row]) + b[f];
}

// edge scatter: out[dst] += dinv[src]*dinv[dst]*h[src]
__global__ void k_scatter(const int* __restrict__ ei, const float* __restrict__ H,
                          float* __restrict__ out, int Fout, int cshift) {
    int t = blockIdx.x * 256 + threadIdx.x;
    int e = t >> cshift;
    if (e >= EE) return;
    int chunks = Fout >> 2;
    int c = t & (chunks - 1);
    int s = ei[e], d = ei[EE + e];
    float coef = g_dinv[s] * g_dinv[d];
    float4 v = *(const float4*)(H + (size_t)s * Fout + c * 4);
    float* o = out + (size_t)d * Fout + c * 4;
    atomicAdd(o + 0, coef * v.x);
    atomicAdd(o + 1, coef * v.y);
    atomicAdd(o + 2, coef * v.z);
    atomicAdd(o + 3, coef * v.w);
}

// ---------------- similarity matrix passes (min/max, histogram) ----------------
// S[i,j] = sum_k af1[i,k]*af2[j,k]; 128x128 tile, 8x8 per thread.
__global__ void k_simpass(const float* __restrict__ A, const float* __restrict__ B,
                          int pass) {
    __shared__ float As[32][132];
    __shared__ float Bs[32][132];
    __shared__ unsigned sh[16];
    int tid = threadIdx.x;
    int i0 = blockIdx.y * 128, j0 = blockIdx.x * 128;
    for (int idx = tid; idx < 128 * 32; idx += 256) {
        int r = idx >> 5, k = idx & 31;
        int ia = i0 + r, jb = j0 + r;
        As[k][r] = (ia < NN) ? A[ia * 32 + k] : 0.f;
        Bs[k][r] = (jb < NN) ? B[jb * 32 + k] : 0.f;
    }
    if (pass && tid < 16) sh[tid] = 0u;
    __syncthreads();
    int tx = tid & 15, ty = tid >> 4;
    float acc[8][8];
#pragma unroll
    for (int r = 0; r < 8; r++)
#pragma unroll
        for (int c = 0; c < 8; c++) acc[r][c] = 0.f;
#pragma unroll 4
    for (int k = 0; k < 32; k++) {
        float4 a0 = *(const float4*)&As[k][ty * 8];
        float4 a1 = *(const float4*)&As[k][ty * 8 + 4];
        float4 b0 = *(const float4*)&Bs[k][tx * 8];
        float4 b1 = *(const float4*)&Bs[k][tx * 8 + 4];
        float av[8] = {a0.x, a0.y, a0.z, a0.w, a1.x, a1.y, a1.z, a1.w};
        float bv[8] = {b0.x, b0.y, b0.z, b0.w, b1.x, b1.y, b1.z, b1.w};
#pragma unroll
        for (int r = 0; r < 8; r++)
#pragma unroll
            for (int c = 0; c < 8; c++) acc[r][c] += av[r] * bv[c];
    }
    int ibase = i0 + ty * 8, jbase = j0 + tx * 8;
    if (pass == 0) {
        float lmin = 3.4e38f, lmax = -3.4e38f;
#pragma unroll
        for (int r = 0; r < 8; r++) {
            if (ibase + r >= NN) continue;
#pragma unroll
            for (int c = 0; c < 8; c++) {
                if (jbase + c >= NN) continue;
                float v = acc[r][c];
                lmin = fminf(lmin, v);
                lmax = fmaxf(lmax, v);
            }
        }
        for (int o = 16; o; o >>= 1) {
            lmin = fminf(lmin, __shfl_down_sync(0xffffffffu, lmin, o));
            lmax = fmaxf(lmax, __shfl_down_sync(0xffffffffu, lmax, o));
        }
        if ((tid & 31) == 0) {
            atomicMin(&g_keymin, fkey(lmin));
            atomicMax(&g_keymax, fkey(lmax));
        }
    } else {
        float lo = fdec(g_keymin), hi = fdec(g_keymax);
        float inv = 1.0f / ((hi - lo) + 1e-12f);
        unsigned long long cl = 0ull, ch = 0ull;
#pragma unroll
        for (int r = 0; r < 8; r++) {
            if (ibase + r >= NN) continue;
#pragma unroll
            for (int c = 0; c < 8; c++) {
                if (jbase + c >= NN) continue;
                float q = (acc[r][c] - lo) * inv;
                int b = (int)(q * 16.0f);
                b = min(max(b, 0), 15);
                if (b < 8) cl += 1ull << (b * 8);
                else       ch += 1ull << ((b - 8) * 8);
            }
        }
#pragma unroll
        for (int b = 0; b < 16; b++) {
            unsigned v = (unsigned)((b < 8 ? (cl >> (b * 8)) : (ch >> ((b - 8) * 8))) & 0xFFull);
            for (int o = 16; o; o >>= 1) v += __shfl_down_sync(0xffffffffu, v, o);
            if ((tid & 31) == 0 && v) atomicAdd(&sh[b], v);
        }
        __syncthreads();
        if (tid < 16 && sh[tid]) atomicAdd(&g_hist[tid * 32], sh[tid]);
    }
}

// ---------------- attention ----------------
__global__ void k_colmean(const float* __restrict__ X, int g) {
    int lane = threadIdx.x & 31;
    int w = (blockIdx.x * blockDim.x + threadIdx.x) >> 5;
    int nw = (gridDim.x * blockDim.x) >> 5;
    float acc = 0.f;
    for (int n = w; n < NN; n += nw) acc += X[n * 32 + lane];
    atomicAdd(&g_meanraw[g][lane], acc);
}
__global__ void k_gc(const float* __restrict__ att_w, int g) {
    int j = threadIdx.x;  // 32 threads
    float acc = 0.f;
    const float invN = 1.0f / NN;
    for (int f = 0; f < 32; f++) acc += (g_meanraw[g][f] * invN) * att_w[f * 32 + j];
    g_gc[j] = tanhf(acc);
}
__global__ void k_pool(const float* __restrict__ X, int g) {
    int lane = threadIdx.x & 31;
    int w = (blockIdx.x * blockDim.x + threadIdx.x) >> 5;
    int nw = (gridDim.x * blockDim.x) >> 5;
    float gcv = g_gc[lane];
    float acc = 0.f;
    for (int n = w; n < NN; n += nw) {
        float x = X[n * 32 + lane];
        float p = x * gcv;
        for (int o = 16; o; o >>= 1) p += __shfl_xor_sync(0xffffffffu, p, o);
        float sig = 1.0f / (1.0f + expf(-p));
        acc += x * sig;
    }
    atomicAdd(&g_pool[g][lane], acc);
}

// ---------------- tensor network ----------------
// A[f,k] = sum_g tn_w[f,g,k]*e2[g] + tn_wb[k,f];  c[k] = tn_wb[k,32:]·e2 + bias[k]
__global__ void k_tnprep(const float* __restrict__ tn_w, const float* __restrict__ tn_wb,
                         const float* __restrict__ tn_bias, int ge2) {
    int t = threadIdx.x;  // 512 threads
    const float* e2 = g_pool[ge2];
    if (t < 512) {
        int f = t >> 4, k = t & 15;
        float acc = tn_wb[k * 64 + f];
        for (int gg = 0; gg < 32; gg++) acc += tn_w[f * 512 + gg * 16 + k] * e2[gg];
        g_A[f * 16 + k] = acc;
    }
    if (t < 16) {
        float acc = tn_bias[t];
        for (int gg = 0; gg < 32; gg++) acc += tn_wb[t * 64 + 32 + gg] * e2[gg];
        g_c[t] = acc;
    }
}
__global__ void k_s0(int ge1) {
    int k = threadIdx.x;
    if (k >= 16) return;
    const float* e1 = g_pool[ge1];
    float acc = g_c[k];
    for (int f = 0; f < 32; f++) acc += e1[f] * g_A[f * 16 + k];
    g_s0[k] = fmaxf(acc, 0.f);
}
__global__ void k_tnnodes(const float* __restrict__ X, int slot) {
    int lane = threadIdx.x & 31;
    int w = (blockIdx.x * blockDim.x + threadIdx.x) >> 5;
    int nw = (gridDim.x * blockDim.x) >> 5;
    float acc = 0.f;
    for (int n = w; n < NN; n += nw) {
        float x = X[n * 32 + lane];
        float v = (lane < 16) ? g_c[lane] : 0.f;
#pragma unroll
        for (int f = 0; f < 32; f++) {
            float xf = __shfl_sync(0xffffffffu, x, f);
            if (lane < 16) v += xf * g_A[f * 16 + lane];
        }
        if (lane < 16) acc += fmaxf(v, 0.f);
    }
    if (lane < 16) atomicAdd(&g_sAcc[slot][lane], acc);
}

// ---------------- final MLP head ----------------
__global__ void k_final(const float* __restrict__ fc1_w, const float* __restrict__ fc1_b,
                        const float* __restrict__ fc2_w, const float* __restrict__ fc2_b,
                        float* __restrict__ out) {
    if (threadIdx.x != 0) return;
    float sc[64];
    const float invN = 1.0f / NN;
    for (int k = 0; k < 16; k++) {
        sc[k]      = g_s0[k];
        sc[16 + k] = g_sAcc[0][k] * invN;
        sc[32 + k] = g_sAcc[1][k] * invN;
    }
    float hf[16], hsum = 0.f;
    for (int b = 0; b < 16; b++) {
        unsigned c = g_hist[b * 32];
        if (c > 16777216u) c = 16777216u;  // emulate f32 +1.0 saturation at 2^24
        hf[b] = (float)c;
        hsum += hf[b];
    }
    for (int b = 0; b < 16; b++) sc[48 + b] = hf[b] / hsum;
    float o2 = fc2_b[0];
    for (int j = 0; j < 16; j++) {
        float a = fc1_b[j];
        for (int i = 0; i < 64; i++) a += sc[i] * fc1_w[i * 16 + j];
        a = fmaxf(a, 0.f);
        o2 += a * fc2_w[j];
    }
    out[0] = 1.0f / (1.0f + expf(-o2));
}

// ---------------- host driver ----------------
static void conv_pass(const float* feat, const int* ei, float* af,
                      const float* W1, const float* b1,
                      const float* W2, const float* b2,
                      const float* W3, const float* b3,
                      float* bufA, float* bufB, float* bufC) {
    k_deg_init<<<(NN + 255) / 256, 256>>>();
    k_deg_count<<<(EE + 255) / 256, 256>>>(ei);
    k_dinv<<<(NN + 255) / 256, 256>>>();
    // Layer 1: 128 -> 128, relu folded into next gemm's read
    k_gemm<<<(NN * 128 + 255) / 256, 256>>>(feat, W1, bufA, 128, 128, 0);
    k_selfinit<<<(NN * 128 + 255) / 256, 256>>>(bufA, b1, bufB, 128);
    k_scatter<<<(EE * 32 + 255) / 256, 256>>>(ei, bufA, bufB, 128, 5);
    // Layer 2: 128 -> 64
    k_gemm<<<(NN * 64 + 255) / 256, 256>>>(bufB, W2, bufA, 128, 64, 1);
    k_selfinit<<<(NN * 64 + 255) / 256, 256>>>(bufA, b2, bufC, 64);
    k_scatter<<<(EE * 16 + 255) / 256, 256>>>(ei, bufA, bufC, 64, 4);
    // Layer 3: 64 -> 32 (no relu on output)
    k_gemm<<<(NN * 32 + 255) / 256, 256>>>(bufC, W3, bufA, 64, 32, 1);
    k_selfinit<<<(NN * 32 + 255) / 256, 256>>>(bufA, b3, af, 32);
    k_scatter<<<(EE * 8 + 255) / 256, 256>>>(ei, bufA, af, 32, 3);
}

extern "C" void kernel_launch(void* const* d_in, const int* in_sizes, int n_in,
                              void* d_out, int out_size) {
    const float* feat1 = (const float*)d_in[0];
    const float* feat2 = (const float*)d_in[1];
    const int* ei1 = (const int*)d_in[2];
    const int* ei2 = (const int*)d_in[3];
    const float* W1 = (const float*)d_in[4];
    const float* b1 = (const float*)d_in[5];
    const float* W2 = (const float*)d_in[6];
    const float* b2 = (const float*)d_in[7];
    const float* W3 = (const float*)d_in[8];
    const float* b3 = (const float*)d_in[9];
    const float* att_w = (const float*)d_in[10];
    const float* tn_w = (const float*)d_in[11];
    const float* tn_wb = (const float*)d_in[12];
    const float* tn_bias = (const float*)d_in[13];
    const float* fc1_w = (const float*)d_in[14];
    const float* fc1_b = (const float*)d_in[15];
    const float* fc2_w = (const float*)d_in[16];
    const float* fc2_b = (const float*)d_in[17];
    float* out = (float*)d_out;

    float *bufA, *bufB, *bufC, *af1, *af2;
    cudaGetSymbolAddress((void**)&bufA, g_bufA);
    cudaGetSymbolAddress((void**)&bufB, g_bufB);
    cudaGetSymbolAddress((void**)&bufC, g_bufC);
    cudaGetSymbolAddress((void**)&af1, g_af1);
    cudaGetSymbolAddress((void**)&af2, g_af2);

    k_reset<<<1, 512>>>();

    conv_pass(feat1, ei1, af1, W1, b1, W2, b2, W3, b3, bufA, bufB, bufC);
    conv_pass(feat2, ei2, af2, W1, b1, W2, b2, W3, b3, bufA, bufB, bufC);

    // histogram: pass 0 = min/max, pass 1 = bin
    dim3 hgrid((NN + 127) / 128, (NN + 127) / 128);
    k_simpass<<<hgrid, 256>>>(af1, af2, 0);
    k_simpass<<<hgrid, 256>>>(af1, af2, 1);

    // attention pooling (graph 1 then graph 2; g_gc reused sequentially)
    k_colmean<<<40, 256>>>(af1, 0);
    k_gc<<<1, 32>>>(att_w, 0);
    k_pool<<<40, 256>>>(af1, 0);
    k_colmean<<<40, 256>>>(af2, 1);
    k_gc<<<1, 32>>>(att_w, 1);
    k_pool<<<40, 256>>>(af2, 1);

    // tensor network: prep with e2=p2 -> s0(p1), s1(af1); prep with e2=p1 -> s2(af2)
    k_tnprep<<<1, 512>>>(tn_w, tn_wb, tn_bias, 1);
    k_s0<<<1, 32>>>(0);
    k_tnnodes<<<40, 256>>>(af1, 0);
    k_tnprep<<<1, 512>>>(tn_w, tn_wb, tn_bias, 0);
    k_tnnodes<<<40, 256>>>(af2, 1);

    k_final<<<1, 32>>>(fc1_w, fc1_b, fc2_w, fc2_b, out);
}

// round 2
// speedup vs baseline: 1.7703x; 1.7703x over previous
#include <cuda_runtime.h>
#include <math.h>

#define NN 10000
#define EE 320000
typedef unsigned long long u64;

// ---------------- device scratch ----------------
__device__ float g_H[2][NN * 128];     // gemm output (pre-aggregation)
__device__ float g_X[2][NN * 128];     // aggregated output (next layer input)
__device__ float g_af[2][NN * 32];
__device__ float g_dinv[2][NN];
__device__ int   g_indeg[2][NN];
__device__ int   g_rowstart[2][NN + 1];
__device__ int   g_cursor[2][NN];
__device__ int   g_adj[2][EE];
__device__ unsigned g_keymin, g_keymax;
__device__ unsigned g_hist[16 * 32];
__device__ float g_meanraw[2][32];
__device__ float g_gc[2][32];
__device__ float g_pool[2][32];
__device__ float g_A[2][32 * 16];
__device__ float g_c[2][16];
__device__ float g_sAcc[2][16];
__device__ float g_s0[16];

// ---------------- helpers ----------------
__device__ __forceinline__ unsigned fkey(float f) {
    unsigned u = __float_as_uint(f);
    return (u & 0x80000000u) ? ~u : (u | 0x80000000u);
}
__device__ __forceinline__ float fdec(unsigned k) {
    return (k & 0x80000000u) ? __uint_as_float(k ^ 0x80000000u)
                             : __uint_as_float(~k);
}

// ---------------- reset ----------------
__global__ void k_reset() {
    int t = threadIdx.x;
    for (int i = t; i < 2 * NN; i += 1024)
        ((int*)g_indeg)[i] = 0;
    if (t < 16 * 32) g_hist[t] = 0u;
    if (t < 32) {
        g_meanraw[0][t] = 0.f; g_meanraw[1][t] = 0.f;
        g_pool[0][t] = 0.f;    g_pool[1][t] = 0.f;
    }
    if (t < 16) { g_sAcc[0][t] = 0.f; g_sAcc[1][t] = 0.f; }
    if (t == 0) { g_keymin = 0xFFFFFFFFu; g_keymax = 0u; }
}

// ---------------- CSR build (both graphs) ----------------
__global__ void k_indeg(const int* __restrict__ ei1, const int* __restrict__ ei2) {
    int t = blockIdx.x * 256 + threadIdx.x;
    if (t >= 2 * EE) return;
    int g = t >= EE;
    const int* ei = g ? ei2 : ei1;
    int e = t - g * EE;
    atomicAdd(&g_indeg[g][ei[EE + e]], 1);
}

__global__ void k_scan() {   // grid=2, block=1024
    int g = blockIdx.x, t = threadIdx.x;
    int lane = t & 31, w = t >> 5;
    __shared__ int warpsum[32];
    __shared__ int s_carry;
    if (t == 0) s_carry = 0;
    __syncthreads();
    for (int base = 0; base < NN; base += 1024) {
        int i = base + t;
        int v = (i < NN) ? g_indeg[g][i] : 0;
        int x = v;
#pragma unroll
        for (int o = 1; o < 32; o <<= 1) {
            int y = __shfl_up_sync(0xffffffffu, x, o);
            if (lane >= o) x += y;
        }
        if (lane == 31) warpsum[w] = x;
        __syncthreads();
        if (w == 0) {
            int ws = warpsum[lane];
#pragma unroll
            for (int o = 1; o < 32; o <<= 1) {
                int y = __shfl_up_sync(0xffffffffu, ws, o);
                if (lane >= o) ws += y;
            }
            warpsum[lane] = ws;
        }
        __syncthreads();
        int carry = s_carry;
        int excl = carry + (x - v) + (w ? warpsum[w - 1] : 0);
        if (i < NN) {
            g_rowstart[g][i] = excl;
            g_cursor[g][i] = excl;
            g_dinv[g][i] = rsqrtf((float)v + 1.0f);
        }
        int total = warpsum[31];
        __syncthreads();
        if (t == 0) s_carry = carry + total;
        __syncthreads();
    }
    if (t == 0) g_rowstart[g][NN] = s_carry;
}

__global__ void k_fill(const int* __restrict__ ei1, const int* __restrict__ ei2) {
    int t = blockIdx.x * 256 + threadIdx.x;
    if (t >= 2 * EE) return;
    int g = t >= EE;
    const int* ei = g ? ei2 : ei1;
    int e = t - g * EE;
    int s = ei[e], d = ei[EE + e];
    int pos = atomicAdd(&g_cursor[g][d], 1);
    g_adj[g][pos] = s;
}

// ---------------- GEMM: H = relu?(X) @ W   (z = graph) ----------------
__global__ void k_gemm(const float* __restrict__ X0, const float* __restrict__ X1,
                       const float* __restrict__ W,
                       float* __restrict__ H0, float* __restrict__ H1,
                       int Fin, int Fout, int reluIn) {
    __shared__ float Ws[32 * 128];
    int z = blockIdx.z;
    const float* X = z ? X1 : X0;
    float* H = z ? H1 : H0;
    int tid = threadIdx.x;
    int gpf = Fout >> 2;                       // float4 cols
    int idx = blockIdx.x * 256 + tid;
    int row = idx / gpf;
    int c4 = idx - row * gpf;
    float4 acc = make_float4(0.f, 0.f, 0.f, 0.f);
    const float* xr = X + (size_t)row * Fin;
    for (int k0 = 0; k0 < Fin; k0 += 32) {
        for (int i = tid; i < 32 * gpf; i += 256)
            ((float4*)Ws)[i] = ((const float4*)(W + (size_t)(k0 + i / gpf) * Fout))[i % gpf];
        __syncthreads();
        if (row < NN) {
#pragma unroll 8
            for (int k = 0; k < 32; k++) {
                float x = __ldg(xr + k0 + k);
                if (reluIn) x = fmaxf(x, 0.f);
                float4 w = ((const float4*)Ws)[k * gpf + c4];
                acc.x += x * w.x; acc.y += x * w.y;
                acc.z += x * w.z; acc.w += x * w.w;
            }
        }
        __syncthreads();
    }
    if (row < NN) ((float4*)(H + (size_t)row * Fout))[c4] = acc;
}

// ---------------- gather: O[d] = H[d]/deg + b + sum_in coef*H[s] ----------------
__global__ void k_gather(const float* __restrict__ H0, const float* __restrict__ H1,
                         const float* __restrict__ b,
                         float* __restrict__ O0, float* __restrict__ O1, int Fout) {
    int z = blockIdx.z;
    const float* H = z ? H1 : H0;
    float* O = z ? O1 : O0;
    int gpf = Fout >> 2;
    int idx = blockIdx.x * 256 + threadIdx.x;
    int node = idx / gpf;
    int c = idx - node * gpf;
    if (node >= NN) return;
    int rs = g_rowstart[z][node], re = g_rowstart[z][node + 1];
    float di_d = g_dinv[z][node];
    float invdeg = 1.0f / ((float)(re - rs) + 1.0f);
    float4 hs = ((const float4*)(H + (size_t)node * Fout))[c];
    float4 bb = ((const float4*)b)[c];
    float4 acc;
    acc.x = hs.x * invdeg + bb.x; acc.y = hs.y * invdeg + bb.y;
    acc.z = hs.z * invdeg + bb.z; acc.w = hs.w * invdeg + bb.w;
    for (int e = rs; e < re; e++) {
        int s = __ldg(&g_adj[z][e]);
        float coef = g_dinv[z][s] * di_d;
        float4 v = ((const float4*)(H + (size_t)s * Fout))[c];
        acc.x += coef * v.x; acc.y += coef * v.y;
        acc.z += coef * v.z; acc.w += coef * v.w;
    }
    ((float4*)(O + (size_t)node * Fout))[c] = acc;
}

// ---------------- similarity passes (FFMA2 mainloop) ----------------
__global__ void k_simpass(const float* __restrict__ A, const float* __restrict__ B,
                          int pass) {
    __shared__ float As[32][132];
    __shared__ float Bs[32][132];
    __shared__ unsigned sh[16];
    int tid = threadIdx.x;
    int i0 = blockIdx.y * 128, j0 = blockIdx.x * 128;
    for (int idx = tid; idx < 128 * 32; idx += 256) {
        int r = idx >> 5, k = idx & 31;
        int ia = i0 + r, jb = j0 + r;
        As[k][r] = (ia < NN) ? A[ia * 32 + k] : 0.f;
        Bs[k][r] = (jb < NN) ? B[jb * 32 + k] : 0.f;
    }
    if (pass && tid < 16) sh[tid] = 0u;
    __syncthreads();
    int tx = tid & 15, ty = tid >> 4;
    u64 acc2[8][4];
#pragma unroll
    for (int r = 0; r < 8; r++)
#pragma unroll
        for (int c = 0; c < 4; c++) acc2[r][c] = 0ull;
#pragma unroll 4
    for (int k = 0; k < 32; k++) {
        float4 a0 = *(const float4*)&As[k][ty * 8];
        float4 a1 = *(const float4*)&As[k][ty * 8 + 4];
        const u64* bp = (const u64*)&Bs[k][tx * 8];
        u64 bv[4];
        bv[0] = bp[0]; bv[1] = bp[1]; bv[2] = bp[2]; bv[3] = bp[3];
        float av[8] = {a0.x, a0.y, a0.z, a0.w, a1.x, a1.y, a1.z, a1.w};
        u64 aa[8];
#pragma unroll
        for (int r = 0; r < 8; r++)
            asm("mov.b64 %0, {%1, %1};" : "=l"(aa[r]) : "r"(__float_as_uint(av[r])));
#pragma unroll
        for (int r = 0; r < 8; r++)
#pragma unroll
            for (int c = 0; c < 4; c++)
                asm("fma.rn.f32x2 %0, %1, %2, %0;"
                    : "+l"(acc2[r][c]) : "l"(aa[r]), "l"(bv[c]));
    }
    float acc[8][8];
#pragma unroll
    for (int r = 0; r < 8; r++)
#pragma unroll
        for (int c = 0; c < 4; c++) {
            unsigned lo, hi;
            asm("mov.b64 {%0, %1}, %2;" : "=r"(lo), "=r"(hi) : "l"(acc2[r][c]));
            acc[r][2 * c]     = __uint_as_float(lo);
            acc[r][2 * c + 1] = __uint_as_float(hi);
        }
    int ibase = i0 + ty * 8, jbase = j0 + tx * 8;
    if (pass == 0) {
        float lmin = 3.4e38f, lmax = -3.4e38f;
#pragma unroll
        for (int r = 0; r < 8; r++) {
            if (ibase + r >= NN) continue;
#pragma unroll
            for (int c = 0; c < 8; c++) {
                if (jbase + c >= NN) continue;
                float v = acc[r][c];
                lmin = fminf(lmin, v);
                lmax = fmaxf(lmax, v);
            }
        }
        for (int o = 16; o; o >>= 1) {
            lmin = fminf(lmin, __shfl_down_sync(0xffffffffu, lmin, o));
            lmax = fmaxf(lmax, __shfl_down_sync(0xffffffffu, lmax, o));
        }
        if ((tid & 31) == 0) {
            atomicMin(&g_keymin, fkey(lmin));
            atomicMax(&g_keymax, fkey(lmax));
        }
    } else {
        float lo = fdec(g_keymin), hi = fdec(g_keymax);
        float inv = 1.0f / ((hi - lo) + 1e-12f);
        u64 cl = 0ull, ch = 0ull;
#pragma unroll
        for (int r = 0; r < 8; r++) {
            if (ibase + r >= NN) continue;
#pragma unroll
            for (int c = 0; c < 8; c++) {
                if (jbase + c >= NN) continue;
                float q = (acc[r][c] - lo) * inv;
                int b = (int)(q * 16.0f);
                b = min(max(b, 0), 15);
                if (b < 8) cl += 1ull << (b * 8);
                else       ch += 1ull << ((b - 8) * 8);
            }
        }
#pragma unroll
        for (int b = 0; b < 16; b++) {
            unsigned v = (unsigned)((b < 8 ? (cl >> (b * 8)) : (ch >> ((b - 8) * 8))) & 0xFFull);
            for (int o = 16; o; o >>= 1) v += __shfl_down_sync(0xffffffffu, v, o);
            if ((tid & 31) == 0 && v) atomicAdd(&sh[b], v);
        }
        __syncthreads();
        if (tid < 16 && sh[tid]) atomicAdd(&g_hist[tid * 32], sh[tid]);
    }
}

// ---------------- attention ----------------
__global__ void k_colmean() {
    int z = blockIdx.z;
    const float* X = g_af[z];
    int lane = threadIdx.x & 31;
    int w = (blockIdx.x * blockDim.x + threadIdx.x) >> 5;
    int nw = (gridDim.x * blockDim.x) >> 5;
    float acc = 0.f;
    for (int n = w; n < NN; n += nw) acc += X[n * 32 + lane];
    atomicAdd(&g_meanraw[z][lane], acc);
}
__global__ void k_gc2(const float* __restrict__ att_w) {   // 1 block, 64 threads
    int g = threadIdx.x >> 5, j = threadIdx.x & 31;
    float acc = 0.f;
    const float invN = 1.0f / NN;
    for (int f = 0; f < 32; f++)
        acc += (g_meanraw[g][f] * invN) * att_w[f * 32 + j];
    g_gc[g][j] = tanhf(acc);
}
__global__ void k_pool() {
    int z = blockIdx.z;
    const float* X = g_af[z];
    int lane = threadIdx.x & 31;
    int w = (blockIdx.x * blockDim.x + threadIdx.x) >> 5;
    int nw = (gridDim.x * blockDim.x) >> 5;
    float gcv = g_gc[z][lane];
    float acc = 0.f;
    for (int n = w; n < NN; n += nw) {
        float x = X[n * 32 + lane];
        float p = x * gcv;
        for (int o = 16; o; o >>= 1) p += __shfl_xor_sync(0xffffffffu, p, o);
        float sig = 1.0f / (1.0f + expf(-p));
        acc += x * sig;
    }
    atomicAdd(&g_pool[z][lane], acc);
}

// ---------------- tensor network prep (both slots) + s0 ----------------
// slot 0: e2 = p2 (used for s0 and af1 nodes); slot 1: e2 = p1 (af2 nodes)
__global__ void k_tnprep(const float* __restrict__ tn_w, const float* __restrict__ tn_wb,
                         const float* __restrict__ tn_bias) {   // 1 block, 1024 threads
    int t = threadIdx.x;
    int slot = t >> 9;
    int r = t & 511;
    int f = r >> 4, k = r & 15;
    const float* e2 = g_pool[1 - slot];
    float acc = tn_wb[k * 64 + f];
    for (int gg = 0; gg < 32; gg++)
        acc += tn_w[f * 512 + gg * 16 + k] * e2[gg];
    g_A[slot][f * 16 + k] = acc;
    if (t < 32) {
        int sl = t >> 4, kk = t & 15;
        const float* e2b = g_pool[1 - sl];
        float c = tn_bias[kk];
        for (int gg = 0; gg < 32; gg++)
            c += tn_wb[kk * 64 + 32 + gg] * e2b[gg];
        g_c[sl][kk] = c;
    }
    __syncthreads();
    if (t < 16) {
        float acc2 = g_c[0][t];
        for (int f2 = 0; f2 < 32; f2++)
            acc2 += g_pool[0][f2] * g_A[0][f2 * 16 + t];
        g_s0[t] = fmaxf(acc2, 0.f);
    }
}
__global__ void k_tnnodes() {
    int z = blockIdx.z;                      // graph z uses slot z
    const float* X = g_af[z];
    int lane = threadIdx.x & 31;
    int w = (blockIdx.x * blockDim.x + threadIdx.x) >> 5;
    int nw = (gridDim.x * blockDim.x) >> 5;
    float acc = 0.f;
    for (int n = w; n < NN; n += nw) {
        float x = X[n * 32 + lane];
        float v = (lane < 16) ? g_c[z][lane] : 0.f;
#pragma unroll
        for (int f = 0; f < 32; f++) {
            float xf = __shfl_sync(0xffffffffu, x, f);
            if (lane < 16) v += xf * g_A[z][f * 16 + lane];
        }
        if (lane < 16) acc += fmaxf(v, 0.f);
    }
    if (lane < 16) atomicAdd(&g_sAcc[z][lane], acc);
}

// ---------------- final MLP head ----------------
__global__ void k_final(const float* __restrict__ fc1_w, const float* __restrict__ fc1_b,
                        const float* __restrict__ fc2_w, const float* __restrict__ fc2_b,
                        float* __restrict__ out) {
    if (threadIdx.x != 0) return;
    float sc[64];
    const float invN = 1.0f / NN;
    for (int k = 0; k < 16; k++) {
        sc[k]      = g_s0[k];
        sc[16 + k] = g_sAcc[0][k] * invN;
        sc[32 + k] = g_sAcc[1][k] * invN;
    }
    float hf[16], hsum = 0.f;
    for (int b = 0; b < 16; b++) {
        unsigned c = g_hist[b * 32];
        if (c > 16777216u) c = 16777216u;
        hf[b] = (float)c;
        hsum += hf[b];
    }
    for (int b = 0; b < 16; b++) sc[48 + b] = hf[b] / hsum;
    float o2 = fc2_b[0];
    for (int j = 0; j < 16; j++) {
        float a = fc1_b[j];
        for (int i = 0; i < 64; i++) a += sc[i] * fc1_w[i * 16 + j];
        a = fmaxf(a, 0.f);
        o2 += a * fc2_w[j];
    }
    out[0] = 1.0f / (1.0f + expf(-o2));
}

// ---------------- host driver ----------------
extern "C" void kernel_launch(void* const* d_in, const int* in_sizes, int n_in,
                              void* d_out, int out_size) {
    const float* feat1 = (const float*)d_in[0];
    const float* feat2 = (const float*)d_in[1];
    const int* ei1 = (const int*)d_in[2];
    const int* ei2 = (const int*)d_in[3];
    const float* W1 = (const float*)d_in[4];
    const float* b1 = (const float*)d_in[5];
    const float* W2 = (const float*)d_in[6];
    const float* b2 = (const float*)d_in[7];
    const float* W3 = (const float*)d_in[8];
    const float* b3 = (const float*)d_in[9];
    const float* att_w = (const float*)d_in[10];
    const float* tn_w = (const float*)d_in[11];
    const float* tn_wb = (const float*)d_in[12];
    const float* tn_bias = (const float*)d_in[13];
    const float* fc1_w = (const float*)d_in[14];
    const float* fc1_b = (const float*)d_in[15];
    const float* fc2_w = (const float*)d_in[16];
    const float* fc2_b = (const float*)d_in[17];
    float* out = (float*)d_out;

    float *H0, *H1, *X0, *X1, *af0, *af1;
    cudaGetSymbolAddress((void**)&H0, g_H);   H1 = H0 + NN * 128;
    cudaGetSymbolAddress((void**)&X0, g_X);   X1 = X0 + NN * 128;
    cudaGetSymbolAddress((void**)&af0, g_af); af1 = af0 + NN * 32;

    k_reset<<<1, 1024>>>();

    // CSR build for both graphs
    k_indeg<<<(2 * EE + 255) / 256, 256>>>(ei1, ei2);
    k_scan<<<2, 1024>>>();
    k_fill<<<(2 * EE + 255) / 256, 256>>>(ei1, ei2);

    // Layer 1: 128 -> 128
    {
        dim3 grid((NN * 32 + 255) / 256, 1, 2);
        k_gemm<<<grid, 256>>>(feat1, feat2, W1, H0, H1, 128, 128, 0);
        k_gather<<<grid, 256>>>(H0, H1, b1, X0, X1, 128);
    }
    // Layer 2: 128 -> 64
    {
        dim3 grid((NN * 16 + 255) / 256, 1, 2);
        k_gemm<<<grid, 256>>>(X0, X1, W2, H0, H1, 128, 64, 1);
        k_gather<<<grid, 256>>>(H0, H1, b2, X0, X1, 64);
    }
    // Layer 3: 64 -> 32
    {
        dim3 grid((NN * 8 + 255) / 256, 1, 2);
        k_gemm<<<grid, 256>>>(X0, X1, W3, H0, H1, 64, 32, 1);
        k_gather<<<grid, 256>>>(H0, H1, b3, af0, af1, 32);
    }

    // histogram: pass 0 = min/max, pass 1 = bin
    dim3 hgrid((NN + 127) / 128, (NN + 127) / 128);
    k_simpass<<<hgrid, 256>>>(af0, af1, 0);
    k_simpass<<<hgrid, 256>>>(af0, af1, 1);

    // attention pooling (both graphs per launch)
    dim3 pg(40, 1, 2);
    k_colmean<<<pg, 256>>>();
    k_gc2<<<1, 64>>>(att_w);
    k_pool<<<pg, 256>>>();

    // tensor network
    k_tnprep<<<1, 1024>>>(tn_w, tn_wb, tn_bias);
    k_tnnodes<<<pg, 256>>>();

    k_final<<<1, 32>>>(fc1_w, fc1_b, fc2_w, fc2_b, out);
}

// round 3
// speedup vs baseline: 1.8266x; 1.0318x over previous
#include <cuda_runtime.h>
#include <math.h>

#define NN 10000
#define EE 320000
typedef unsigned long long u64;

// ---------------- device scratch ----------------
__device__ float g_H[2][NN * 128];
__device__ float g_X[2][NN * 128];
__device__ float g_af[2][NN * 32];
__device__ float g_dinv[2][NN];
__device__ int   g_indeg[2][NN];
__device__ int   g_rowstart[2][NN + 1];
__device__ int   g_cursor[2][NN];
__device__ int   g_adj[2][EE];
__device__ unsigned g_keymin, g_keymax;
__device__ unsigned g_hist[16 * 32];
__device__ float g_meanraw[2][32];
__device__ float g_gc[2][32];
__device__ float g_pool[2][32];
__device__ float g_A[2][32 * 16];
__device__ float g_c[2][16];
__device__ float g_sAcc[2][16];
__device__ float g_s0[16];

// ---------------- helpers ----------------
__device__ __forceinline__ unsigned fkey(float f) {
    unsigned u = __float_as_uint(f);
    return (u & 0x80000000u) ? ~u : (u | 0x80000000u);
}
__device__ __forceinline__ float fdec(unsigned k) {
    return (k & 0x80000000u) ? __uint_as_float(k ^ 0x80000000u)
                             : __uint_as_float(~k);
}
__device__ __forceinline__ u64 dup2(float a) {
    u64 r;
    asm("mov.b64 %0, {%1, %1};" : "=l"(r) : "r"(__float_as_uint(a)));
    return r;
}
__device__ __forceinline__ void ffma2(u64& acc, u64 a, u64 b) {
    asm("fma.rn.f32x2 %0, %1, %2, %0;" : "+l"(acc) : "l"(a), "l"(b));
}
__device__ __forceinline__ void unpk(u64 v, float& lo, float& hi) {
    unsigned l, h;
    asm("mov.b64 {%0, %1}, %2;" : "=r"(l), "=r"(h) : "l"(v));
    lo = __uint_as_float(l); hi = __uint_as_float(h);
}

// ---------------- reset ----------------
__global__ void k_reset() {
    int t = threadIdx.x;
    for (int i = t; i < 2 * NN; i += 1024)
        ((int*)g_indeg)[i] = 0;
    if (t < 16 * 32) g_hist[t] = 0u;
    if (t < 32) {
        g_meanraw[0][t] = 0.f; g_meanraw[1][t] = 0.f;
        g_pool[0][t] = 0.f;    g_pool[1][t] = 0.f;
    }
    if (t < 16) { g_sAcc[0][t] = 0.f; g_sAcc[1][t] = 0.f; }
    if (t == 0) { g_keymin = 0xFFFFFFFFu; g_keymax = 0u; }
}

// ---------------- CSR build ----------------
__global__ void k_indeg(const int* __restrict__ ei1, const int* __restrict__ ei2) {
    int t = blockIdx.x * 256 + threadIdx.x;
    if (t >= 2 * EE) return;
    int g = t >= EE;
    const int* ei = g ? ei2 : ei1;
    int e = t - g * EE;
    atomicAdd(&g_indeg[g][ei[EE + e]], 1);
}

__global__ void k_scan() {   // grid=2, block=1024
    int g = blockIdx.x, t = threadIdx.x;
    int lane = t & 31, w = t >> 5;
    __shared__ int warpsum[32];
    __shared__ int s_carry;
    if (t == 0) s_carry = 0;
    __syncthreads();
    for (int base = 0; base < NN; base += 1024) {
        int i = base + t;
        int v = (i < NN) ? g_indeg[g][i] : 0;
        int x = v;
#pragma unroll
        for (int o = 1; o < 32; o <<= 1) {
            int y = __shfl_up_sync(0xffffffffu, x, o);
            if (lane >= o) x += y;
        }
        if (lane == 31) warpsum[w] = x;
        __syncthreads();
        if (w == 0) {
            int ws = warpsum[lane];
#pragma unroll
            for (int o = 1; o < 32; o <<= 1) {
                int y = __shfl_up_sync(0xffffffffu, ws, o);
                if (lane >= o) ws += y;
            }
            warpsum[lane] = ws;
        }
        __syncthreads();
        int carry = s_carry;
        int excl = carry + (x - v) + (w ? warpsum[w - 1] : 0);
        if (i < NN) {
            g_rowstart[g][i] = excl;
            g_cursor[g][i] = excl;
            g_dinv[g][i] = rsqrtf((float)v + 1.0f);
        }
        int total = warpsum[31];
        __syncthreads();
        if (t == 0) s_carry = carry + total;
        __syncthreads();
    }
    if (t == 0) g_rowstart[g][NN] = s_carry;
}

__global__ void k_fill(const int* __restrict__ ei1, const int* __restrict__ ei2) {
    int t = blockIdx.x * 256 + threadIdx.x;
    if (t >= 2 * EE) return;
    int g = t >= EE;
    const int* ei = g ? ei2 : ei1;
    int e = t - g * EE;
    int s = ei[e], d = ei[EE + e];
    int pos = atomicAdd(&g_cursor[g][d], 1);
    g_adj[g][pos] = s;
}

// ---------------- GEMM: H = relu?(X) @ W   (f32x2 inner) ----------------
__global__ void k_gemm(const float* __restrict__ X0, const float* __restrict__ X1,
                       const float* __restrict__ W,
                       float* __restrict__ H0, float* __restrict__ H1,
                       int Fin, int Fout, int reluIn) {
    __shared__ float Ws[32 * 128];
    int z = blockIdx.z;
    const float* X = z ? X1 : X0;
    float* H = z ? H1 : H0;
    int tid = threadIdx.x;
    int gpf = Fout >> 2;
    int idx = blockIdx.x * 256 + tid;
    int row = idx / gpf;
    int c4 = idx - row * gpf;
    u64 acc0 = 0ull, acc1 = 0ull;
    const float* xr = X + (size_t)row * Fin;
    const u64* Wp = (const u64*)Ws;
    for (int k0 = 0; k0 < Fin; k0 += 32) {
        for (int i = tid; i < 32 * gpf; i += 256)
            ((float4*)Ws)[i] = ((const float4*)(W + (size_t)(k0 + i / gpf) * Fout))[i % gpf];
        __syncthreads();
        if (row < NN) {
#pragma unroll 8
            for (int k = 0; k < 32; k++) {
                float x = __ldg(xr + k0 + k);
                if (reluIn) x = fmaxf(x, 0.f);
                u64 xx = dup2(x);
                ffma2(acc0, xx, Wp[(k * gpf + c4) * 2]);
                ffma2(acc1, xx, Wp[(k * gpf + c4) * 2 + 1]);
            }
        }
        __syncthreads();
    }
    if (row < NN) {
        float4 o;
        unpk(acc0, o.x, o.y);
        unpk(acc1, o.z, o.w);
        ((float4*)(H + (size_t)row * Fout))[c4] = o;
    }
}

// ---------------- gather: O[d] = H[d]/deg + b + sum_in coef*H[s] ----------------
__global__ void k_gather(const float* __restrict__ H0, const float* __restrict__ H1,
                         const float* __restrict__ b,
                         float* __restrict__ O0, float* __restrict__ O1, int Fout) {
    int z = blockIdx.z;
    const float* H = z ? H1 : H0;
    float* O = z ? O1 : O0;
    int gpf = Fout >> 2;
    int idx = blockIdx.x * 256 + threadIdx.x;
    int node = idx / gpf;
    int c = idx - node * gpf;
    if (node >= NN) return;
    int rs = g_rowstart[z][node], re = g_rowstart[z][node + 1];
    float di_d = g_dinv[z][node];
    float invdeg = 1.0f / ((float)(re - rs) + 1.0f);
    float4 hs = ((const float4*)(H + (size_t)node * Fout))[c];
    float4 bb = ((const float4*)b)[c];
    float4 acc;
    acc.x = hs.x * invdeg + bb.x; acc.y = hs.y * invdeg + bb.y;
    acc.z = hs.z * invdeg + bb.z; acc.w = hs.w * invdeg + bb.w;
    for (int e = rs; e < re; e++) {
        int s = __ldg(&g_adj[z][e]);
        float coef = g_dinv[z][s] * di_d;
        float4 v = ((const float4*)(H + (size_t)s * Fout))[c];
        acc.x += coef * v.x; acc.y += coef * v.y;
        acc.z += coef * v.z; acc.w += coef * v.w;
    }
    ((float4*)(O + (size_t)node * Fout))[c] = acc;
}

// ---------------- similarity passes (conflict-free smem, FFMA2) ----------------
// A tile row-major As[128][36]; B tile k-major Bs[32][132].
// Thread (ty,tx): rows {ty*4+i, 64+ty*4+i}, cols {tx*4+j, 64+tx*4+j}.
__global__ void __launch_bounds__(256, 2)
k_simpass(const float* __restrict__ A, const float* __restrict__ B, int pass) {
    __shared__ float As[128][36];
    __shared__ float Bs[32][132];
    __shared__ unsigned sh[16];
    int tid = threadIdx.x;
    int i0 = blockIdx.y * 128, j0 = blockIdx.x * 128;
    // stage A: lane = k4 (coalesced gmem, conflict-free float4 STS)
    for (int idx = tid; idx < 1024; idx += 256) {
        int r = idx >> 3, k4 = idx & 7;
        int ia = i0 + r;
        float4 v = make_float4(0.f, 0.f, 0.f, 0.f);
        if (ia < NN) v = ((const float4*)(A + (size_t)ia * 32))[k4];
        *(float4*)&As[r][k4 * 4] = v;
    }
    // stage B: lane = column (conflict-free scalar STS, consecutive banks)
    for (int idx = tid; idx < 1024; idx += 256) {
        int jr = idx & 127, k4 = idx >> 7;
        int jb = j0 + jr;
        float4 v = make_float4(0.f, 0.f, 0.f, 0.f);
        if (jb < NN) v = ((const float4*)(B + (size_t)jb * 32))[k4];
        Bs[k4 * 4 + 0][jr] = v.x;
        Bs[k4 * 4 + 1][jr] = v.y;
        Bs[k4 * 4 + 2][jr] = v.z;
        Bs[k4 * 4 + 3][jr] = v.w;
    }
    if (pass && tid < 16) sh[tid] = 0u;
    __syncthreads();
    int tx = tid & 15, ty = tid >> 4;
    u64 acc2[8][4];
#pragma unroll
    for (int r = 0; r < 8; r++)
#pragma unroll
        for (int c = 0; c < 4; c++) acc2[r][c] = 0ull;
#pragma unroll 2
    for (int k = 0; k < 32; k++) {
        u64 aa[8];
#pragma unroll
        for (int i = 0; i < 4; i++) {
            aa[i]     = dup2(As[ty * 4 + i][k]);
            aa[4 + i] = dup2(As[64 + ty * 4 + i][k]);
        }
        u64 bv[4];
        const u64* bp0 = (const u64*)&Bs[k][tx * 4];
        const u64* bp1 = (const u64*)&Bs[k][64 + tx * 4];
        bv[0] = bp0[0]; bv[1] = bp0[1];
        bv[2] = bp1[0]; bv[3] = bp1[1];
#pragma unroll
        for (int r = 0; r < 8; r++)
#pragma unroll
            for (int c = 0; c < 4; c++) ffma2(acc2[r][c], aa[r], bv[c]);
    }
    float acc[8][8];
#pragma unroll
    for (int r = 0; r < 8; r++)
#pragma unroll
        for (int c = 0; c < 4; c++)
            unpk(acc2[r][c], acc[r][2 * c], acc[r][2 * c + 1]);
    // index maps
    int rowi[8], colj[8];
#pragma unroll
    for (int r = 0; r < 8; r++)
        rowi[r] = i0 + (r < 4 ? ty * 4 + r : 64 + ty * 4 + (r - 4));
#pragma unroll
    for (int c = 0; c < 4; c++) {
        int base = (c < 2) ? (j0 + tx * 4 + 2 * c) : (j0 + 64 + tx * 4 + 2 * (c - 2));
        colj[2 * c] = base; colj[2 * c + 1] = base + 1;
    }
    if (pass == 0) {
        float lmin = 3.4e38f, lmax = -3.4e38f;
#pragma unroll
        for (int r = 0; r < 8; r++) {
            if (rowi[r] >= NN) continue;
#pragma unroll
            for (int c = 0; c < 8; c++) {
                if (colj[c] >= NN) continue;
                float v = acc[r][c];
                lmin = fminf(lmin, v);
                lmax = fmaxf(lmax, v);
            }
        }
        for (int o = 16; o; o >>= 1) {
            lmin = fminf(lmin, __shfl_down_sync(0xffffffffu, lmin, o));
            lmax = fmaxf(lmax, __shfl_down_sync(0xffffffffu, lmax, o));
        }
        if ((tid & 31) == 0) {
            atomicMin(&g_keymin, fkey(lmin));
            atomicMax(&g_keymax, fkey(lmax));
        }
    } else {
        float lo = fdec(g_keymin), hi = fdec(g_keymax);
        float inv = 1.0f / ((hi - lo) + 1e-12f);
        u64 cl = 0ull, ch = 0ull;
#pragma unroll
        for (int r = 0; r < 8; r++) {
            if (rowi[r] >= NN) continue;
#pragma unroll
            for (int c = 0; c < 8; c++) {
                if (colj[c] >= NN) continue;
                float q = (acc[r][c] - lo) * inv;
                int b = (int)(q * 16.0f);
                b = min(max(b, 0), 15);
                if (b < 8) cl += 1ull << (b * 8);
                else       ch += 1ull << ((b - 8) * 8);
            }
        }
#pragma unroll
        for (int b = 0; b < 16; b++) {
            unsigned v = (unsigned)((b < 8 ? (cl >> (b * 8)) : (ch >> ((b - 8) * 8))) & 0xFFull);
            for (int o = 16; o; o >>= 1) v += __shfl_down_sync(0xffffffffu, v, o);
            if ((tid & 31) == 0 && v) atomicAdd(&sh[b], v);
        }
        __syncthreads();
        if (tid < 16 && sh[tid]) atomicAdd(&g_hist[tid * 32], sh[tid]);
    }
}

// ---------------- attention ----------------
__global__ void k_colmean() {
    int z = blockIdx.z;
    const float* X = g_af[z];
    int lane = threadIdx.x & 31;
    int w = (blockIdx.x * blockDim.x + threadIdx.x) >> 5;
    int nw = (gridDim.x * blockDim.x) >> 5;
    float acc = 0.f;
    for (int n = w; n < NN; n += nw) acc += X[n * 32 + lane];
    atomicAdd(&g_meanraw[z][lane], acc);
}
__global__ void k_gc2(const float* __restrict__ att_w) {
    int g = threadIdx.x >> 5, j = threadIdx.x & 31;
    float acc = 0.f;
    const float invN = 1.0f / NN;
    for (int f = 0; f < 32; f++)
        acc += (g_meanraw[g][f] * invN) * att_w[f * 32 + j];
    g_gc[g][j] = tanhf(acc);
}
__global__ void k_pool() {
    int z = blockIdx.z;
    const float* X = g_af[z];
    int lane = threadIdx.x & 31;
    int w = (blockIdx.x * blockDim.x + threadIdx.x) >> 5;
    int nw = (gridDim.x * blockDim.x) >> 5;
    float gcv = g_gc[z][lane];
    float acc = 0.f;
    for (int n = w; n < NN; n += nw) {
        float x = X[n * 32 + lane];
        float p = x * gcv;
        for (int o = 16; o; o >>= 1) p += __shfl_xor_sync(0xffffffffu, p, o);
        float sig = 1.0f / (1.0f + expf(-p));
        acc += x * sig;
    }
    atomicAdd(&g_pool[z][lane], acc);
}

// ---------------- tensor network ----------------
__global__ void k_tnprep(const float* __restrict__ tn_w, const float* __restrict__ tn_wb,
                         const float* __restrict__ tn_bias) {
    int t = threadIdx.x;
    int slot = t >> 9;
    int r = t & 511;
    int f = r >> 4, k = r & 15;
    const float* e2 = g_pool[1 - slot];
    float acc = tn_wb[k * 64 + f];
    for (int gg = 0; gg < 32; gg++)
        acc += tn_w[f * 512 + gg * 16 + k] * e2[gg];
    g_A[slot][f * 16 + k] = acc;
    if (t < 32) {
        int sl = t >> 4, kk = t & 15;
        const float* e2b = g_pool[1 - sl];
        float c = tn_bias[kk];
        for (int gg = 0; gg < 32; gg++)
            c += tn_wb[kk * 64 + 32 + gg] * e2b[gg];
        g_c[sl][kk] = c;
    }
    __syncthreads();
    if (t < 16) {
        float acc2 = g_c[0][t];
        for (int f2 = 0; f2 < 32; f2++)
            acc2 += g_pool[0][f2] * g_A[0][f2 * 16 + t];
        g_s0[t] = fmaxf(acc2, 0.f);
    }
}
__global__ void k_tnnodes() {
    int z = blockIdx.z;
    const float* X = g_af[z];
    int lane = threadIdx.x & 31;
    int w = (blockIdx.x * blockDim.x + threadIdx.x) >> 5;
    int nw = (gridDim.x * blockDim.x) >> 5;
    float acc = 0.f;
    for (int n = w; n < NN; n += nw) {
        float x = X[n * 32 + lane];
        float v = (lane < 16) ? g_c[z][lane] : 0.f;
#pragma unroll
        for (int f = 0; f < 32; f++) {
            float xf = __shfl_sync(0xffffffffu, x, f);
            if (lane < 16) v += xf * g_A[z][f * 16 + lane];
        }
        if (lane < 16) acc += fmaxf(v, 0.f);
    }
    if (lane < 16) atomicAdd(&g_sAcc[z][lane], acc);
}

// ---------------- final head ----------------
__global__ void k_final(const float* __restrict__ fc1_w, const float* __restrict__ fc1_b,
                        const float* __restrict__ fc2_w, const float* __restrict__ fc2_b,
                        float* __restrict__ out) {
    if (threadIdx.x != 0) return;
    float sc[64];
    const float invN = 1.0f / NN;
    for (int k = 0; k < 16; k++) {
        sc[k]      = g_s0[k];
        sc[16 + k] = g_sAcc[0][k] * invN;
        sc[32 + k] = g_sAcc[1][k] * invN;
    }
    float hf[16], hsum = 0.f;
    for (int b = 0; b < 16; b++) {
        unsigned c = g_hist[b * 32];
        if (c > 16777216u) c = 16777216u;
        hf[b] = (float)c;
        hsum += hf[b];
    }
    for (int b = 0; b < 16; b++) sc[48 + b] = hf[b] / hsum;
    float o2 = fc2_b[0];
    for (int j = 0; j < 16; j++) {
        float a = fc1_b[j];
        for (int i = 0; i < 64; i++) a += sc[i] * fc1_w[i * 16 + j];
        a = fmaxf(a, 0.f);
        o2 += a * fc2_w[j];
    }
    out[0] = 1.0f / (1.0f + expf(-o2));
}

// ---------------- host driver ----------------
extern "C" void kernel_launch(void* const* d_in, const int* in_sizes, int n_in,
                              void* d_out, int out_size) {
    const float* feat1 = (const float*)d_in[0];
    const float* feat2 = (const float*)d_in[1];
    const int* ei1 = (const int*)d_in[2];
    const int* ei2 = (const int*)d_in[3];
    const float* W1 = (const float*)d_in[4];
    const float* b1 = (const float*)d_in[5];
    const float* W2 = (const float*)d_in[6];
    const float* b2 = (const float*)d_in[7];
    const float* W3 = (const float*)d_in[8];
    const float* b3 = (const float*)d_in[9];
    const float* att_w = (const float*)d_in[10];
    const float* tn_w = (const float*)d_in[11];
    const float* tn_wb = (const float*)d_in[12];
    const float* tn_bias = (const float*)d_in[13];
    const float* fc1_w = (const float*)d_in[14];
    const float* fc1_b = (const float*)d_in[15];
    const float* fc2_w = (const float*)d_in[16];
    const float* fc2_b = (const float*)d_in[17];
    float* out = (float*)d_out;

    float *H0, *H1, *X0, *X1, *af0, *af1;
    cudaGetSymbolAddress((void**)&H0, g_H);   H1 = H0 + NN * 128;
    cudaGetSymbolAddress((void**)&X0, g_X);   X1 = X0 + NN * 128;
    cudaGetSymbolAddress((void**)&af0, g_af); af1 = af0 + NN * 32;

    k_reset<<<1, 1024>>>();
    k_indeg<<<(2 * EE + 255) / 256, 256>>>(ei1, ei2);
    k_scan<<<2, 1024>>>();
    k_fill<<<(2 * EE + 255) / 256, 256>>>(ei1, ei2);

    {
        dim3 grid((NN * 32 + 255) / 256, 1, 2);
        k_gemm<<<grid, 256>>>(feat1, feat2, W1, H0, H1, 128, 128, 0);
        k_gather<<<grid, 256>>>(H0, H1, b1, X0, X1, 128);
    }
    {
        dim3 grid((NN * 16 + 255) / 256, 1, 2);
        k_gemm<<<grid, 256>>>(X0, X1, W2, H0, H1, 128, 64, 1);
        k_gather<<<grid, 256>>>(H0, H1, b2, X0, X1, 64);
    }
    {
        dim3 grid((NN * 8 + 255) / 256, 1, 2);
        k_gemm<<<grid, 256>>>(X0, X1, W3, H0, H1, 64, 32, 1);
        k_gather<<<grid, 256>>>(H0, H1, b3, af0, af1, 32);
    }

    dim3 hgrid((NN + 127) / 128, (NN + 127) / 128);
    k_simpass<<<hgrid, 256>>>(af0, af1, 0);
    k_simpass<<<hgrid, 256>>>(af0, af1, 1);

    dim3 pg(40, 1, 2);
    k_colmean<<<pg, 256>>>();
    k_gc2<<<1, 64>>>(att_w);
    k_pool<<<pg, 256>>>();

    k_tnprep<<<1, 1024>>>(tn_w, tn_wb, tn_bias);
    k_tnnodes<<<pg, 256>>>();

    k_final<<<1, 32>>>(fc1_w, fc1_b, fc2_w, fc2_b, out);
}

// round 4
// speedup vs baseline: 2.2228x; 1.2169x over previous
#include <cuda_runtime.h>
#include <math.h>

#define NN 10000
#define EE 320000
#define NNP 10112                    // padded transposed row stride
typedef unsigned long long u64;

// ---------------- device scratch ----------------
__device__ float g_H[2][NN * 128];
__device__ float g_X[2][NN * 128];
__device__ float g_af[2][NN * 32];
__device__ float g_aft[2][32 * NNP];   // transposed af, padded
__device__ float g_dinv[2][NN];
__device__ int   g_indeg[2][NN];
__device__ int   g_rowstart[2][NN + 1];
__device__ int   g_cursor[2][NN];
__device__ int   g_adj[2][EE];
__device__ unsigned g_keymin, g_keymax;
__device__ unsigned g_hist[16 * 32];
__device__ float g_meanraw[2][32];
__device__ float g_gc[2][32];
__device__ float g_pool[2][32];
__device__ float g_A[2][32 * 16];
__device__ float g_c[2][16];
__device__ float g_sAcc[2][16];
__device__ float g_s0[16];

// ---------------- helpers ----------------
__device__ __forceinline__ unsigned fkey(float f) {
    unsigned u = __float_as_uint(f);
    return (u & 0x80000000u) ? ~u : (u | 0x80000000u);
}
__device__ __forceinline__ float fdec(unsigned k) {
    return (k & 0x80000000u) ? __uint_as_float(k ^ 0x80000000u)
                             : __uint_as_float(~k);
}
__device__ __forceinline__ u64 dup2(float a) {
    u64 r;
    asm("mov.b64 %0, {%1, %1};" : "=l"(r) : "r"(__float_as_uint(a)));
    return r;
}
__device__ __forceinline__ void ffma2(u64& acc, u64 a, u64 b) {
    asm("fma.rn.f32x2 %0, %1, %2, %0;" : "+l"(acc) : "l"(a), "l"(b));
}
__device__ __forceinline__ void unpk(u64 v, float& lo, float& hi) {
    unsigned l, h;
    asm("mov.b64 {%0, %1}, %2;" : "=r"(l), "=r"(h) : "l"(v));
    lo = __uint_as_float(l); hi = __uint_as_float(h);
}

// ---------------- reset ----------------
__global__ void k_reset() {
    int t = threadIdx.x;
    for (int i = t; i < 2 * NN; i += 1024)
        ((int*)g_indeg)[i] = 0;
    if (t < 16 * 32) g_hist[t] = 0u;
    if (t < 32) {
        g_meanraw[0][t] = 0.f; g_meanraw[1][t] = 0.f;
        g_pool[0][t] = 0.f;    g_pool[1][t] = 0.f;
    }
    if (t < 16) { g_sAcc[0][t] = 0.f; g_sAcc[1][t] = 0.f; }
    if (t == 0) { g_keymin = 0xFFFFFFFFu; g_keymax = 0u; }
}

// ---------------- CSR build ----------------
__global__ void k_indeg(const int* __restrict__ ei1, const int* __restrict__ ei2) {
    int t = blockIdx.x * 256 + threadIdx.x;
    if (t >= 2 * EE) return;
    int g = t >= EE;
    const int* ei = g ? ei2 : ei1;
    int e = t - g * EE;
    atomicAdd(&g_indeg[g][ei[EE + e]], 1);
}

__global__ void k_scan() {   // grid=2, block=1024
    int g = blockIdx.x, t = threadIdx.x;
    int lane = t & 31, w = t >> 5;
    __shared__ int warpsum[32];
    __shared__ int s_carry;
    if (t == 0) s_carry = 0;
    __syncthreads();
    for (int base = 0; base < NN; base += 1024) {
        int i = base + t;
        int v = (i < NN) ? g_indeg[g][i] : 0;
        int x = v;
#pragma unroll
        for (int o = 1; o < 32; o <<= 1) {
            int y = __shfl_up_sync(0xffffffffu, x, o);
            if (lane >= o) x += y;
        }
        if (lane == 31) warpsum[w] = x;
        __syncthreads();
        if (w == 0) {
            int ws = warpsum[lane];
#pragma unroll
            for (int o = 1; o < 32; o <<= 1) {
                int y = __shfl_up_sync(0xffffffffu, ws, o);
                if (lane >= o) ws += y;
            }
            warpsum[lane] = ws;
        }
        __syncthreads();
        int carry = s_carry;
        int excl = carry + (x - v) + (w ? warpsum[w - 1] : 0);
        if (i < NN) {
            g_rowstart[g][i] = excl;
            g_cursor[g][i] = excl;
            g_dinv[g][i] = rsqrtf((float)v + 1.0f);
        }
        int total = warpsum[31];
        __syncthreads();
        if (t == 0) s_carry = carry + total;
        __syncthreads();
    }
    if (t == 0) g_rowstart[g][NN] = s_carry;
}

__global__ void k_fill(const int* __restrict__ ei1, const int* __restrict__ ei2) {
    int t = blockIdx.x * 256 + threadIdx.x;
    if (t >= 2 * EE) return;
    int g = t >= EE;
    const int* ei = g ? ei2 : ei1;
    int e = t - g * EE;
    int s = ei[e], d = ei[EE + e];
    int pos = atomicAdd(&g_cursor[g][d], 1);
    g_adj[g][pos] = s;
}

// ---------------- tiled GEMM: H = relu?(X) @ W ----------------
// 128-row tile, FOUT cols. Thread (tx 0..31, ty 0..7): 16 rows x CPT cols.
// A tile k-major (row-pairs as u64), W k-major. FFMA2 row-pair x dup(col).
template <int FOUT, int KTOT, int RELU>
__global__ void __launch_bounds__(256, 2)
k_tgemm(const float* __restrict__ X0, const float* __restrict__ X1,
        const float* __restrict__ W,
        float* __restrict__ H0, float* __restrict__ H1) {
    constexpr int CPT = FOUT / 32;
    __shared__ __align__(16) float As[32][132];
    __shared__ __align__(16) float Ws[32][FOUT];
    int z = blockIdx.z;
    const float* X = z ? X1 : X0;
    float* H = z ? H1 : H0;
    int tid = threadIdx.x;
    int i0 = blockIdx.x * 128;
    int tx = tid & 31, ty = tid >> 5;
    u64 acc2[8][CPT];
#pragma unroll
    for (int r = 0; r < 8; r++)
#pragma unroll
        for (int c = 0; c < CPT; c++) acc2[r][c] = 0ull;

    for (int k0 = 0; k0 < KTOT; k0 += 32) {
        // stage X tile (k-major): coalesced LDG, 4-way STS (cheap)
        for (int idx = tid; idx < 1024; idx += 256) {
            int r = idx >> 3, k4 = idx & 7;
            int row = i0 + r;
            float4 v = make_float4(0.f, 0.f, 0.f, 0.f);
            if (row < NN) v = *(const float4*)&X[(size_t)row * KTOT + k0 + k4 * 4];
            if (RELU) {
                v.x = fmaxf(v.x, 0.f); v.y = fmaxf(v.y, 0.f);
                v.z = fmaxf(v.z, 0.f); v.w = fmaxf(v.w, 0.f);
            }
            As[k4 * 4 + 0][r] = v.x; As[k4 * 4 + 1][r] = v.y;
            As[k4 * 4 + 2][r] = v.z; As[k4 * 4 + 3][r] = v.w;
        }
        // stage W (k-major, conflict-free STS)
        for (int idx = tid; idx < 8 * FOUT; idx += 256) {
            int j4 = idx % (FOUT / 4), kk = idx / (FOUT / 4);
            float4 w = *(const float4*)&W[(size_t)(k0 + kk) * FOUT + j4 * 4];
            Ws[kk][j4 * 4 + 0] = w.x; Ws[kk][j4 * 4 + 1] = w.y;
            Ws[kk][j4 * 4 + 2] = w.z; Ws[kk][j4 * 4 + 3] = w.w;
        }
        __syncthreads();
#pragma unroll 4
        for (int k = 0; k < 32; k++) {
            u64 aa[8];
            {
                const ulonglong2* ap = (const ulonglong2*)&As[k][ty * 16];
                ulonglong2 t0 = ap[0], t1 = ap[1], t2 = ap[2], t3 = ap[3];
                aa[0] = t0.x; aa[1] = t0.y; aa[2] = t1.x; aa[3] = t1.y;
                aa[4] = t2.x; aa[5] = t2.y; aa[6] = t3.x; aa[7] = t3.y;
            }
            u64 bd[CPT];
            if (CPT == 4) {
                float4 b = *(const float4*)&Ws[k][tx * 4];
                bd[0] = dup2(b.x); bd[1] = dup2(b.y);
                bd[2] = dup2(b.z); bd[3] = dup2(b.w);
            } else if (CPT == 2) {
                float2 b = *(const float2*)&Ws[k][tx * 2];
                bd[0] = dup2(b.x); bd[1] = dup2(b.y);
            } else {
                bd[0] = dup2(Ws[k][tx]);
            }
#pragma unroll
            for (int r = 0; r < 8; r++)
#pragma unroll
                for (int c = 0; c < CPT; c++) ffma2(acc2[r][c], aa[r], bd[c]);
        }
        __syncthreads();
    }
    // store: rows i0+ty*16+2rp (+1), cols tx*CPT..
#pragma unroll
    for (int rp = 0; rp < 8; rp++) {
        int r0 = i0 + ty * 16 + 2 * rp;
        float lo[CPT], hi[CPT];
#pragma unroll
        for (int c = 0; c < CPT; c++) unpk(acc2[rp][c], lo[c], hi[c]);
        if (r0 < NN) {
            float* p = H + (size_t)r0 * FOUT + tx * CPT;
            if (CPT == 4) *(float4*)p = make_float4(lo[0], lo[1], lo[2], lo[3]);
            else if (CPT == 2) *(float2*)p = make_float2(lo[0], lo[1]);
            else *p = lo[0];
        }
        if (r0 + 1 < NN) {
            float* p = H + (size_t)(r0 + 1) * FOUT + tx * CPT;
            if (CPT == 4) *(float4*)p = make_float4(hi[0], hi[1], hi[2], hi[3]);
            else if (CPT == 2) *(float2*)p = make_float2(hi[0], hi[1]);
            else *p = hi[0];
        }
    }
}

// ---------------- gather: O[d] = H[d]/deg + b + sum_in coef*H[s] ----------------
__global__ void k_gather(const float* __restrict__ H0, const float* __restrict__ H1,
                         const float* __restrict__ b,
                         float* __restrict__ O0, float* __restrict__ O1, int Fout) {
    int z = blockIdx.z;
    const float* H = z ? H1 : H0;
    float* O = z ? O1 : O0;
    int gpf = Fout >> 2;
    int idx = blockIdx.x * 256 + threadIdx.x;
    int node = idx / gpf;
    int c = idx - node * gpf;
    if (node >= NN) return;
    int rs = g_rowstart[z][node], re = g_rowstart[z][node + 1];
    float di_d = g_dinv[z][node];
    float invdeg = 1.0f / ((float)(re - rs) + 1.0f);
    float4 hs = ((const float4*)(H + (size_t)node * Fout))[c];
    float4 bb = ((const float4*)b)[c];
    float4 acc;
    acc.x = hs.x * invdeg + bb.x; acc.y = hs.y * invdeg + bb.y;
    acc.z = hs.z * invdeg + bb.z; acc.w = hs.w * invdeg + bb.w;
    for (int e = rs; e < re; e++) {
        int s = __ldg(&g_adj[z][e]);
        float coef = g_dinv[z][s] * di_d;
        float4 v = ((const float4*)(H + (size_t)s * Fout))[c];
        acc.x += coef * v.x; acc.y += coef * v.y;
        acc.z += coef * v.z; acc.w += coef * v.w;
    }
    ((float4*)(O + (size_t)node * Fout))[c] = acc;
}

// ---------------- af transpose: g_aft[z][k][n] = g_af[z][n][k] ----------------
__global__ void k_aftrans() {
    int z = blockIdx.z;
    int n0 = blockIdx.x * 128;
    int tid = threadIdx.x;
    __shared__ __align__(16) float t[32][132];
    const float* af = g_af[z];
    for (int idx = tid; idx < 1024; idx += 256) {
        int r = idx >> 3, k4 = idx & 7;
        int n = n0 + r;
        float4 v = make_float4(0.f, 0.f, 0.f, 0.f);
        if (n < NN) v = *(const float4*)&af[n * 32 + k4 * 4];
        t[k4 * 4 + 0][r] = v.x; t[k4 * 4 + 1][r] = v.y;
        t[k4 * 4 + 2][r] = v.z; t[k4 * 4 + 3][r] = v.w;
    }
    __syncthreads();
    float* AT = g_aft[z];
    for (int idx = tid; idx < 1024; idx += 256) {
        int k = idx >> 5, c4 = idx & 31;
        int n = n0 + c4 * 4;
        if (n < NN) *(float4*)&AT[k * NNP + n] = *(const float4*)&t[k][c4 * 4];
    }
}

// ---------------- similarity passes ----------------
// Tiles from transposed af. Thread (tx 0..31, ty 0..7): 16 rows x 4 cols.
// Row-pairs are contiguous u64 in k-major A tile -> no dup on A side.
__global__ void __launch_bounds__(256, 2)
k_simpass(int pass) {
    __shared__ __align__(16) float As[32][132];
    __shared__ __align__(16) float Bs[32][132];
    __shared__ unsigned sh[16];
    int tid = threadIdx.x;
    int i0 = blockIdx.y * 128, j0 = blockIdx.x * 128;
    const float* AT = g_aft[0];
    const float* BT = g_aft[1];
    for (int idx = tid; idx < 1024; idx += 256) {
        int k = idx >> 5, c4 = idx & 31;
        *(float4*)&As[k][c4 * 4] = *(const float4*)&AT[k * NNP + i0 + c4 * 4];
        *(float4*)&Bs[k][c4 * 4] = *(const float4*)&BT[k * NNP + j0 + c4 * 4];
    }
    if (pass && tid < 16) sh[tid] = 0u;
    __syncthreads();
    int tx = tid & 31, ty = tid >> 5;
    u64 acc2[8][4];
#pragma unroll
    for (int r = 0; r < 8; r++)
#pragma unroll
        for (int c = 0; c < 4; c++) acc2[r][c] = 0ull;
#pragma unroll 4
    for (int k = 0; k < 32; k++) {
        u64 aa[8];
        {
            const ulonglong2* ap = (const ulonglong2*)&As[k][ty * 16];
            ulonglong2 t0 = ap[0], t1 = ap[1], t2 = ap[2], t3 = ap[3];
            aa[0] = t0.x; aa[1] = t0.y; aa[2] = t1.x; aa[3] = t1.y;
            aa[4] = t2.x; aa[5] = t2.y; aa[6] = t3.x; aa[7] = t3.y;
        }
        float4 b = *(const float4*)&Bs[k][tx * 4];
        u64 bd[4] = {dup2(b.x), dup2(b.y), dup2(b.z), dup2(b.w)};
#pragma unroll
        for (int r = 0; r < 8; r++)
#pragma unroll
            for (int c = 0; c < 4; c++) ffma2(acc2[r][c], aa[r], bd[c]);
    }
    // rows: i0 + ty*16 + 2rp + h ; cols: j0 + tx*4 + c
    int rbase = i0 + ty * 16;
    int cbase = j0 + tx * 4;
    if (pass == 0) {
        float lmin = 3.4e38f, lmax = -3.4e38f;
#pragma unroll
        for (int rp = 0; rp < 8; rp++) {
            float lo[4], hi[4];
#pragma unroll
            for (int c = 0; c < 4; c++) unpk(acc2[rp][c], lo[c], hi[c]);
            int r0 = rbase + 2 * rp;
            if (r0 < NN) {
#pragma unroll
                for (int c = 0; c < 4; c++) {
                    if (cbase + c < NN) {
                        lmin = fminf(lmin, lo[c]); lmax = fmaxf(lmax, lo[c]);
                    }
                }
            }
            if (r0 + 1 < NN) {
#pragma unroll
                for (int c = 0; c < 4; c++) {
                    if (cbase + c < NN) {
                        lmin = fminf(lmin, hi[c]); lmax = fmaxf(lmax, hi[c]);
                    }
                }
            }
        }
        for (int o = 16; o; o >>= 1) {
            lmin = fminf(lmin, __shfl_down_sync(0xffffffffu, lmin, o));
            lmax = fmaxf(lmax, __shfl_down_sync(0xffffffffu, lmax, o));
        }
        if ((tid & 31) == 0) {
            atomicMin(&g_keymin, fkey(lmin));
            atomicMax(&g_keymax, fkey(lmax));
        }
    } else {
        float lo_r = fdec(g_keymin), hi_r = fdec(g_keymax);
        float inv = 1.0f / ((hi_r - lo_r) + 1e-12f);
        u64 cl = 0ull, ch = 0ull;
#pragma unroll
        for (int rp = 0; rp < 8; rp++) {
            float lo[4], hi[4];
#pragma unroll
            for (int c = 0; c < 4; c++) unpk(acc2[rp][c], lo[c], hi[c]);
            int r0 = rbase + 2 * rp;
#pragma unroll
            for (int h = 0; h < 2; h++) {
                if (r0 + h >= NN) continue;
                float* vals = h ? hi : lo;
#pragma unroll
                for (int c = 0; c < 4; c++) {
                    if (cbase + c >= NN) continue;
                    float q = (vals[c] - lo_r) * inv;
                    int b = (int)(q * 16.0f);
                    b = min(max(b, 0), 15);
                    if (b < 8) cl += 1ull << (b * 8);
                    else       ch += 1ull << ((b - 8) * 8);
                }
            }
        }
#pragma unroll
        for (int b = 0; b < 16; b++) {
            unsigned v = (unsigned)((b < 8 ? (cl >> (b * 8)) : (ch >> ((b - 8) * 8))) & 0xFFull);
            for (int o = 16; o; o >>= 1) v += __shfl_down_sync(0xffffffffu, v, o);
            if ((tid & 31) == 0 && v) atomicAdd(&sh[b], v);
        }
        __syncthreads();
        if (tid < 16 && sh[tid]) atomicAdd(&g_hist[tid * 32], sh[tid]);
    }
}

// ---------------- attention ----------------
__global__ void k_colmean() {
    int z = blockIdx.z;
    const float* X = g_af[z];
    int lane = threadIdx.x & 31;
    int w = (blockIdx.x * blockDim.x + threadIdx.x) >> 5;
    int nw = (gridDim.x * blockDim.x) >> 5;
    float acc = 0.f;
    for (int n = w; n < NN; n += nw) acc += X[n * 32 + lane];
    atomicAdd(&g_meanraw[z][lane], acc);
}
__global__ void k_gc2(const float* __restrict__ att_w) {
    int g = threadIdx.x >> 5, j = threadIdx.x & 31;
    float acc = 0.f;
    const float invN = 1.0f / NN;
    for (int f = 0; f < 32; f++)
        acc += (g_meanraw[g][f] * invN) * att_w[f * 32 + j];
    g_gc[g][j] = tanhf(acc);
}
__global__ void k_pool() {
    int z = blockIdx.z;
    const float* X = g_af[z];
    int lane = threadIdx.x & 31;
    int w = (blockIdx.x * blockDim.x + threadIdx.x) >> 5;
    int nw = (gridDim.x * blockDim.x) >> 5;
    float gcv = g_gc[z][lane];
    float acc = 0.f;
    for (int n = w; n < NN; n += nw) {
        float x = X[n * 32 + lane];
        float p = x * gcv;
        for (int o = 16; o; o >>= 1) p += __shfl_xor_sync(0xffffffffu, p, o);
        float sig = 1.0f / (1.0f + expf(-p));
        acc += x * sig;
    }
    atomicAdd(&g_pool[z][lane], acc);
}

// ---------------- tensor network ----------------
__global__ void k_tnprep(const float* __restrict__ tn_w, const float* __restrict__ tn_wb,
                         const float* __restrict__ tn_bias) {
    int t = threadIdx.x;
    int slot = t >> 9;
    int r = t & 511;
    int f = r >> 4, k = r & 15;
    const float* e2 = g_pool[1 - slot];
    float acc = tn_wb[k * 64 + f];
    for (int gg = 0; gg < 32; gg++)
        acc += tn_w[f * 512 + gg * 16 + k] * e2[gg];
    g_A[slot][f * 16 + k] = acc;
    if (t < 32) {
        int sl = t >> 4, kk = t & 15;
        const float* e2b = g_pool[1 - sl];
        float c = tn_bias[kk];
        for (int gg = 0; gg < 32; gg++)
            c += tn_wb[kk * 64 + 32 + gg] * e2b[gg];
        g_c[sl][kk] = c;
    }
    __syncthreads();
    if (t < 16) {
        float acc2 = g_c[0][t];
        for (int f2 = 0; f2 < 32; f2++)
            acc2 += g_pool[0][f2] * g_A[0][f2 * 16 + t];
        g_s0[t] = fmaxf(acc2, 0.f);
    }
}
__global__ void k_tnnodes() {
    int z = blockIdx.z;
    const float* X = g_af[z];
    int lane = threadIdx.x & 31;
    int w = (blockIdx.x * blockDim.x + threadIdx.x) >> 5;
    int nw = (gridDim.x * blockDim.x) >> 5;
    float acc = 0.f;
    for (int n = w; n < NN; n += nw) {
        float x = X[n * 32 + lane];
        float v = (lane < 16) ? g_c[z][lane] : 0.f;
#pragma unroll
        for (int f = 0; f < 32; f++) {
            float xf = __shfl_sync(0xffffffffu, x, f);
            if (lane < 16) v += xf * g_A[z][f * 16 + lane];
        }
        if (lane < 16) acc += fmaxf(v, 0.f);
    }
    if (lane < 16) atomicAdd(&g_sAcc[z][lane], acc);
}

// ---------------- final head ----------------
__global__ void k_final(const float* __restrict__ fc1_w, const float* __restrict__ fc1_b,
                        const float* __restrict__ fc2_w, const float* __restrict__ fc2_b,
                        float* __restrict__ out) {
    if (threadIdx.x != 0) return;
    float sc[64];
    const float invN = 1.0f / NN;
    for (int k = 0; k < 16; k++) {
        sc[k]      = g_s0[k];
        sc[16 + k] = g_sAcc[0][k] * invN;
        sc[32 + k] = g_sAcc[1][k] * invN;
    }
    float hf[16], hsum = 0.f;
    for (int b = 0; b < 16; b++) {
        unsigned c = g_hist[b * 32];
        if (c > 16777216u) c = 16777216u;
        hf[b] = (float)c;
        hsum += hf[b];
    }
    for (int b = 0; b < 16; b++) sc[48 + b] = hf[b] / hsum;
    float o2 = fc2_b[0];
    for (int j = 0; j < 16; j++) {
        float a = fc1_b[j];
        for (int i = 0; i < 64; i++) a += sc[i] * fc1_w[i * 16 + j];
        a = fmaxf(a, 0.f);
        o2 += a * fc2_w[j];
    }
    out[0] = 1.0f / (1.0f + expf(-o2));
}

// ---------------- host driver ----------------
extern "C" void kernel_launch(void* const* d_in, const int* in_sizes, int n_in,
                              void* d_out, int out_size) {
    const float* feat1 = (const float*)d_in[0];
    const float* feat2 = (const float*)d_in[1];
    const int* ei1 = (const int*)d_in[2];
    const int* ei2 = (const int*)d_in[3];
    const float* W1 = (const float*)d_in[4];
    const float* b1 = (const float*)d_in[5];
    const float* W2 = (const float*)d_in[6];
    const float* b2 = (const float*)d_in[7];
    const float* W3 = (const float*)d_in[8];
    const float* b3 = (const float*)d_in[9];
    const float* att_w = (const float*)d_in[10];
    const float* tn_w = (const float*)d_in[11];
    const float* tn_wb = (const float*)d_in[12];
    const float* tn_bias = (const float*)d_in[13];
    const float* fc1_w = (const float*)d_in[14];
    const float* fc1_b = (const float*)d_in[15];
    const float* fc2_w = (const float*)d_in[16];
    const float* fc2_b = (const float*)d_in[17];
    float* out = (float*)d_out;

    float *H0, *H1, *X0, *X1, *af0, *af1;
    cudaGetSymbolAddress((void**)&H0, g_H);   H1 = H0 + NN * 128;
    cudaGetSymbolAddress((void**)&X0, g_X);   X1 = X0 + NN * 128;
    cudaGetSymbolAddress((void**)&af0, g_af); af1 = af0 + NN * 32;

    k_reset<<<1, 1024>>>();
    k_indeg<<<(2 * EE + 255) / 256, 256>>>(ei1, ei2);
    k_scan<<<2, 1024>>>();
    k_fill<<<(2 * EE + 255) / 256, 256>>>(ei1, ei2);

    dim3 ggrid((NN + 127) / 128, 1, 2);
    k_tgemm<128, 128, 0><<<ggrid, 256>>>(feat1, feat2, W1, H0, H1);
    {
        dim3 grid((NN * 32 + 255) / 256, 1, 2);
        k_gather<<<grid, 256>>>(H0, H1, b1, X0, X1, 128);
    }
    k_tgemm<64, 128, 1><<<ggrid, 256>>>(X0, X1, W2, H0, H1);
    {
        dim3 grid((NN * 16 + 255) / 256, 1, 2);
        k_gather<<<grid, 256>>>(H0, H1, b2, X0, X1, 64);
    }
    k_tgemm<32, 64, 1><<<ggrid, 256>>>(X0, X1, W3, H0, H1);
    {
        dim3 grid((NN * 8 + 255) / 256, 1, 2);
        k_gather<<<grid, 256>>>(H0, H1, b3, af0, af1, 32);
    }

    k_aftrans<<<ggrid, 256>>>();

    dim3 hgrid((NN + 127) / 128, (NN + 127) / 128);
    k_simpass<<<hgrid, 256>>>(0);
    k_simpass<<<hgrid, 256>>>(1);

    dim3 pg(40, 1, 2);
    k_colmean<<<pg, 256>>>();
    k_gc2<<<1, 64>>>(att_w);
    k_pool<<<pg, 256>>>();

    k_tnprep<<<1, 1024>>>(tn_w, tn_wb, tn_bias);
    k_tnnodes<<<pg, 256>>>();

    k_final<<<1, 32>>>(fc1_w, fc1_b, fc2_w, fc2_b, out);
}

// round 5
// speedup vs baseline: 3.0690x; 1.3807x over previous
#include <cuda_runtime.h>
#include <math.h>

#define NN 10000
#define EE 320000
#define MT_TILES 632                 // ceil(10112/16) m-tiles (rows of graph-1)
#define NT_TILES 1264                // ceil(10112/8)  n-tiles (rows of graph-2)
typedef unsigned long long u64;

// ---------------- device scratch ----------------
__device__ float g_H[2][NN * 128];
__device__ float g_X[2][NN * 128];
__device__ float g_af[2][NN * 32];
__device__ uint4 g_fA[MT_TILES * 4 * 32];   // A-fragments (tf32), [mt][ks][lane]
__device__ uint2 g_fB[NT_TILES * 4 * 32];   // B-fragments (tf32), [nt][ks][lane]
__device__ float g_dinv[2][NN];
__device__ int   g_indeg[2][NN];
__device__ int   g_rowstart[2][NN + 1];
__device__ int   g_cursor[2][NN];
__device__ int   g_adj[2][EE];
__device__ unsigned g_keymin, g_keymax;
__device__ unsigned g_hist[16 * 32];
__device__ float g_meanraw[2][32];
__device__ float g_gc[2][32];
__device__ float g_pool[2][32];
__device__ float g_A[2][32 * 16];
__device__ float g_c[2][16];
__device__ float g_sAcc[2][16];
__device__ float g_s0[16];

// ---------------- helpers ----------------
__device__ __forceinline__ unsigned fkey(float f) {
    unsigned u = __float_as_uint(f);
    return (u & 0x80000000u) ? ~u : (u | 0x80000000u);
}
__device__ __forceinline__ float fdec(unsigned k) {
    return (k & 0x80000000u) ? __uint_as_float(k ^ 0x80000000u)
                             : __uint_as_float(~k);
}
__device__ __forceinline__ u64 dup2(float a) {
    u64 r;
    asm("mov.b64 %0, {%1, %1};" : "=l"(r) : "r"(__float_as_uint(a)));
    return r;
}
__device__ __forceinline__ void ffma2(u64& acc, u64 a, u64 b) {
    asm("fma.rn.f32x2 %0, %1, %2, %0;" : "+l"(acc) : "l"(a), "l"(b));
}
__device__ __forceinline__ void unpk(u64 v, float& lo, float& hi) {
    unsigned l, h;
    asm("mov.b64 {%0, %1}, %2;" : "=r"(l), "=r"(h) : "l"(v));
    lo = __uint_as_float(l); hi = __uint_as_float(h);
}
__device__ __forceinline__ unsigned totf32(float f) {
    unsigned r;
    asm("cvt.rna.tf32.f32 %0, %1;" : "=r"(r) : "f"(f));
    return r;
}
__device__ __forceinline__ void mma_tf32(float c[4], uint4 a, uint2 b) {
    asm("mma.sync.aligned.m16n8k8.row.col.f32.tf32.tf32.f32 "
        "{%0,%1,%2,%3}, {%4,%5,%6,%7}, {%8,%9}, {%0,%1,%2,%3};"
        : "+f"(c[0]), "+f"(c[1]), "+f"(c[2]), "+f"(c[3])
        : "r"(a.x), "r"(a.y), "r"(a.z), "r"(a.w), "r"(b.x), "r"(b.y));
}

// ---------------- reset ----------------
__global__ void k_reset() {
    int t = threadIdx.x;
    for (int i = t; i < 2 * NN; i += 1024)
        ((int*)g_indeg)[i] = 0;
    if (t < 16 * 32) g_hist[t] = 0u;
    if (t < 32) {
        g_meanraw[0][t] = 0.f; g_meanraw[1][t] = 0.f;
        g_pool[0][t] = 0.f;    g_pool[1][t] = 0.f;
    }
    if (t < 16) { g_sAcc[0][t] = 0.f; g_sAcc[1][t] = 0.f; }
    if (t == 0) { g_keymin = 0xFFFFFFFFu; g_keymax = 0u; }
}

// ---------------- CSR build ----------------
__global__ void k_indeg(const int* __restrict__ ei1, const int* __restrict__ ei2) {
    int t = blockIdx.x * 256 + threadIdx.x;
    if (t >= 2 * EE) return;
    int g = t >= EE;
    const int* ei = g ? ei2 : ei1;
    int e = t - g * EE;
    atomicAdd(&g_indeg[g][ei[EE + e]], 1);
}

__global__ void k_scan() {   // grid=2, block=1024
    int g = blockIdx.x, t = threadIdx.x;
    int lane = t & 31, w = t >> 5;
    __shared__ int warpsum[32];
    __shared__ int s_carry;
    if (t == 0) s_carry = 0;
    __syncthreads();
    for (int base = 0; base < NN; base += 1024) {
        int i = base + t;
        int v = (i < NN) ? g_indeg[g][i] : 0;
        int x = v;
#pragma unroll
        for (int o = 1; o < 32; o <<= 1) {
            int y = __shfl_up_sync(0xffffffffu, x, o);
            if (lane >= o) x += y;
        }
        if (lane == 31) warpsum[w] = x;
        __syncthreads();
        if (w == 0) {
            int ws = warpsum[lane];
#pragma unroll
            for (int o = 1; o < 32; o <<= 1) {
                int y = __shfl_up_sync(0xffffffffu, ws, o);
                if (lane >= o) ws += y;
            }
            warpsum[lane] = ws;
        }
        __syncthreads();
        int carry = s_carry;
        int excl = carry + (x - v) + (w ? warpsum[w - 1] : 0);
        if (i < NN) {
            g_rowstart[g][i] = excl;
            g_cursor[g][i] = excl;
            g_dinv[g][i] = rsqrtf((float)v + 1.0f);
        }
        int total = warpsum[31];
        __syncthreads();
        if (t == 0) s_carry = carry + total;
        __syncthreads();
    }
    if (t == 0) g_rowstart[g][NN] = s_carry;
}

__global__ void k_fill(const int* __restrict__ ei1, const int* __restrict__ ei2) {
    int t = blockIdx.x * 256 + threadIdx.x;
    if (t >= 2 * EE) return;
    int g = t >= EE;
    const int* ei = g ? ei2 : ei1;
    int e = t - g * EE;
    int s = ei[e], d = ei[EE + e];
    int pos = atomicAdd(&g_cursor[g][d], 1);
    g_adj[g][pos] = s;
}

// ---------------- tiled GEMM: H = relu?(X) @ W ----------------
template <int FOUT, int KTOT, int RELU>
__global__ void __launch_bounds__(256, 2)
k_tgemm(const float* __restrict__ X0, const float* __restrict__ X1,
        const float* __restrict__ W,
        float* __restrict__ H0, float* __restrict__ H1) {
    constexpr int CPT = FOUT / 32;
    __shared__ __align__(16) float As[32][132];
    __shared__ __align__(16) float Ws[32][FOUT];
    int z = blockIdx.z;
    const float* X = z ? X1 : X0;
    float* H = z ? H1 : H0;
    int tid = threadIdx.x;
    int i0 = blockIdx.x * 128;
    int tx = tid & 31, ty = tid >> 5;
    u64 acc2[8][CPT];
#pragma unroll
    for (int r = 0; r < 8; r++)
#pragma unroll
        for (int c = 0; c < CPT; c++) acc2[r][c] = 0ull;

    for (int k0 = 0; k0 < KTOT; k0 += 32) {
        for (int idx = tid; idx < 1024; idx += 256) {
            int r = idx >> 3, k4 = idx & 7;
            int row = i0 + r;
            float4 v = make_float4(0.f, 0.f, 0.f, 0.f);
            if (row < NN) v = *(const float4*)&X[(size_t)row * KTOT + k0 + k4 * 4];
            if (RELU) {
                v.x = fmaxf(v.x, 0.f); v.y = fmaxf(v.y, 0.f);
                v.z = fmaxf(v.z, 0.f); v.w = fmaxf(v.w, 0.f);
            }
            As[k4 * 4 + 0][r] = v.x; As[k4 * 4 + 1][r] = v.y;
            As[k4 * 4 + 2][r] = v.z; As[k4 * 4 + 3][r] = v.w;
        }
        for (int idx = tid; idx < 8 * FOUT; idx += 256) {
            int j4 = idx % (FOUT / 4), kk = idx / (FOUT / 4);
            float4 w = *(const float4*)&W[(size_t)(k0 + kk) * FOUT + j4 * 4];
            Ws[kk][j4 * 4 + 0] = w.x; Ws[kk][j4 * 4 + 1] = w.y;
            Ws[kk][j4 * 4 + 2] = w.z; Ws[kk][j4 * 4 + 3] = w.w;
        }
        __syncthreads();
#pragma unroll 4
        for (int k = 0; k < 32; k++) {
            u64 aa[8];
            {
                const ulonglong2* ap = (const ulonglong2*)&As[k][ty * 16];
                ulonglong2 t0 = ap[0], t1 = ap[1], t2 = ap[2], t3 = ap[3];
                aa[0] = t0.x; aa[1] = t0.y; aa[2] = t1.x; aa[3] = t1.y;
                aa[4] = t2.x; aa[5] = t2.y; aa[6] = t3.x; aa[7] = t3.y;
            }
            u64 bd[CPT];
            if (CPT == 4) {
                float4 b = *(const float4*)&Ws[k][tx * 4];
                bd[0] = dup2(b.x); bd[1] = dup2(b.y);
                bd[2] = dup2(b.z); bd[3] = dup2(b.w);
            } else if (CPT == 2) {
                float2 b = *(const float2*)&Ws[k][tx * 2];
                bd[0] = dup2(b.x); bd[1] = dup2(b.y);
            } else {
                bd[0] = dup2(Ws[k][tx]);
            }
#pragma unroll
            for (int r = 0; r < 8; r++)
#pragma unroll
                for (int c = 0; c < CPT; c++) ffma2(acc2[r][c], aa[r], bd[c]);
        }
        __syncthreads();
    }
#pragma unroll
    for (int rp = 0; rp < 8; rp++) {
        int r0 = i0 + ty * 16 + 2 * rp;
        float lo[CPT], hi[CPT];
#pragma unroll
        for (int c = 0; c < CPT; c++) unpk(acc2[rp][c], lo[c], hi[c]);
        if (r0 < NN) {
            float* p = H + (size_t)r0 * FOUT + tx * CPT;
            if (CPT == 4) *(float4*)p = make_float4(lo[0], lo[1], lo[2], lo[3]);
            else if (CPT == 2) *(float2*)p = make_float2(lo[0], lo[1]);
            else *p = lo[0];
        }
        if (r0 + 1 < NN) {
            float* p = H + (size_t)(r0 + 1) * FOUT + tx * CPT;
            if (CPT == 4) *(float4*)p = make_float4(hi[0], hi[1], hi[2], hi[3]);
            else if (CPT == 2) *(float2*)p = make_float2(hi[0], hi[1]);
            else *p = hi[0];
        }
    }
}

// ---------------- gather ----------------
__global__ void k_gather(const float* __restrict__ H0, const float* __restrict__ H1,
                         const float* __restrict__ b,
                         float* __restrict__ O0, float* __restrict__ O1, int Fout) {
    int z = blockIdx.z;
    const float* H = z ? H1 : H0;
    float* O = z ? O1 : O0;
    int gpf = Fout >> 2;
    int idx = blockIdx.x * 256 + threadIdx.x;
    int node = idx / gpf;
    int c = idx - node * gpf;
    if (node >= NN) return;
    int rs = g_rowstart[z][node], re = g_rowstart[z][node + 1];
    float di_d = g_dinv[z][node];
    float invdeg = 1.0f / ((float)(re - rs) + 1.0f);
    float4 hs = ((const float4*)(H + (size_t)node * Fout))[c];
    float4 bb = ((const float4*)b)[c];
    float4 acc;
    acc.x = hs.x * invdeg + bb.x; acc.y = hs.y * invdeg + bb.y;
    acc.z = hs.z * invdeg + bb.z; acc.w = hs.w * invdeg + bb.w;
    for (int e = rs; e < re; e++) {
        int s = __ldg(&g_adj[z][e]);
        float coef = g_dinv[z][s] * di_d;
        float4 v = ((const float4*)(H + (size_t)s * Fout))[c];
        acc.x += coef * v.x; acc.y += coef * v.y;
        acc.z += coef * v.z; acc.w += coef * v.w;
    }
    ((float4*)(O + (size_t)node * Fout))[c] = acc;
}

// ---------------- fragment builder (tf32 pack of af1/af2) ----------------
__device__ __forceinline__ float afld(const float* af, int n, int k) {
    return (n < NN) ? af[n * 32 + k] : 0.f;
}
__global__ void k_frag() {
    int wg = (blockIdx.x * 256 + threadIdx.x) >> 5;
    int lane = threadIdx.x & 31;
    if (wg < MT_TILES * 4) {
        int mt = wg >> 2, ks = wg & 3;
        const float* af = g_af[0];
        int r0 = mt * 16 + (lane >> 2);
        int c0 = ks * 8 + (lane & 3);
        uint4 v;
        v.x = totf32(afld(af, r0,     c0));
        v.y = totf32(afld(af, r0 + 8, c0));
        v.z = totf32(afld(af, r0,     c0 + 4));
        v.w = totf32(afld(af, r0 + 8, c0 + 4));
        g_fA[(mt * 4 + ks) * 32 + lane] = v;
    } else if (wg < MT_TILES * 4 + NT_TILES * 4) {
        int w = wg - MT_TILES * 4;
        int nt = w >> 2, ks = w & 3;
        const float* af = g_af[1];
        int n = nt * 8 + (lane >> 2);
        int k = ks * 8 + (lane & 3);
        uint2 v;
        v.x = totf32(afld(af, n, k));
        v.y = totf32(afld(af, n, k + 4));
        g_fB[(nt * 4 + ks) * 32 + lane] = v;
    }
}

// ---------------- similarity passes via tf32 mma ----------------
// Block 256 thr = 8 warps; warp w covers rows [by*128 + w*16, +16), cols [bx*128, +128).
__global__ void __launch_bounds__(256, 2)
k_simpass(int pass) {
    __shared__ unsigned sh[16];
    int tid = threadIdx.x, lane = tid & 31, w = tid >> 5;
    int mt = blockIdx.y * 8 + w;
    int bx = blockIdx.x;
    float c[16][4];
#pragma unroll
    for (int j = 0; j < 16; j++)
#pragma unroll
        for (int r = 0; r < 4; r++) c[j][r] = 0.f;
    if (pass && tid < 16) sh[tid] = 0u;
#pragma unroll
    for (int ks = 0; ks < 4; ks++) {
        uint4 a = g_fA[(mt * 4 + ks) * 32 + lane];
#pragma unroll
        for (int j = 0; j < 16; j++) {
            uint2 b = g_fB[((bx * 16 + j) * 4 + ks) * 32 + lane];
            mma_tf32(c[j], a, b);
        }
    }
    // element coords: c[j][0]:(r_lo, col0)  c[j][1]:(r_lo, col0+1)
    //                 c[j][2]:(r_hi, col0)  c[j][3]:(r_hi, col0+1)
    int r_lo = mt * 16 + (lane >> 2);
    int r_hi = r_lo + 8;
    int cb = bx * 128 + 2 * (lane & 3);
    bool vlo = r_lo < NN, vhi = r_hi < NN;
    if (pass == 0) {
        float lmin = 3.4e38f, lmax = -3.4e38f;
#pragma unroll
        for (int j = 0; j < 16; j++) {
            int c0 = cb + j * 8;
            bool v0 = c0 < NN, v1 = c0 + 1 < NN;
            if (vlo && v0) { lmin = fminf(lmin, c[j][0]); lmax = fmaxf(lmax, c[j][0]); }
            if (vlo && v1) { lmin = fminf(lmin, c[j][1]); lmax = fmaxf(lmax, c[j][1]); }
            if (vhi && v0) { lmin = fminf(lmin, c[j][2]); lmax = fmaxf(lmax, c[j][2]); }
            if (vhi && v1) { lmin = fminf(lmin, c[j][3]); lmax = fmaxf(lmax, c[j][3]); }
        }
        for (int o = 16; o; o >>= 1) {
            lmin = fminf(lmin, __shfl_down_sync(0xffffffffu, lmin, o));
            lmax = fmaxf(lmax, __shfl_down_sync(0xffffffffu, lmax, o));
        }
        if (lane == 0) {
            atomicMin(&g_keymin, fkey(lmin));
            atomicMax(&g_keymax, fkey(lmax));
        }
    } else {
        __syncthreads();
        float lo_r = fdec(g_keymin), hi_r = fdec(g_keymax);
        float inv = 1.0f / ((hi_r - lo_r) + 1e-12f);
        u64 cl = 0ull, ch = 0ull;
#pragma unroll
        for (int j = 0; j < 16; j++) {
            int c0 = cb + j * 8;
            bool vc[2] = {c0 < NN, c0 + 1 < NN};
            bool vr[2] = {vlo, vhi};
#pragma unroll
            for (int r = 0; r < 4; r++) {
                if (!(vr[r >> 1] && vc[r & 1])) continue;
                float q = (c[j][r] - lo_r) * inv;
                int b = (int)(q * 16.0f);
                b = min(max(b, 0), 15);
                if (b < 8) cl += 1ull << (b * 8);
                else       ch += 1ull << ((b - 8) * 8);
            }
        }
#pragma unroll
        for (int b = 0; b < 16; b++) {
            unsigned v = (unsigned)((b < 8 ? (cl >> (b * 8)) : (ch >> ((b - 8) * 8))) & 0xFFull);
            for (int o = 16; o; o >>= 1) v += __shfl_down_sync(0xffffffffu, v, o);
            if (lane == 0 && v) atomicAdd(&sh[b], v);
        }
        __syncthreads();
        if (tid < 16 && sh[tid]) atomicAdd(&g_hist[tid * 32], sh[tid]);
    }
}

// ---------------- attention ----------------
__global__ void k_colmean() {
    int z = blockIdx.z;
    const float* X = g_af[z];
    int lane = threadIdx.x & 31;
    int w = (blockIdx.x * blockDim.x + threadIdx.x) >> 5;
    int nw = (gridDim.x * blockDim.x) >> 5;
    float acc = 0.f;
    for (int n = w; n < NN; n += nw) acc += X[n * 32 + lane];
    atomicAdd(&g_meanraw[z][lane], acc);
}
__global__ void k_gc2(const float* __restrict__ att_w) {
    int g = threadIdx.x >> 5, j = threadIdx.x & 31;
    float acc = 0.f;
    const float invN = 1.0f / NN;
    for (int f = 0; f < 32; f++)
        acc += (g_meanraw[g][f] * invN) * att_w[f * 32 + j];
    g_gc[g][j] = tanhf(acc);
}
__global__ void k_pool() {
    int z = blockIdx.z;
    const float* X = g_af[z];
    int lane = threadIdx.x & 31;
    int w = (blockIdx.x * blockDim.x + threadIdx.x) >> 5;
    int nw = (gridDim.x * blockDim.x) >> 5;
    float gcv = g_gc[z][lane];
    float acc = 0.f;
    for (int n = w; n < NN; n += nw) {
        float x = X[n * 32 + lane];
        float p = x * gcv;
        for (int o = 16; o; o >>= 1) p += __shfl_xor_sync(0xffffffffu, p, o);
        float sig = 1.0f / (1.0f + expf(-p));
        acc += x * sig;
    }
    atomicAdd(&g_pool[z][lane], acc);
}

// ---------------- tensor network ----------------
__global__ void k_tnprep(const float* __restrict__ tn_w, const float* __restrict__ tn_wb,
                         const float* __restrict__ tn_bias) {
    int t = threadIdx.x;
    int slot = t >> 9;
    int r = t & 511;
    int f = r >> 4, k = r & 15;
    const float* e2 = g_pool[1 - slot];
    float acc = tn_wb[k * 64 + f];
    for (int gg = 0; gg < 32; gg++)
        acc += tn_w[f * 512 + gg * 16 + k] * e2[gg];
    g_A[slot][f * 16 + k] = acc;
    if (t < 32) {
        int sl = t >> 4, kk = t & 15;
        const float* e2b = g_pool[1 - sl];
        float c = tn_bias[kk];
        for (int gg = 0; gg < 32; gg++)
            c += tn_wb[kk * 64 + 32 + gg] * e2b[gg];
        g_c[sl][kk] = c;
    }
    __syncthreads();
    if (t < 16) {
        float acc2 = g_c[0][t];
        for (int f2 = 0; f2 < 32; f2++)
            acc2 += g_pool[0][f2] * g_A[0][f2 * 16 + t];
        g_s0[t] = fmaxf(acc2, 0.f);
    }
}
__global__ void k_tnnodes() {
    int z = blockIdx.z;
    const float* X = g_af[z];
    int lane = threadIdx.x & 31;
    int w = (blockIdx.x * blockDim.x + threadIdx.x) >> 5;
    int nw = (gridDim.x * blockDim.x) >> 5;
    float acc = 0.f;
    for (int n = w; n < NN; n += nw) {
        float x = X[n * 32 + lane];
        float v = (lane < 16) ? g_c[z][lane] : 0.f;
#pragma unroll
        for (int f = 0; f < 32; f++) {
            float xf = __shfl_sync(0xffffffffu, x, f);
            if (lane < 16) v += xf * g_A[z][f * 16 + lane];
        }
        if (lane < 16) acc += fmaxf(v, 0.f);
    }
    if (lane < 16) atomicAdd(&g_sAcc[z][lane], acc);
}

// ---------------- final head ----------------
__global__ void k_final(const float* __restrict__ fc1_w, const float* __restrict__ fc1_b,
                        const float* __restrict__ fc2_w, const float* __restrict__ fc2_b,
                        float* __restrict__ out) {
    if (threadIdx.x != 0) return;
    float sc[64];
    const float invN = 1.0f / NN;
    for (int k = 0; k < 16; k++) {
        sc[k]      = g_s0[k];
        sc[16 + k] = g_sAcc[0][k] * invN;
        sc[32 + k] = g_sAcc[1][k] * invN;
    }
    float hf[16], hsum = 0.f;
    for (int b = 0; b < 16; b++) {
        unsigned c = g_hist[b * 32];
        if (c > 16777216u) c = 16777216u;
        hf[b] = (float)c;
        hsum += hf[b];
    }
    for (int b = 0; b < 16; b++) sc[48 + b] = hf[b] / hsum;
    float o2 = fc2_b[0];
    for (int j = 0; j < 16; j++) {
        float a = fc1_b[j];
        for (int i = 0; i < 64; i++) a += sc[i] * fc1_w[i * 16 + j];
        a = fmaxf(a, 0.f);
        o2 += a * fc2_w[j];
    }
    out[0] = 1.0f / (1.0f + expf(-o2));
}

// ---------------- host driver ----------------
extern "C" void kernel_launch(void* const* d_in, const int* in_sizes, int n_in,
                              void* d_out, int out_size) {
    const float* feat1 = (const float*)d_in[0];
    const float* feat2 = (const float*)d_in[1];
    const int* ei1 = (const int*)d_in[2];
    const int* ei2 = (const int*)d_in[3];
    const float* W1 = (const float*)d_in[4];
    const float* b1 = (const float*)d_in[5];
    const float* W2 = (const float*)d_in[6];
    const float* b2 = (const float*)d_in[7];
    const float* W3 = (const float*)d_in[8];
    const float* b3 = (const float*)d_in[9];
    const float* att_w = (const float*)d_in[10];
    const float* tn_w = (const float*)d_in[11];
    const float* tn_wb = (const float*)d_in[12];
    const float* tn_bias = (const float*)d_in[13];
    const float* fc1_w = (const float*)d_in[14];
    const float* fc1_b = (const float*)d_in[15];
    const float* fc2_w = (const float*)d_in[16];
    const float* fc2_b = (const float*)d_in[17];
    float* out = (float*)d_out;

    float *H0, *H1, *X0, *X1, *af0, *af1;
    cudaGetSymbolAddress((void**)&H0, g_H);   H1 = H0 + NN * 128;
    cudaGetSymbolAddress((void**)&X0, g_X);   X1 = X0 + NN * 128;
    cudaGetSymbolAddress((void**)&af0, g_af); af1 = af0 + NN * 32;

    k_reset<<<1, 1024>>>();
    k_indeg<<<(2 * EE + 255) / 256, 256>>>(ei1, ei2);
    k_scan<<<2, 1024>>>();
    k_fill<<<(2 * EE + 255) / 256, 256>>>(ei1, ei2);

    dim3 ggrid((NN + 127) / 128, 1, 2);
    k_tgemm<128, 128, 0><<<ggrid, 256>>>(feat1, feat2, W1, H0, H1);
    {
        dim3 grid((NN * 32 + 255) / 256, 1, 2);
        k_gather<<<grid, 256>>>(H0, H1, b1, X0, X1, 128);
    }
    k_tgemm<64, 128, 1><<<ggrid, 256>>>(X0, X1, W2, H0, H1);
    {
        dim3 grid((NN * 16 + 255) / 256, 1, 2);
        k_gather<<<grid, 256>>>(H0, H1, b2, X0, X1, 64);
    }
    k_tgemm<32, 64, 1><<<ggrid, 256>>>(X0, X1, W3, H0, H1);
    {
        dim3 grid((NN * 8 + 255) / 256, 1, 2);
        k_gather<<<grid, 256>>>(H0, H1, b3, af0, af1, 32);
    }

    // tf32 fragment pack (af1 -> A-frags, af2 -> B-frags)
    {
        int warps = MT_TILES * 4 + NT_TILES * 4;
        k_frag<<<(warps * 32 + 255) / 256, 256>>>();
    }

    dim3 hgrid((NN + 127) / 128, (NN + 127) / 128);
    k_simpass<<<hgrid, 256>>>(0);
    k_simpass<<<hgrid, 256>>>(1);

    dim3 pg(40, 1, 2);
    k_colmean<<<pg, 256>>>();
    k_gc2<<<1, 64>>>(att_w);
    k_pool<<<pg, 256>>>();

    k_tnprep<<<1, 1024>>>(tn_w, tn_wb, tn_bias);
    k_tnnodes<<<pg, 256>>>();

    k_final<<<1, 32>>>(fc1_w, fc1_b, fc2_w, fc2_b, out);
}

// round 6
// speedup vs baseline: 3.1174x; 1.0158x over previous
#include <cuda_runtime.h>
#include <math.h>

#define NN 10000
#define EE 320000
#define MT_TILES 632
#define NT_TILES 1264
#define TAILB 80
typedef unsigned long long u64;

// ---------------- device scratch ----------------
__device__ float g_H[2][NN * 128];
__device__ float g_X[2][NN * 128];
__device__ float g_af[2][NN * 32];
__device__ uint4 g_fA[MT_TILES * 4 * 32];
__device__ uint2 g_fB[NT_TILES * 4 * 32];
__device__ float g_dinv[2][NN];
__device__ int   g_indeg[2][NN];
__device__ int   g_rowstart[2][NN + 1];
__device__ int   g_cursor[2][NN];
__device__ int2  g_adjc[2][EE];          // (src, coef-bits)
__device__ unsigned g_keymin, g_keymax;
__device__ unsigned g_hist[16 * 32];
__device__ unsigned g_barctr[8];
__device__ float g_meanraw[2][32];
__device__ float g_gc[2][32];
__device__ float g_pool[2][32];
__device__ float g_A[2][32 * 16];
__device__ float g_c[2][16];
__device__ float g_sAcc[2][16];
__device__ float g_s0[16];

// ---------------- helpers ----------------
__device__ __forceinline__ unsigned fkey(float f) {
    unsigned u = __float_as_uint(f);
    return (u & 0x80000000u) ? ~u : (u | 0x80000000u);
}
__device__ __forceinline__ float fdec(unsigned k) {
    return (k & 0x80000000u) ? __uint_as_float(k ^ 0x80000000u)
                             : __uint_as_float(~k);
}
__device__ __forceinline__ u64 dup2(float a) {
    u64 r;
    asm("mov.b64 %0, {%1, %1};" : "=l"(r) : "r"(__float_as_uint(a)));
    return r;
}
__device__ __forceinline__ void ffma2(u64& acc, u64 a, u64 b) {
    asm("fma.rn.f32x2 %0, %1, %2, %0;" : "+l"(acc) : "l"(a), "l"(b));
}
__device__ __forceinline__ void unpk(u64 v, float& lo, float& hi) {
    unsigned l, h;
    asm("mov.b64 {%0, %1}, %2;" : "=r"(l), "=r"(h) : "l"(v));
    lo = __uint_as_float(l); hi = __uint_as_float(h);
}
__device__ __forceinline__ unsigned totf32(float f) {
    unsigned r;
    asm("cvt.rna.tf32.f32 %0, %1;" : "=r"(r) : "f"(f));
    return r;
}
__device__ __forceinline__ void mma_tf32(float c[4], uint4 a, uint2 b) {
    asm("mma.sync.aligned.m16n8k8.row.col.f32.tf32.tf32.f32 "
        "{%0,%1,%2,%3}, {%4,%5,%6,%7}, {%8,%9}, {%0,%1,%2,%3};"
        : "+f"(c[0]), "+f"(c[1]), "+f"(c[2]), "+f"(c[3])
        : "r"(a.x), "r"(a.y), "r"(a.z), "r"(a.w), "r"(b.x), "r"(b.y));
}
__device__ __forceinline__ void gridbar(int ph) {
    __syncthreads();
    if (threadIdx.x == 0) {
        __threadfence();
        unsigned t = atomicAdd(&g_barctr[ph], 1u) + 1;
        if (t < TAILB) {
            while (((volatile unsigned*)g_barctr)[ph] < TAILB) { }
        }
        __threadfence();
    }
    __syncthreads();
}

// ---------------- reset ----------------
__global__ void k_reset() {
    int t = threadIdx.x;
    for (int i = t; i < 2 * NN; i += 1024)
        ((int*)g_indeg)[i] = 0;
    if (t < 16 * 32) g_hist[t] = 0u;
    if (t < 32) {
        g_meanraw[0][t] = 0.f; g_meanraw[1][t] = 0.f;
        g_pool[0][t] = 0.f;    g_pool[1][t] = 0.f;
    }
    if (t < 16) { g_sAcc[0][t] = 0.f; g_sAcc[1][t] = 0.f; }
    if (t < 8) g_barctr[t] = 0u;
    if (t == 0) { g_keymin = 0xFFFFFFFFu; g_keymax = 0u; }
}

// ---------------- CSR build ----------------
__global__ void k_indeg(const int* __restrict__ ei1, const int* __restrict__ ei2) {
    int t = blockIdx.x * 256 + threadIdx.x;
    if (t >= 2 * EE) return;
    int g = t >= EE;
    const int* ei = g ? ei2 : ei1;
    int e = t - g * EE;
    atomicAdd(&g_indeg[g][ei[EE + e]], 1);
}

__global__ void k_scan() {   // grid=2, block=1024
    int g = blockIdx.x, t = threadIdx.x;
    int lane = t & 31, w = t >> 5;
    __shared__ int warpsum[32];
    __shared__ int s_carry;
    if (t == 0) s_carry = 0;
    __syncthreads();
    for (int base = 0; base < NN; base += 1024) {
        int i = base + t;
        int v = (i < NN) ? g_indeg[g][i] : 0;
        int x = v;
#pragma unroll
        for (int o = 1; o < 32; o <<= 1) {
            int y = __shfl_up_sync(0xffffffffu, x, o);
            if (lane >= o) x += y;
        }
        if (lane == 31) warpsum[w] = x;
        __syncthreads();
        if (w == 0) {
            int ws = warpsum[lane];
#pragma unroll
            for (int o = 1; o < 32; o <<= 1) {
                int y = __shfl_up_sync(0xffffffffu, ws, o);
                if (lane >= o) ws += y;
            }
            warpsum[lane] = ws;
        }
        __syncthreads();
        int carry = s_carry;
        int excl = carry + (x - v) + (w ? warpsum[w - 1] : 0);
        if (i < NN) {
            g_rowstart[g][i] = excl;
            g_cursor[g][i] = excl;
            g_dinv[g][i] = rsqrtf((float)v + 1.0f);
        }
        int total = warpsum[31];
        __syncthreads();
        if (t == 0) s_carry = carry + total;
        __syncthreads();
    }
    if (t == 0) g_rowstart[g][NN] = s_carry;
}

__global__ void k_fill(const int* __restrict__ ei1, const int* __restrict__ ei2) {
    int t = blockIdx.x * 256 + threadIdx.x;
    if (t >= 2 * EE) return;
    int g = t >= EE;
    const int* ei = g ? ei2 : ei1;
    int e = t - g * EE;
    int s = ei[e], d = ei[EE + e];
    int pos = atomicAdd(&g_cursor[g][d], 1);
    float coef = g_dinv[g][s] * g_dinv[g][d];
    g_adjc[g][pos] = make_int2(s, __float_as_int(coef));
}

// ---------------- tiled GEMM: H = relu?(X) @ W ----------------
template <int FOUT, int KTOT, int RELU>
__global__ void __launch_bounds__(256, 2)
k_tgemm(const float* __restrict__ X0, const float* __restrict__ X1,
        const float* __restrict__ W,
        float* __restrict__ H0, float* __restrict__ H1) {
    constexpr int CPT = FOUT / 32;
    __shared__ __align__(16) float As[32][132];
    __shared__ __align__(16) float Ws[32][FOUT];
    int z = blockIdx.z;
    const float* X = z ? X1 : X0;
    float* H = z ? H1 : H0;
    int tid = threadIdx.x;
    int i0 = blockIdx.x * 128;
    int tx = tid & 31, ty = tid >> 5;
    u64 acc2[8][CPT];
#pragma unroll
    for (int r = 0; r < 8; r++)
#pragma unroll
        for (int c = 0; c < CPT; c++) acc2[r][c] = 0ull;

    for (int k0 = 0; k0 < KTOT; k0 += 32) {
        for (int idx = tid; idx < 1024; idx += 256) {
            int r = idx >> 3, k4 = idx & 7;
            int row = i0 + r;
            float4 v = make_float4(0.f, 0.f, 0.f, 0.f);
            if (row < NN) v = *(const float4*)&X[(size_t)row * KTOT + k0 + k4 * 4];
            if (RELU) {
                v.x = fmaxf(v.x, 0.f); v.y = fmaxf(v.y, 0.f);
                v.z = fmaxf(v.z, 0.f); v.w = fmaxf(v.w, 0.f);
            }
            As[k4 * 4 + 0][r] = v.x; As[k4 * 4 + 1][r] = v.y;
            As[k4 * 4 + 2][r] = v.z; As[k4 * 4 + 3][r] = v.w;
        }
        for (int idx = tid; idx < 8 * FOUT; idx += 256) {
            int j4 = idx % (FOUT / 4), kk = idx / (FOUT / 4);
            float4 w = *(const float4*)&W[(size_t)(k0 + kk) * FOUT + j4 * 4];
            Ws[kk][j4 * 4 + 0] = w.x; Ws[kk][j4 * 4 + 1] = w.y;
            Ws[kk][j4 * 4 + 2] = w.z; Ws[kk][j4 * 4 + 3] = w.w;
        }
        __syncthreads();
#pragma unroll 4
        for (int k = 0; k < 32; k++) {
            u64 aa[8];
            {
                const ulonglong2* ap = (const ulonglong2*)&As[k][ty * 16];
                ulonglong2 t0 = ap[0], t1 = ap[1], t2 = ap[2], t3 = ap[3];
                aa[0] = t0.x; aa[1] = t0.y; aa[2] = t1.x; aa[3] = t1.y;
                aa[4] = t2.x; aa[5] = t2.y; aa[6] = t3.x; aa[7] = t3.y;
            }
            u64 bd[CPT];
            if (CPT == 4) {
                float4 b = *(const float4*)&Ws[k][tx * 4];
                bd[0] = dup2(b.x); bd[1] = dup2(b.y);
                bd[2] = dup2(b.z); bd[3] = dup2(b.w);
            } else if (CPT == 2) {
                float2 b = *(const float2*)&Ws[k][tx * 2];
                bd[0] = dup2(b.x); bd[1] = dup2(b.y);
            } else {
                bd[0] = dup2(Ws[k][tx]);
            }
#pragma unroll
            for (int r = 0; r < 8; r++)
#pragma unroll
                for (int c = 0; c < CPT; c++) ffma2(acc2[r][c], aa[r], bd[c]);
        }
        __syncthreads();
    }
#pragma unroll
    for (int rp = 0; rp < 8; rp++) {
        int r0 = i0 + ty * 16 + 2 * rp;
        float lo[CPT], hi[CPT];
#pragma unroll
        for (int c = 0; c < CPT; c++) unpk(acc2[rp][c], lo[c], hi[c]);
        if (r0 < NN) {
            float* p = H + (size_t)r0 * FOUT + tx * CPT;
            if (CPT == 4) *(float4*)p = make_float4(lo[0], lo[1], lo[2], lo[3]);
            else if (CPT == 2) *(float2*)p = make_float2(lo[0], lo[1]);
            else *p = lo[0];
        }
        if (r0 + 1 < NN) {
            float* p = H + (size_t)(r0 + 1) * FOUT + tx * CPT;
            if (CPT == 4) *(float4*)p = make_float4(hi[0], hi[1], hi[2], hi[3]);
            else if (CPT == 2) *(float2*)p = make_float2(hi[0], hi[1]);
            else *p = hi[0];
        }
    }
}

// ---------------- gather: O[d] = H[d]/deg + b + sum_in coef*H[s] ----------------
__global__ void k_gather(const float* __restrict__ H0, const float* __restrict__ H1,
                         const float* __restrict__ b,
                         float* __restrict__ O0, float* __restrict__ O1, int Fout) {
    int z = blockIdx.z;
    const float* H = z ? H1 : H0;
    float* O = z ? O1 : O0;
    int gpf = Fout >> 2;
    int idx = blockIdx.x * 256 + threadIdx.x;
    int node = idx / gpf;
    int c = idx - node * gpf;
    if (node >= NN) return;
    int rs = g_rowstart[z][node], re = g_rowstart[z][node + 1];
    float invdeg = 1.0f / ((float)(re - rs) + 1.0f);
    float4 hs = ((const float4*)(H + (size_t)node * Fout))[c];
    float4 bb = ((const float4*)b)[c];
    float4 acc;
    acc.x = hs.x * invdeg + bb.x; acc.y = hs.y * invdeg + bb.y;
    acc.z = hs.z * invdeg + bb.z; acc.w = hs.w * invdeg + bb.w;
    const int2* __restrict__ adjc = g_adjc[z];
#pragma unroll 4
    for (int e = rs; e < re; e++) {
        int2 sc = __ldg(&adjc[e]);
        float coef = __int_as_float(sc.y);
        float4 v = ((const float4*)(H + (size_t)sc.x * Fout))[c];
        acc.x += coef * v.x; acc.y += coef * v.y;
        acc.z += coef * v.z; acc.w += coef * v.w;
    }
    ((float4*)(O + (size_t)node * Fout))[c] = acc;
}

// ---------------- fragment builder ----------------
__device__ __forceinline__ float afld(const float* af, int n, int k) {
    return (n < NN) ? af[n * 32 + k] : 0.f;
}
__global__ void k_frag() {
    int wg = (blockIdx.x * 256 + threadIdx.x) >> 5;
    int lane = threadIdx.x & 31;
    if (wg < MT_TILES * 4) {
        int mt = wg >> 2, ks = wg & 3;
        const float* af = g_af[0];
        int r0 = mt * 16 + (lane >> 2);
        int c0 = ks * 8 + (lane & 3);
        uint4 v;
        v.x = totf32(afld(af, r0,     c0));
        v.y = totf32(afld(af, r0 + 8, c0));
        v.z = totf32(afld(af, r0,     c0 + 4));
        v.w = totf32(afld(af, r0 + 8, c0 + 4));
        g_fA[(mt * 4 + ks) * 32 + lane] = v;
    } else if (wg < MT_TILES * 4 + NT_TILES * 4) {
        int w = wg - MT_TILES * 4;
        int nt = w >> 2, ks = w & 3;
        const float* af = g_af[1];
        int n = nt * 8 + (lane >> 2);
        int k = ks * 8 + (lane & 3);
        uint2 v;
        v.x = totf32(afld(af, n, k));
        v.y = totf32(afld(af, n, k + 4));
        g_fB[(nt * 4 + ks) * 32 + lane] = v;
    }
}

// ---------------- similarity passes via tf32 mma ----------------
__global__ void __launch_bounds__(256, 2)
k_simpass(int pass) {
    __shared__ unsigned sh[16];
    int tid = threadIdx.x, lane = tid & 31, w = tid >> 5;
    int mt = blockIdx.y * 8 + w;
    int bx = blockIdx.x;
    float c[16][4];
#pragma unroll
    for (int j = 0; j < 16; j++)
#pragma unroll
        for (int r = 0; r < 4; r++) c[j][r] = 0.f;
    if (pass && tid < 16) sh[tid] = 0u;
#pragma unroll
    for (int ks = 0; ks < 4; ks++) {
        uint4 a = g_fA[(mt * 4 + ks) * 32 + lane];
#pragma unroll
        for (int j = 0; j < 16; j++) {
            uint2 b = g_fB[((bx * 16 + j) * 4 + ks) * 32 + lane];
            mma_tf32(c[j], a, b);
        }
    }
    int r_lo = mt * 16 + (lane >> 2);
    int r_hi = r_lo + 8;
    int cb = bx * 128 + 2 * (lane & 3);
    bool vlo = r_lo < NN, vhi = r_hi < NN;
    if (pass == 0) {
        float lmin = 3.4e38f, lmax = -3.4e38f;
#pragma unroll
        for (int j = 0; j < 16; j++) {
            int c0 = cb + j * 8;
            bool v0 = c0 < NN, v1 = c0 + 1 < NN;
            if (vlo && v0) { lmin = fminf(lmin, c[j][0]); lmax = fmaxf(lmax, c[j][0]); }
            if (vlo && v1) { lmin = fminf(lmin, c[j][1]); lmax = fmaxf(lmax, c[j][1]); }
            if (vhi && v0) { lmin = fminf(lmin, c[j][2]); lmax = fmaxf(lmax, c[j][2]); }
            if (vhi && v1) { lmin = fminf(lmin, c[j][3]); lmax = fmaxf(lmax, c[j][3]); }
        }
        for (int o = 16; o; o >>= 1) {
            lmin = fminf(lmin, __shfl_down_sync(0xffffffffu, lmin, o));
            lmax = fmaxf(lmax, __shfl_down_sync(0xffffffffu, lmax, o));
        }
        if (lane == 0) {
            atomicMin(&g_keymin, fkey(lmin));
            atomicMax(&g_keymax, fkey(lmax));
        }
    } else {
        __syncthreads();
        float lo_r = fdec(g_keymin), hi_r = fdec(g_keymax);
        float inv = 1.0f / ((hi_r - lo_r) + 1e-12f);
        u64 cl = 0ull, ch = 0ull;
#pragma unroll
        for (int j = 0; j < 16; j++) {
            int c0 = cb + j * 8;
            bool vc[2] = {c0 < NN, c0 + 1 < NN};
            bool vr[2] = {vlo, vhi};
#pragma unroll
            for (int r = 0; r < 4; r++) {
                if (!(vr[r >> 1] && vc[r & 1])) continue;
                float q = (c[j][r] - lo_r) * inv;
                int b = (int)(q * 16.0f);
                b = min(max(b, 0), 15);
                if (b < 8) cl += 1ull << (b * 8);
                else       ch += 1ull << ((b - 8) * 8);
            }
        }
#pragma unroll
        for (int b = 0; b < 16; b++) {
            unsigned v = (unsigned)((b < 8 ? (cl >> (b * 8)) : (ch >> ((b - 8) * 8))) & 0xFFull);
            for (int o = 16; o; o >>= 1) v += __shfl_down_sync(0xffffffffu, v, o);
            if (lane == 0 && v) atomicAdd(&sh[b], v);
        }
        __syncthreads();
        if (tid < 16 && sh[tid]) atomicAdd(&g_hist[tid * 32], sh[tid]);
    }
}

// ---------------- fused tail: colmean->gc->pool->tnprep->tnnodes->final ----------------
__global__ void __launch_bounds__(256, 4)
k_tail(const float* __restrict__ att_w,
       const float* __restrict__ tn_w, const float* __restrict__ tn_wb,
       const float* __restrict__ tn_bias,
       const float* __restrict__ fc1_w, const float* __restrict__ fc1_b,
       const float* __restrict__ fc2_w, const float* __restrict__ fc2_b,
       float* __restrict__ out) {
    int bid = blockIdx.x, tid = threadIdx.x;
    int z = bid >= (TAILB / 2);
    int lb = z ? bid - TAILB / 2 : bid;
    int lane = tid & 31;
    int wz = (lb * 256 + tid) >> 5;
    const int nwz = (TAILB / 2) * 256 / 32;
    const float* X = g_af[z];

    // P1: column mean accumulation
    {
        float acc = 0.f;
        for (int n = wz; n < NN; n += nwz) acc += X[n * 32 + lane];
        atomicAdd(&g_meanraw[z][lane], acc);
    }
    gridbar(0);
    // P2: global context vector
    if (bid == 0 && tid < 64) {
        int g = tid >> 5, j = tid & 31;
        float acc = 0.f;
        const float invN = 1.0f / NN;
        for (int f = 0; f < 32; f++)
            acc += (g_meanraw[g][f] * invN) * att_w[f * 32 + j];
        g_gc[g][j] = tanhf(acc);
    }
    gridbar(1);
    // P3: attention pooling
    {
        float gcv = g_gc[z][lane];
        float acc = 0.f;
        for (int n = wz; n < NN; n += nwz) {
            float x = X[n * 32 + lane];
            float p = x * gcv;
            for (int o = 16; o; o >>= 1) p += __shfl_xor_sync(0xffffffffu, p, o);
            float sig = 1.0f / (1.0f + expf(-p));
            acc += x * sig;
        }
        atomicAdd(&g_pool[z][lane], acc);
    }
    gridbar(2);
    // P4: tensor-network prep + s0
    if (bid == 0) {
        for (int t = tid; t < 1024; t += 256) {
            int slot = t >> 9, r = t & 511, f = r >> 4, k = r & 15;
            const float* e2 = g_pool[1 - slot];
            float acc = tn_wb[k * 64 + f];
            for (int gg = 0; gg < 32; gg++)
                acc += tn_w[f * 512 + gg * 16 + k] * e2[gg];
            g_A[slot][f * 16 + k] = acc;
        }
        if (tid < 32) {
            int sl = tid >> 4, kk = tid & 15;
            const float* e2b = g_pool[1 - sl];
            float cc = tn_bias[kk];
            for (int gg = 0; gg < 32; gg++)
                cc += tn_wb[kk * 64 + 32 + gg] * e2b[gg];
            g_c[sl][kk] = cc;
        }
        __syncthreads();
        if (tid < 16) {
            float a2 = g_c[0][tid];
            for (int f2 = 0; f2 < 32; f2++)
                a2 += g_pool[0][f2] * g_A[0][f2 * 16 + tid];
            g_s0[tid] = fmaxf(a2, 0.f);
        }
    }
    gridbar(3);
    // P5: per-node TN mean accumulation
    {
        float acc = 0.f;
        for (int n = wz; n < NN; n += nwz) {
            float x = X[n * 32 + lane];
            float v = (lane < 16) ? g_c[z][lane] : 0.f;
#pragma unroll
            for (int f = 0; f < 32; f++) {
                float xf = __shfl_sync(0xffffffffu, x, f);
                if (lane < 16) v += xf * g_A[z][f * 16 + lane];
            }
            if (lane < 16) acc += fmaxf(v, 0.f);
        }
        if (lane < 16) atomicAdd(&g_sAcc[z][lane], acc);
    }
    gridbar(4);
    // P6: final head
    if (bid == 0 && tid == 0) {
        float sc[64];
        const float invN = 1.0f / NN;
        for (int k = 0; k < 16; k++) {
            sc[k]      = g_s0[k];
            sc[16 + k] = g_sAcc[0][k] * invN;
            sc[32 + k] = g_sAcc[1][k] * invN;
        }
        float hf[16], hsum = 0.f;
        for (int b = 0; b < 16; b++) {
            unsigned c = g_hist[b * 32];
            if (c > 16777216u) c = 16777216u;
            hf[b] = (float)c;
            hsum += hf[b];
        }
        for (int b = 0; b < 16; b++) sc[48 + b] = hf[b] / hsum;
        float o2 = fc2_b[0];
        for (int j = 0; j < 16; j++) {
            float a = fc1_b[j];
            for (int i = 0; i < 64; i++) a += sc[i] * fc1_w[i * 16 + j];
            a = fmaxf(a, 0.f);
            o2 += a * fc2_w[j];
        }
        out[0] = 1.0f / (1.0f + expf(-o2));
    }
}

// ---------------- host driver ----------------
extern "C" void kernel_launch(void* const* d_in, const int* in_sizes, int n_in,
                              void* d_out, int out_size) {
    const float* feat1 = (const float*)d_in[0];
    const float* feat2 = (const float*)d_in[1];
    const int* ei1 = (const int*)d_in[2];
    const int* ei2 = (const int*)d_in[3];
    const float* W1 = (const float*)d_in[4];
    const float* b1 = (const float*)d_in[5];
    const float* W2 = (const float*)d_in[6];
    const float* b2 = (const float*)d_in[7];
    const float* W3 = (const float*)d_in[8];
    const float* b3 = (const float*)d_in[9];
    const float* att_w = (const float*)d_in[10];
    const float* tn_w = (const float*)d_in[11];
    const float* tn_wb = (const float*)d_in[12];
    const float* tn_bias = (const float*)d_in[13];
    const float* fc1_w = (const float*)d_in[14];
    const float* fc1_b = (const float*)d_in[15];
    const float* fc2_w = (const float*)d_in[16];
    const float* fc2_b = (const float*)d_in[17];
    float* out = (float*)d_out;

    float *H0, *H1, *X0, *X1, *af0, *af1;
    cudaGetSymbolAddress((void**)&H0, g_H);   H1 = H0 + NN * 128;
    cudaGetSymbolAddress((void**)&X0, g_X);   X1 = X0 + NN * 128;
    cudaGetSymbolAddress((void**)&af0, g_af); af1 = af0 + NN * 32;

    k_reset<<<1, 1024>>>();
    k_indeg<<<(2 * EE + 255) / 256, 256>>>(ei1, ei2);
    k_scan<<<2, 1024>>>();
    k_fill<<<(2 * EE + 255) / 256, 256>>>(ei1, ei2);

    dim3 ggrid((NN + 127) / 128, 1, 2);
    k_tgemm<128, 128, 0><<<ggrid, 256>>>(feat1, feat2, W1, H0, H1);
    {
        dim3 grid((NN * 32 + 255) / 256, 1, 2);
        k_gather<<<grid, 256>>>(H0, H1, b1, X0, X1, 128);
    }
    k_tgemm<64, 128, 1><<<ggrid, 256>>>(X0, X1, W2, H0, H1);
    {
        dim3 grid((NN * 16 + 255) / 256, 1, 2);
        k_gather<<<grid, 256>>>(H0, H1, b2, X0, X1, 64);
    }
    k_tgemm<32, 64, 1><<<ggrid, 256>>>(X0, X1, W3, H0, H1);
    {
        dim3 grid((NN * 8 + 255) / 256, 1, 2);
        k_gather<<<grid, 256>>>(H0, H1, b3, af0, af1, 32);
    }

    {
        int warps = MT_TILES * 4 + NT_TILES * 4;
        k_frag<<<(warps * 32 + 255) / 256, 256>>>();
    }

    dim3 hgrid((NN + 127) / 128, (NN + 127) / 128);
    k_simpass<<<hgrid, 256>>>(0);
    k_simpass<<<hgrid, 256>>>(1);

    k_tail<<<TAILB, 256>>>(att_w, tn_w, tn_wb, tn_bias,
                           fc1_w, fc1_b, fc2_w, fc2_b, out);
}

// round 7
// speedup vs baseline: 3.4626x; 1.1107x over previous
#include <cuda_runtime.h>
#include <math.h>

#define NN 10000
#define EE 320000
#define MT_TILES 632
#define NT_TILES 1264
#define TAILB 80
typedef unsigned long long u64;

// ---------------- device scratch ----------------
__device__ float g_H[2][NN * 128];
__device__ float g_X[2][NN * 128];
__device__ float g_af[2][NN * 32];
__device__ uint4 g_fA[MT_TILES * 4 * 32];
__device__ uint2 g_fB[NT_TILES * 4 * 32];
__device__ float g_dinv[2][NN];
__device__ int   g_indeg[2][NN];
__device__ int   g_rowstart[2][NN + 1];
__device__ int   g_cursor[2][NN];
__device__ int2  g_adjc[2][EE];
__device__ unsigned g_keymin, g_keymax;
__device__ unsigned g_hist[16 * 32];
__device__ unsigned g_barctr[8];
__device__ float g_meanraw[2][32];
__device__ float g_gc[2][32];
__device__ float g_pool[2][32];
__device__ float g_A[2][32 * 16];
__device__ float g_c[2][16];
__device__ float g_sAcc[2][16];
__device__ float g_s0[16];

// ---------------- helpers ----------------
__device__ __forceinline__ unsigned fkey(float f) {
    unsigned u = __float_as_uint(f);
    return (u & 0x80000000u) ? ~u : (u | 0x80000000u);
}
__device__ __forceinline__ float fdec(unsigned k) {
    return (k & 0x80000000u) ? __uint_as_float(k ^ 0x80000000u)
                             : __uint_as_float(~k);
}
__device__ __forceinline__ u64 dup2(float a) {
    u64 r;
    asm("mov.b64 %0, {%1, %1};" : "=l"(r) : "r"(__float_as_uint(a)));
    return r;
}
__device__ __forceinline__ void ffma2(u64& acc, u64 a, u64 b) {
    asm("fma.rn.f32x2 %0, %1, %2, %0;" : "+l"(acc) : "l"(a), "l"(b));
}
__device__ __forceinline__ void unpk(u64 v, float& lo, float& hi) {
    unsigned l, h;
    asm("mov.b64 {%0, %1}, %2;" : "=r"(l), "=r"(h) : "l"(v));
    lo = __uint_as_float(l); hi = __uint_as_float(h);
}
__device__ __forceinline__ unsigned totf32(float f) {
    unsigned r;
    asm("cvt.rna.tf32.f32 %0, %1;" : "=r"(r) : "f"(f));
    return r;
}
__device__ __forceinline__ void mma_tf32(float c[4], uint4 a, uint2 b) {
    asm("mma.sync.aligned.m16n8k8.row.col.f32.tf32.tf32.f32 "
        "{%0,%1,%2,%3}, {%4,%5,%6,%7}, {%8,%9}, {%0,%1,%2,%3};"
        : "+f"(c[0]), "+f"(c[1]), "+f"(c[2]), "+f"(c[3])
        : "r"(a.x), "r"(a.y), "r"(a.z), "r"(a.w), "r"(b.x), "r"(b.y));
}
__device__ __forceinline__ void gridbar(int ph) {
    __syncthreads();
    if (threadIdx.x == 0) {
        __threadfence();
        unsigned t = atomicAdd(&g_barctr[ph], 1u) + 1;
        if (t < TAILB) {
            while (((volatile unsigned*)g_barctr)[ph] < TAILB) { }
        }
        __threadfence();
    }
    __syncthreads();
}

// ---------------- reset ----------------
__global__ void k_reset() {
    int t = threadIdx.x;
    for (int i = t; i < 2 * NN; i += 1024)
        ((int*)g_indeg)[i] = 0;
    if (t < 16 * 32) g_hist[t] = 0u;
    if (t < 32) {
        g_meanraw[0][t] = 0.f; g_meanraw[1][t] = 0.f;
        g_pool[0][t] = 0.f;    g_pool[1][t] = 0.f;
    }
    if (t < 16) { g_sAcc[0][t] = 0.f; g_sAcc[1][t] = 0.f; }
    if (t < 8) g_barctr[t] = 0u;
    if (t == 0) { g_keymin = 0xFFFFFFFFu; g_keymax = 0u; }
}

// ---------------- CSR build (2 edges / thread) ----------------
__global__ void k_indeg(const int* __restrict__ ei1, const int* __restrict__ ei2) {
    int t = blockIdx.x * 256 + threadIdx.x;
    if (t >= EE) return;                       // EE pairs total (EE/2 per graph)
    int g = t >= (EE / 2);
    const int* ei = g ? ei2 : ei1;
    int e2 = (t - g * (EE / 2)) * 2;
    int2 d = *(const int2*)&ei[EE + e2];
    atomicAdd(&g_indeg[g][d.x], 1);
    atomicAdd(&g_indeg[g][d.y], 1);
}

__global__ void k_scan() {   // grid=2, block=1024
    int g = blockIdx.x, t = threadIdx.x;
    int lane = t & 31, w = t >> 5;
    __shared__ int warpsum[32];
    __shared__ int s_carry;
    if (t == 0) s_carry = 0;
    __syncthreads();
    for (int base = 0; base < NN; base += 1024) {
        int i = base + t;
        int v = (i < NN) ? g_indeg[g][i] : 0;
        int x = v;
#pragma unroll
        for (int o = 1; o < 32; o <<= 1) {
            int y = __shfl_up_sync(0xffffffffu, x, o);
            if (lane >= o) x += y;
        }
        if (lane == 31) warpsum[w] = x;
        __syncthreads();
        if (w == 0) {
            int ws = warpsum[lane];
#pragma unroll
            for (int o = 1; o < 32; o <<= 1) {
                int y = __shfl_up_sync(0xffffffffu, ws, o);
                if (lane >= o) ws += y;
            }
            warpsum[lane] = ws;
        }
        __syncthreads();
        int carry = s_carry;
        int excl = carry + (x - v) + (w ? warpsum[w - 1] : 0);
        if (i < NN) {
            g_rowstart[g][i] = excl;
            g_cursor[g][i] = excl;
            g_dinv[g][i] = rsqrtf((float)v + 1.0f);
        }
        int total = warpsum[31];
        __syncthreads();
        if (t == 0) s_carry = carry + total;
        __syncthreads();
    }
    if (t == 0) g_rowstart[g][NN] = s_carry;
}

__global__ void k_fill(const int* __restrict__ ei1, const int* __restrict__ ei2) {
    int t = blockIdx.x * 256 + threadIdx.x;
    if (t >= EE) return;
    int g = t >= (EE / 2);
    const int* ei = g ? ei2 : ei1;
    int e2 = (t - g * (EE / 2)) * 2;
    int2 s = *(const int2*)&ei[e2];
    int2 d = *(const int2*)&ei[EE + e2];
    float ds0 = g_dinv[g][s.x], ds1 = g_dinv[g][s.y];
    int p0 = atomicAdd(&g_cursor[g][d.x], 1);
    int p1 = atomicAdd(&g_cursor[g][d.y], 1);
    g_adjc[g][p0] = make_int2(s.x, __float_as_int(ds0 * g_dinv[g][d.x]));
    g_adjc[g][p1] = make_int2(s.y, __float_as_int(ds1 * g_dinv[g][d.y]));
}

// ---------------- tiled GEMM: H = relu?(X) @ W ----------------
template <int FOUT, int KTOT, int RELU>
__global__ void __launch_bounds__(256, 2)
k_tgemm(const float* __restrict__ X0, const float* __restrict__ X1,
        const float* __restrict__ W,
        float* __restrict__ H0, float* __restrict__ H1) {
    constexpr int CPT = FOUT / 32;
    __shared__ __align__(16) float As[32][132];
    __shared__ __align__(16) float Ws[32][FOUT];
    int z = blockIdx.z;
    const float* X = z ? X1 : X0;
    float* H = z ? H1 : H0;
    int tid = threadIdx.x;
    int i0 = blockIdx.x * 128;
    int tx = tid & 31, ty = tid >> 5;
    u64 acc2[8][CPT];
#pragma unroll
    for (int r = 0; r < 8; r++)
#pragma unroll
        for (int c = 0; c < CPT; c++) acc2[r][c] = 0ull;

    for (int k0 = 0; k0 < KTOT; k0 += 32) {
        for (int idx = tid; idx < 1024; idx += 256) {
            int r = idx >> 3, k4 = idx & 7;
            int row = i0 + r;
            float4 v = make_float4(0.f, 0.f, 0.f, 0.f);
            if (row < NN) v = *(const float4*)&X[(size_t)row * KTOT + k0 + k4 * 4];
            if (RELU) {
                v.x = fmaxf(v.x, 0.f); v.y = fmaxf(v.y, 0.f);
                v.z = fmaxf(v.z, 0.f); v.w = fmaxf(v.w, 0.f);
            }
            As[k4 * 4 + 0][r] = v.x; As[k4 * 4 + 1][r] = v.y;
            As[k4 * 4 + 2][r] = v.z; As[k4 * 4 + 3][r] = v.w;
        }
        for (int idx = tid; idx < 8 * FOUT; idx += 256) {
            int j4 = idx % (FOUT / 4), kk = idx / (FOUT / 4);
            float4 w = *(const float4*)&W[(size_t)(k0 + kk) * FOUT + j4 * 4];
            Ws[kk][j4 * 4 + 0] = w.x; Ws[kk][j4 * 4 + 1] = w.y;
            Ws[kk][j4 * 4 + 2] = w.z; Ws[kk][j4 * 4 + 3] = w.w;
        }
        __syncthreads();
#pragma unroll 4
        for (int k = 0; k < 32; k++) {
            u64 aa[8];
            {
                const ulonglong2* ap = (const ulonglong2*)&As[k][ty * 16];
                ulonglong2 t0 = ap[0], t1 = ap[1], t2 = ap[2], t3 = ap[3];
                aa[0] = t0.x; aa[1] = t0.y; aa[2] = t1.x; aa[3] = t1.y;
                aa[4] = t2.x; aa[5] = t2.y; aa[6] = t3.x; aa[7] = t3.y;
            }
            u64 bd[CPT];
            if (CPT == 4) {
                float4 b = *(const float4*)&Ws[k][tx * 4];
                bd[0] = dup2(b.x); bd[1] = dup2(b.y);
                bd[2] = dup2(b.z); bd[3] = dup2(b.w);
            } else if (CPT == 2) {
                float2 b = *(const float2*)&Ws[k][tx * 2];
                bd[0] = dup2(b.x); bd[1] = dup2(b.y);
            } else {
                bd[0] = dup2(Ws[k][tx]);
            }
#pragma unroll
            for (int r = 0; r < 8; r++)
#pragma unroll
                for (int c = 0; c < CPT; c++) ffma2(acc2[r][c], aa[r], bd[c]);
        }
        __syncthreads();
    }
#pragma unroll
    for (int rp = 0; rp < 8; rp++) {
        int r0 = i0 + ty * 16 + 2 * rp;
        float lo[CPT], hi[CPT];
#pragma unroll
        for (int c = 0; c < CPT; c++) unpk(acc2[rp][c], lo[c], hi[c]);
        if (r0 < NN) {
            float* p = H + (size_t)r0 * FOUT + tx * CPT;
            if (CPT == 4) *(float4*)p = make_float4(lo[0], lo[1], lo[2], lo[3]);
            else if (CPT == 2) *(float2*)p = make_float2(lo[0], lo[1]);
            else *p = lo[0];
        }
        if (r0 + 1 < NN) {
            float* p = H + (size_t)(r0 + 1) * FOUT + tx * CPT;
            if (CPT == 4) *(float4*)p = make_float4(hi[0], hi[1], hi[2], hi[3]);
            else if (CPT == 2) *(float2*)p = make_float2(hi[0], hi[1]);
            else *p = hi[0];
        }
    }
}

// ---------------- gather ----------------
__global__ void k_gather(const float* __restrict__ H0, const float* __restrict__ H1,
                         const float* __restrict__ b,
                         float* __restrict__ O0, float* __restrict__ O1, int Fout) {
    int z = blockIdx.z;
    const float* H = z ? H1 : H0;
    float* O = z ? O1 : O0;
    int gpf = Fout >> 2;
    int idx = blockIdx.x * 256 + threadIdx.x;
    int node = idx / gpf;
    int c = idx - node * gpf;
    if (node >= NN) return;
    int rs = g_rowstart[z][node], re = g_rowstart[z][node + 1];
    float invdeg = 1.0f / ((float)(re - rs) + 1.0f);
    float4 hs = ((const float4*)(H + (size_t)node * Fout))[c];
    float4 bb = ((const float4*)b)[c];
    float4 acc;
    acc.x = hs.x * invdeg + bb.x; acc.y = hs.y * invdeg + bb.y;
    acc.z = hs.z * invdeg + bb.z; acc.w = hs.w * invdeg + bb.w;
    const int2* __restrict__ adjc = g_adjc[z];
#pragma unroll 4
    for (int e = rs; e < re; e++) {
        int2 sc = __ldg(&adjc[e]);
        float coef = __int_as_float(sc.y);
        float4 v = ((const float4*)(H + (size_t)sc.x * Fout))[c];
        acc.x += coef * v.x; acc.y += coef * v.y;
        acc.z += coef * v.z; acc.w += coef * v.w;
    }
    ((float4*)(O + (size_t)node * Fout))[c] = acc;
}

// ---------------- fragment builder ----------------
__device__ __forceinline__ float afld(const float* af, int n, int k) {
    return (n < NN) ? af[n * 32 + k] : 0.f;
}
__global__ void k_frag() {
    int wg = (blockIdx.x * 256 + threadIdx.x) >> 5;
    int lane = threadIdx.x & 31;
    if (wg < MT_TILES * 4) {
        int mt = wg >> 2, ks = wg & 3;
        const float* af = g_af[0];
        int r0 = mt * 16 + (lane >> 2);
        int c0 = ks * 8 + (lane & 3);
        uint4 v;
        v.x = totf32(afld(af, r0,     c0));
        v.y = totf32(afld(af, r0 + 8, c0));
        v.z = totf32(afld(af, r0,     c0 + 4));
        v.w = totf32(afld(af, r0 + 8, c0 + 4));
        g_fA[(mt * 4 + ks) * 32 + lane] = v;
    } else if (wg < MT_TILES * 4 + NT_TILES * 4) {
        int w = wg - MT_TILES * 4;
        int nt = w >> 2, ks = w & 3;
        const float* af = g_af[1];
        int n = nt * 8 + (lane >> 2);
        int k = ks * 8 + (lane & 3);
        uint2 v;
        v.x = totf32(afld(af, n, k));
        v.y = totf32(afld(af, n, k + 4));
        g_fB[(nt * 4 + ks) * 32 + lane] = v;
    }
}

// ---------------- similarity passes via tf32 mma ----------------
__global__ void __launch_bounds__(256, 2)
k_simpass(int pass) {
    __shared__ __align__(16) uint2 shB[2048];   // 16 KB: B-frags for this bx
    __shared__ unsigned sh[16];
    int tid = threadIdx.x, lane = tid & 31, w = tid >> 5;
    int mt = blockIdx.y * 8 + w;
    int bx = blockIdx.x;
    // cooperative stage of contiguous B-frag region
    {
        const uint4* src = (const uint4*)(g_fB + bx * 2048);
        uint4* dst = (uint4*)shB;
#pragma unroll
        for (int i = 0; i < 4; i++) dst[tid + 256 * i] = src[tid + 256 * i];
    }
    if (pass && tid < 16) sh[tid] = 0u;
    __syncthreads();
    uint4 afr[4];
#pragma unroll
    for (int ks = 0; ks < 4; ks++) afr[ks] = g_fA[(mt * 4 + ks) * 32 + lane];
    float c[16][4];
#pragma unroll
    for (int j = 0; j < 16; j++)
#pragma unroll
        for (int r = 0; r < 4; r++) c[j][r] = 0.f;
#pragma unroll
    for (int ks = 0; ks < 4; ks++) {
#pragma unroll
        for (int j = 0; j < 16; j++)
            mma_tf32(c[j], afr[ks], shB[(j * 4 + ks) * 32 + lane]);
    }
    int r_lo = mt * 16 + (lane >> 2);
    int r_hi = r_lo + 8;
    int cb = bx * 128 + 2 * (lane & 3);
    bool full = (mt < 625) && (bx < 78);       // all 64 elements in-bounds
    if (pass == 0) {
        float lmin = 3.4e38f, lmax = -3.4e38f;
        if (full) {
#pragma unroll
            for (int j = 0; j < 16; j++)
#pragma unroll
                for (int r = 0; r < 4; r++) {
                    lmin = fminf(lmin, c[j][r]);
                    lmax = fmaxf(lmax, c[j][r]);
                }
        } else {
            bool vlo = r_lo < NN, vhi = r_hi < NN;
#pragma unroll
            for (int j = 0; j < 16; j++) {
                int c0 = cb + j * 8;
                bool v0 = c0 < NN, v1 = c0 + 1 < NN;
                if (vlo && v0) { lmin = fminf(lmin, c[j][0]); lmax = fmaxf(lmax, c[j][0]); }
                if (vlo && v1) { lmin = fminf(lmin, c[j][1]); lmax = fmaxf(lmax, c[j][1]); }
                if (vhi && v0) { lmin = fminf(lmin, c[j][2]); lmax = fmaxf(lmax, c[j][2]); }
                if (vhi && v1) { lmin = fminf(lmin, c[j][3]); lmax = fmaxf(lmax, c[j][3]); }
            }
        }
        for (int o = 16; o; o >>= 1) {
            lmin = fminf(lmin, __shfl_down_sync(0xffffffffu, lmin, o));
            lmax = fmaxf(lmax, __shfl_down_sync(0xffffffffu, lmax, o));
        }
        if (lane == 0) {
            atomicMin(&g_keymin, fkey(lmin));
            atomicMax(&g_keymax, fkey(lmax));
        }
    } else {
        float lo_r = fdec(g_keymin), hi_r = fdec(g_keymax);
        float s16 = 16.0f / ((hi_r - lo_r) + 1e-12f);
        float b16 = -lo_r * s16;
        u64 cl = 0ull, ch = 0ull;
        if (full) {
#pragma unroll
            for (int j = 0; j < 16; j++)
#pragma unroll
                for (int r = 0; r < 4; r++) {
                    int b = (int)fmaf(c[j][r], s16, b16);
                    b = min(max(b, 0), 15);
                    if (b < 8) cl += 1ull << (b * 8);
                    else       ch += 1ull << ((b - 8) * 8);
                }
        } else {
            bool vr[2] = {r_lo < NN, r_hi < NN};
#pragma unroll
            for (int j = 0; j < 16; j++) {
                int c0 = cb + j * 8;
                bool vc[2] = {c0 < NN, c0 + 1 < NN};
#pragma unroll
                for (int r = 0; r < 4; r++) {
                    if (!(vr[r >> 1] && vc[r & 1])) continue;
                    int b = (int)fmaf(c[j][r], s16, b16);
                    b = min(max(b, 0), 15);
                    if (b < 8) cl += 1ull << (b * 8);
                    else       ch += 1ull << ((b - 8) * 8);
                }
            }
        }
#pragma unroll
        for (int b = 0; b < 16; b++) {
            unsigned v = (unsigned)((b < 8 ? (cl >> (b * 8)) : (ch >> ((b - 8) * 8))) & 0xFFull);
            for (int o = 16; o; o >>= 1) v += __shfl_down_sync(0xffffffffu, v, o);
            if (lane == 0 && v) atomicAdd(&sh[b], v);
        }
        __syncthreads();
        if (tid < 16 && sh[tid]) atomicAdd(&g_hist[tid * 32], sh[tid]);
    }
}

// ---------------- fused tail ----------------
__global__ void __launch_bounds__(256, 4)
k_tail(const float* __restrict__ att_w,
       const float* __restrict__ tn_w, const float* __restrict__ tn_wb,
       const float* __restrict__ tn_bias,
       const float* __restrict__ fc1_w, const float* __restrict__ fc1_b,
       const float* __restrict__ fc2_w, const float* __restrict__ fc2_b,
       float* __restrict__ out) {
    int bid = blockIdx.x, tid = threadIdx.x;
    int z = bid >= (TAILB / 2);
    int lb = z ? bid - TAILB / 2 : bid;
    int lane = tid & 31;
    int wz = (lb * 256 + tid) >> 5;
    const int nwz = (TAILB / 2) * 256 / 32;
    const float* X = g_af[z];

    {
        float acc = 0.f;
        for (int n = wz; n < NN; n += nwz) acc += X[n * 32 + lane];
        atomicAdd(&g_meanraw[z][lane], acc);
    }
    gridbar(0);
    if (bid == 0 && tid < 64) {
        int g = tid >> 5, j = tid & 31;
        float acc = 0.f;
        const float invN = 1.0f / NN;
        for (int f = 0; f < 32; f++)
            acc += (g_meanraw[g][f] * invN) * att_w[f * 32 + j];
        g_gc[g][j] = tanhf(acc);
    }
    gridbar(1);
    {
        float gcv = g_gc[z][lane];
        float acc = 0.f;
        for (int n = wz; n < NN; n += nwz) {
            float x = X[n * 32 + lane];
            float p = x * gcv;
            for (int o = 16; o; o >>= 1) p += __shfl_xor_sync(0xffffffffu, p, o);
            float sig = 1.0f / (1.0f + expf(-p));
            acc += x * sig;
        }
        atomicAdd(&g_pool[z][lane], acc);
    }
    gridbar(2);
    if (bid == 0) {
        for (int t = tid; t < 1024; t += 256) {
            int slot = t >> 9, r = t & 511, f = r >> 4, k = r & 15;
            const float* e2 = g_pool[1 - slot];
            float acc = tn_wb[k * 64 + f];
            for (int gg = 0; gg < 32; gg++)
                acc += tn_w[f * 512 + gg * 16 + k] * e2[gg];
            g_A[slot][f * 16 + k] = acc;
        }
        if (tid < 32) {
            int sl = tid >> 4, kk = tid & 15;
            const float* e2b = g_pool[1 - sl];
            float cc = tn_bias[kk];
            for (int gg = 0; gg < 32; gg++)
                cc += tn_wb[kk * 64 + 32 + gg] * e2b[gg];
            g_c[sl][kk] = cc;
        }
        __syncthreads();
        if (tid < 16) {
            float a2 = g_c[0][tid];
            for (int f2 = 0; f2 < 32; f2++)
                a2 += g_pool[0][f2] * g_A[0][f2 * 16 + tid];
            g_s0[tid] = fmaxf(a2, 0.f);
        }
    }
    gridbar(3);
    {
        float acc = 0.f;
        for (int n = wz; n < NN; n += nwz) {
            float x = X[n * 32 + lane];
            float v = (lane < 16) ? g_c[z][lane] : 0.f;
#pragma unroll
            for (int f = 0; f < 32; f++) {
                float xf = __shfl_sync(0xffffffffu, x, f);
                if (lane < 16) v += xf * g_A[z][f * 16 + lane];
            }
            if (lane < 16) acc += fmaxf(v, 0.f);
        }
        if (lane < 16) atomicAdd(&g_sAcc[z][lane], acc);
    }
    gridbar(4);
    if (bid == 0 && tid == 0) {
        float sc[64];
        const float invN = 1.0f / NN;
        for (int k = 0; k < 16; k++) {
            sc[k]      = g_s0[k];
            sc[16 + k] = g_sAcc[0][k] * invN;
            sc[32 + k] = g_sAcc[1][k] * invN;
        }
        float hf[16], hsum = 0.f;
        for (int b = 0; b < 16; b++) {
            unsigned c = g_hist[b * 32];
            if (c > 16777216u) c = 16777216u;
            hf[b] = (float)c;
            hsum += hf[b];
        }
        for (int b = 0; b < 16; b++) sc[48 + b] = hf[b] / hsum;
        float o2 = fc2_b[0];
        for (int j = 0; j < 16; j++) {
            float a = fc1_b[j];
            for (int i = 0; i < 64; i++) a += sc[i] * fc1_w[i * 16 + j];
            a = fmaxf(a, 0.f);
            o2 += a * fc2_w[j];
        }
        out[0] = 1.0f / (1.0f + expf(-o2));
    }
}

// ---------------- host driver ----------------
extern "C" void kernel_launch(void* const* d_in, const int* in_sizes, int n_in,
                              void* d_out, int out_size) {
    const float* feat1 = (const float*)d_in[0];
    const float* feat2 = (const float*)d_in[1];
    const int* ei1 = (const int*)d_in[2];
    const int* ei2 = (const int*)d_in[3];
    const float* W1 = (const float*)d_in[4];
    const float* b1 = (const float*)d_in[5];
    const float* W2 = (const float*)d_in[6];
    const float* b2 = (const float*)d_in[7];
    const float* W3 = (const float*)d_in[8];
    const float* b3 = (const float*)d_in[9];
    const float* att_w = (const float*)d_in[10];
    const float* tn_w = (const float*)d_in[11];
    const float* tn_wb = (const float*)d_in[12];
    const float* tn_bias = (const float*)d_in[13];
    const float* fc1_w = (const float*)d_in[14];
    const float* fc1_b = (const float*)d_in[15];
    const float* fc2_w = (const float*)d_in[16];
    const float* fc2_b = (const float*)d_in[17];
    float* out = (float*)d_out;

    float *H0, *H1, *X0, *X1, *af0, *af1;
    cudaGetSymbolAddress((void**)&H0, g_H);   H1 = H0 + NN * 128;
    cudaGetSymbolAddress((void**)&X0, g_X);   X1 = X0 + NN * 128;
    cudaGetSymbolAddress((void**)&af0, g_af); af1 = af0 + NN * 32;

    dim3 ggrid((NN + 127) / 128, 1, 2);

    k_reset<<<1, 1024>>>();
    k_indeg<<<(EE + 255) / 256, 256>>>(ei1, ei2);
    k_scan<<<2, 1024>>>();
    k_tgemm<128, 128, 0><<<ggrid, 256>>>(feat1, feat2, W1, H0, H1);  // ncu slot
    k_fill<<<(EE + 255) / 256, 256>>>(ei1, ei2);
    {
        dim3 grid((NN * 32 + 255) / 256, 1, 2);
        k_gather<<<grid, 256>>>(H0, H1, b1, X0, X1, 128);
    }
    k_tgemm<64, 128, 1><<<ggrid, 256>>>(X0, X1, W2, H0, H1);
    {
        dim3 grid((NN * 16 + 255) / 256, 1, 2);
        k_gather<<<grid, 256>>>(H0, H1, b2, X0, X1, 64);
    }
    k_tgemm<32, 64, 1><<<ggrid, 256>>>(X0, X1, W3, H0, H1);
    {
        dim3 grid((NN * 8 + 255) / 256, 1, 2);
        k_gather<<<grid, 256>>>(H0, H1, b3, af0, af1, 32);
    }

    {
        int warps = MT_TILES * 4 + NT_TILES * 4;
        k_frag<<<(warps * 32 + 255) / 256, 256>>>();
    }

    dim3 hgrid((NN + 127) / 128, (NN + 127) / 128);
    k_simpass<<<hgrid, 256>>>(0);
    k_simpass<<<hgrid, 256>>>(1);

    k_tail<<<TAILB, 256>>>(att_w, tn_w, tn_wb, tn_bias,
                           fc1_w, fc1_b, fc2_w, fc2_b, out);
}

// round 8
// speedup vs baseline: 3.6231x; 1.0463x over previous
#include <cuda_runtime.h>
#include <math.h>

#define NN 10000
#define EE 320000
#define MT_TILES 632
#define NT_TILES 1264
#define TAILB 80
typedef unsigned long long u64;

// ---------------- device scratch ----------------
__device__ float g_H[2][NN * 128];
__device__ float g_X[2][NN * 128];
__device__ float g_af[2][NN * 32];
__device__ uint4 g_fA[MT_TILES * 4 * 32];
__device__ uint2 g_fB[NT_TILES * 4 * 32];
__device__ float g_dinv[2][NN];
__device__ int   g_indeg[2][NN];
__device__ int   g_rowstart[2][NN + 1];
__device__ int   g_lpos[2][EE];
__device__ int2  g_adjc[2][EE];
__device__ unsigned g_keymin, g_keymax;
__device__ unsigned g_hist[16 * 32];
__device__ unsigned g_barctr[8];
__device__ float g_meanraw[2][32];
__device__ float g_gc[2][32];
__device__ float g_pool[2][32];
__device__ float g_A[2][32 * 16];
__device__ float g_c[2][16];
__device__ float g_sAcc[2][16];
__device__ float g_s0[16];

// ---------------- helpers ----------------
__device__ __forceinline__ unsigned fkey(float f) {
    unsigned u = __float_as_uint(f);
    return (u & 0x80000000u) ? ~u : (u | 0x80000000u);
}
__device__ __forceinline__ float fdec(unsigned k) {
    return (k & 0x80000000u) ? __uint_as_float(k ^ 0x80000000u)
                             : __uint_as_float(~k);
}
__device__ __forceinline__ u64 dup2(float a) {
    u64 r;
    asm("mov.b64 %0, {%1, %1};" : "=l"(r) : "r"(__float_as_uint(a)));
    return r;
}
__device__ __forceinline__ void ffma2(u64& acc, u64 a, u64 b) {
    asm("fma.rn.f32x2 %0, %1, %2, %0;" : "+l"(acc) : "l"(a), "l"(b));
}
__device__ __forceinline__ void unpk(u64 v, float& lo, float& hi) {
    unsigned l, h;
    asm("mov.b64 {%0, %1}, %2;" : "=r"(l), "=r"(h) : "l"(v));
    lo = __uint_as_float(l); hi = __uint_as_float(h);
}
__device__ __forceinline__ unsigned totf32(float f) {
    unsigned r;
    asm("cvt.rna.tf32.f32 %0, %1;" : "=r"(r) : "f"(f));
    return r;
}
__device__ __forceinline__ void mma_tf32(float c[4], uint4 a, uint2 b) {
    asm("mma.sync.aligned.m16n8k8.row.col.f32.tf32.tf32.f32 "
        "{%0,%1,%2,%3}, {%4,%5,%6,%7}, {%8,%9}, {%0,%1,%2,%3};"
        : "+f"(c[0]), "+f"(c[1]), "+f"(c[2]), "+f"(c[3])
        : "r"(a.x), "r"(a.y), "r"(a.z), "r"(a.w), "r"(b.x), "r"(b.y));
}
__device__ __forceinline__ void gridbar(int ph) {
    __syncthreads();
    if (threadIdx.x == 0) {
        __threadfence();
        unsigned t = atomicAdd(&g_barctr[ph], 1u) + 1;
        if (t < TAILB) {
            while (((volatile unsigned*)g_barctr)[ph] < TAILB) { }
        }
        __threadfence();
    }
    __syncthreads();
}

// ---------------- reset ----------------
__global__ void k_reset() {
    int t = threadIdx.x;
    for (int i = t; i < 2 * NN; i += 1024)
        ((int*)g_indeg)[i] = 0;
    if (t < 16 * 32) g_hist[t] = 0u;
    if (t < 32) {
        g_meanraw[0][t] = 0.f; g_meanraw[1][t] = 0.f;
        g_pool[0][t] = 0.f;    g_pool[1][t] = 0.f;
    }
    if (t < 16) { g_sAcc[0][t] = 0.f; g_sAcc[1][t] = 0.f; }
    if (t < 8) g_barctr[t] = 0u;
    if (t == 0) { g_keymin = 0xFFFFFFFFu; g_keymax = 0u; }
}

// ---------------- CSR build (2 edges / thread; lpos captured in indeg) ----------------
__global__ void k_indeg(const int* __restrict__ ei1, const int* __restrict__ ei2) {
    int t = blockIdx.x * 256 + threadIdx.x;
    if (t >= EE) return;
    int g = t >= (EE / 2);
    const int* ei = g ? ei2 : ei1;
    int e2 = (t - g * (EE / 2)) * 2;
    int2 d = *(const int2*)&ei[EE + e2];
    int p0 = atomicAdd(&g_indeg[g][d.x], 1);
    int p1 = atomicAdd(&g_indeg[g][d.y], 1);
    g_lpos[g][e2] = p0;
    g_lpos[g][e2 + 1] = p1;
}

__global__ void k_scan() {   // grid=2, block=1024
    int g = blockIdx.x, t = threadIdx.x;
    int lane = t & 31, w = t >> 5;
    __shared__ int warpsum[32];
    __shared__ int s_carry;
    if (t == 0) s_carry = 0;
    __syncthreads();
    for (int base = 0; base < NN; base += 1024) {
        int i = base + t;
        int v = (i < NN) ? g_indeg[g][i] : 0;
        int x = v;
#pragma unroll
        for (int o = 1; o < 32; o <<= 1) {
            int y = __shfl_up_sync(0xffffffffu, x, o);
            if (lane >= o) x += y;
        }
        if (lane == 31) warpsum[w] = x;
        __syncthreads();
        if (w == 0) {
            int ws = warpsum[lane];
#pragma unroll
            for (int o = 1; o < 32; o <<= 1) {
                int y = __shfl_up_sync(0xffffffffu, ws, o);
                if (lane >= o) ws += y;
            }
            warpsum[lane] = ws;
        }
        __syncthreads();
        int carry = s_carry;
        int excl = carry + (x - v) + (w ? warpsum[w - 1] : 0);
        if (i < NN) {
            g_rowstart[g][i] = excl;
            g_dinv[g][i] = rsqrtf((float)v + 1.0f);
        }
        int total = warpsum[31];
        __syncthreads();
        if (t == 0) s_carry = carry + total;
        __syncthreads();
    }
    if (t == 0) g_rowstart[g][NN] = s_carry;
}

__global__ void k_fill(const int* __restrict__ ei1, const int* __restrict__ ei2) {
    int t = blockIdx.x * 256 + threadIdx.x;
    if (t >= EE) return;
    int g = t >= (EE / 2);
    const int* ei = g ? ei2 : ei1;
    int e2 = (t - g * (EE / 2)) * 2;
    int2 s = *(const int2*)&ei[e2];
    int2 d = *(const int2*)&ei[EE + e2];
    int lp0 = g_lpos[g][e2], lp1 = g_lpos[g][e2 + 1];
    float c0 = g_dinv[g][s.x] * g_dinv[g][d.x];
    float c1 = g_dinv[g][s.y] * g_dinv[g][d.y];
    g_adjc[g][g_rowstart[g][d.x] + lp0] = make_int2(s.x, __float_as_int(c0));
    g_adjc[g][g_rowstart[g][d.y] + lp1] = make_int2(s.y, __float_as_int(c1));
}

// ---------------- tiled GEMM: 64-row tiles for occupancy ----------------
template <int FOUT, int KTOT, int RELU>
__global__ void __launch_bounds__(256, 3)
k_tgemm(const float* __restrict__ X0, const float* __restrict__ X1,
        const float* __restrict__ W,
        float* __restrict__ H0, float* __restrict__ H1) {
    constexpr int CPT = FOUT / 32;
    __shared__ __align__(16) float As[32][68];
    __shared__ __align__(16) float Ws[32][FOUT];
    int z = blockIdx.z;
    const float* X = z ? X1 : X0;
    float* H = z ? H1 : H0;
    int tid = threadIdx.x;
    int i0 = blockIdx.x * 64;
    int tx = tid & 31, ty = tid >> 5;
    u64 acc2[4][CPT];
#pragma unroll
    for (int r = 0; r < 4; r++)
#pragma unroll
        for (int c = 0; c < CPT; c++) acc2[r][c] = 0ull;

    for (int k0 = 0; k0 < KTOT; k0 += 32) {
        for (int idx = tid; idx < 512; idx += 256) {
            int r = idx >> 3, k4 = idx & 7;
            int row = i0 + r;
            float4 v = make_float4(0.f, 0.f, 0.f, 0.f);
            if (row < NN) v = *(const float4*)&X[(size_t)row * KTOT + k0 + k4 * 4];
            if (RELU) {
                v.x = fmaxf(v.x, 0.f); v.y = fmaxf(v.y, 0.f);
                v.z = fmaxf(v.z, 0.f); v.w = fmaxf(v.w, 0.f);
            }
            As[k4 * 4 + 0][r] = v.x; As[k4 * 4 + 1][r] = v.y;
            As[k4 * 4 + 2][r] = v.z; As[k4 * 4 + 3][r] = v.w;
        }
        for (int idx = tid; idx < 8 * FOUT; idx += 256) {
            int j4 = idx % (FOUT / 4), kk = idx / (FOUT / 4);
            float4 w = *(const float4*)&W[(size_t)(k0 + kk) * FOUT + j4 * 4];
            Ws[kk][j4 * 4 + 0] = w.x; Ws[kk][j4 * 4 + 1] = w.y;
            Ws[kk][j4 * 4 + 2] = w.z; Ws[kk][j4 * 4 + 3] = w.w;
        }
        __syncthreads();
#pragma unroll 4
        for (int k = 0; k < 32; k++) {
            u64 aa[4];
            {
                const ulonglong2* ap = (const ulonglong2*)&As[k][ty * 8];
                ulonglong2 t0 = ap[0], t1 = ap[1];
                aa[0] = t0.x; aa[1] = t0.y; aa[2] = t1.x; aa[3] = t1.y;
            }
            u64 bd[CPT];
            if (CPT == 4) {
                float4 b = *(const float4*)&Ws[k][tx * 4];
                bd[0] = dup2(b.x); bd[1] = dup2(b.y);
                bd[2] = dup2(b.z); bd[3] = dup2(b.w);
            } else if (CPT == 2) {
                float2 b = *(const float2*)&Ws[k][tx * 2];
                bd[0] = dup2(b.x); bd[1] = dup2(b.y);
            } else {
                bd[0] = dup2(Ws[k][tx]);
            }
#pragma unroll
            for (int r = 0; r < 4; r++)
#pragma unroll
                for (int c = 0; c < CPT; c++) ffma2(acc2[r][c], aa[r], bd[c]);
        }
        __syncthreads();
    }
#pragma unroll
    for (int rp = 0; rp < 4; rp++) {
        int r0 = i0 + ty * 8 + 2 * rp;
        float lo[CPT], hi[CPT];
#pragma unroll
        for (int c = 0; c < CPT; c++) unpk(acc2[rp][c], lo[c], hi[c]);
        if (r0 < NN) {
            float* p = H + (size_t)r0 * FOUT + tx * CPT;
            if (CPT == 4) *(float4*)p = make_float4(lo[0], lo[1], lo[2], lo[3]);
            else if (CPT == 2) *(float2*)p = make_float2(lo[0], lo[1]);
            else *p = lo[0];
        }
        if (r0 + 1 < NN) {
            float* p = H + (size_t)(r0 + 1) * FOUT + tx * CPT;
            if (CPT == 4) *(float4*)p = make_float4(hi[0], hi[1], hi[2], hi[3]);
            else if (CPT == 2) *(float2*)p = make_float2(hi[0], hi[1]);
            else *p = hi[0];
        }
    }
}

// ---------------- gather ----------------
__global__ void k_gather(const float* __restrict__ H0, const float* __restrict__ H1,
                         const float* __restrict__ b,
                         float* __restrict__ O0, float* __restrict__ O1, int Fout) {
    int z = blockIdx.z;
    const float* H = z ? H1 : H0;
    float* O = z ? O1 : O0;
    int gpf = Fout >> 2;
    int idx = blockIdx.x * 256 + threadIdx.x;
    int node = idx / gpf;
    int c = idx - node * gpf;
    if (node >= NN) return;
    int rs = g_rowstart[z][node], re = g_rowstart[z][node + 1];
    float invdeg = 1.0f / ((float)(re - rs) + 1.0f);
    float4 hs = ((const float4*)(H + (size_t)node * Fout))[c];
    float4 bb = ((const float4*)b)[c];
    float4 acc;
    acc.x = hs.x * invdeg + bb.x; acc.y = hs.y * invdeg + bb.y;
    acc.z = hs.z * invdeg + bb.z; acc.w = hs.w * invdeg + bb.w;
    const int2* __restrict__ adjc = g_adjc[z];
#pragma unroll 4
    for (int e = rs; e < re; e++) {
        int2 sc = __ldg(&adjc[e]);
        float coef = __int_as_float(sc.y);
        float4 v = ((const float4*)(H + (size_t)sc.x * Fout))[c];
        acc.x += coef * v.x; acc.y += coef * v.y;
        acc.z += coef * v.z; acc.w += coef * v.w;
    }
    ((float4*)(O + (size_t)node * Fout))[c] = acc;
}

// ---------------- fragment builder ----------------
__device__ __forceinline__ float afld(const float* af, int n, int k) {
    return (n < NN) ? af[n * 32 + k] : 0.f;
}
__global__ void k_frag() {
    int wg = (blockIdx.x * 256 + threadIdx.x) >> 5;
    int lane = threadIdx.x & 31;
    if (wg < MT_TILES * 4) {
        int mt = wg >> 2, ks = wg & 3;
        const float* af = g_af[0];
        int r0 = mt * 16 + (lane >> 2);
        int c0 = ks * 8 + (lane & 3);
        uint4 v;
        v.x = totf32(afld(af, r0,     c0));
        v.y = totf32(afld(af, r0 + 8, c0));
        v.z = totf32(afld(af, r0,     c0 + 4));
        v.w = totf32(afld(af, r0 + 8, c0 + 4));
        g_fA[(mt * 4 + ks) * 32 + lane] = v;
    } else if (wg < MT_TILES * 4 + NT_TILES * 4) {
        int w = wg - MT_TILES * 4;
        int nt = w >> 2, ks = w & 3;
        const float* af = g_af[1];
        int n = nt * 8 + (lane >> 2);
        int k = ks * 8 + (lane & 3);
        uint2 v;
        v.x = totf32(afld(af, n, k));
        v.y = totf32(afld(af, n, k + 4));
        g_fB[(nt * 4 + ks) * 32 + lane] = v;
    }
}

// ---------------- similarity passes via tf32 mma ----------------
__global__ void __launch_bounds__(256, 2)
k_simpass(int pass) {
    __shared__ __align__(16) uint2 shB[2048];
    __shared__ unsigned sh[16];
    int tid = threadIdx.x, lane = tid & 31, w = tid >> 5;
    int mt = blockIdx.y * 8 + w;
    int bx = blockIdx.x;
    {
        const uint4* src = (const uint4*)(g_fB + bx * 2048);
        uint4* dst = (uint4*)shB;
#pragma unroll
        for (int i = 0; i < 4; i++) dst[tid + 256 * i] = src[tid + 256 * i];
    }
    if (pass && tid < 16) sh[tid] = 0u;
    __syncthreads();
    uint4 afr[4];
#pragma unroll
    for (int ks = 0; ks < 4; ks++) afr[ks] = g_fA[(mt * 4 + ks) * 32 + lane];
    float c[16][4];
#pragma unroll
    for (int j = 0; j < 16; j++)
#pragma unroll
        for (int r = 0; r < 4; r++) c[j][r] = 0.f;
#pragma unroll
    for (int ks = 0; ks < 4; ks++) {
#pragma unroll
        for (int j = 0; j < 16; j++)
            mma_tf32(c[j], afr[ks], shB[(j * 4 + ks) * 32 + lane]);
    }
    int r_lo = mt * 16 + (lane >> 2);
    int r_hi = r_lo + 8;
    int cb = bx * 128 + 2 * (lane & 3);
    bool full = (mt < 625) && (bx < 78);
    if (pass == 0) {
        float lmin = 3.4e38f, lmax = -3.4e38f;
        if (full) {
#pragma unroll
            for (int j = 0; j < 16; j++)
#pragma unroll
                for (int r = 0; r < 4; r++) {
                    lmin = fminf(lmin, c[j][r]);
                    lmax = fmaxf(lmax, c[j][r]);
                }
        } else {
            bool vlo = r_lo < NN, vhi = r_hi < NN;
#pragma unroll
            for (int j = 0; j < 16; j++) {
                int c0 = cb + j * 8;
                bool v0 = c0 < NN, v1 = c0 + 1 < NN;
                if (vlo && v0) { lmin = fminf(lmin, c[j][0]); lmax = fmaxf(lmax, c[j][0]); }
                if (vlo && v1) { lmin = fminf(lmin, c[j][1]); lmax = fmaxf(lmax, c[j][1]); }
                if (vhi && v0) { lmin = fminf(lmin, c[j][2]); lmax = fmaxf(lmax, c[j][2]); }
                if (vhi && v1) { lmin = fminf(lmin, c[j][3]); lmax = fmaxf(lmax, c[j][3]); }
            }
        }
        for (int o = 16; o; o >>= 1) {
            lmin = fminf(lmin, __shfl_down_sync(0xffffffffu, lmin, o));
            lmax = fmaxf(lmax, __shfl_down_sync(0xffffffffu, lmax, o));
        }
        if (lane == 0) {
            atomicMin(&g_keymin, fkey(lmin));
            atomicMax(&g_keymax, fkey(lmax));
        }
    } else {
        float lo_r = fdec(g_keymin), hi_r = fdec(g_keymax);
        float s16 = 16.0f / ((hi_r - lo_r) + 1e-12f);
        float b16 = -lo_r * s16;
        u64 cl = 0ull, ch = 0ull;
        if (full) {
#pragma unroll
            for (int j = 0; j < 16; j++)
#pragma unroll
                for (int r = 0; r < 4; r++) {
                    int b = (int)fmaf(c[j][r], s16, b16);
                    b = min(max(b, 0), 15);
                    if (b < 8) cl += 1ull << (b * 8);
                    else       ch += 1ull << ((b - 8) * 8);
                }
        } else {
            bool vr[2] = {r_lo < NN, r_hi < NN};
#pragma unroll
            for (int j = 0; j < 16; j++) {
                int c0 = cb + j * 8;
                bool vc[2] = {c0 < NN, c0 + 1 < NN};
#pragma unroll
                for (int r = 0; r < 4; r++) {
                    if (!(vr[r >> 1] && vc[r & 1])) continue;
                    int b = (int)fmaf(c[j][r], s16, b16);
                    b = min(max(b, 0), 15);
                    if (b < 8) cl += 1ull << (b * 8);
                    else       ch += 1ull << ((b - 8) * 8);
                }
            }
        }
#pragma unroll
        for (int b = 0; b < 16; b++) {
            unsigned v = (unsigned)((b < 8 ? (cl >> (b * 8)) : (ch >> ((b - 8) * 8))) & 0xFFull);
            for (int o = 16; o; o >>= 1) v += __shfl_down_sync(0xffffffffu, v, o);
            if (lane == 0 && v) atomicAdd(&sh[b], v);
        }
        __syncthreads();
        if (tid < 16 && sh[tid]) atomicAdd(&g_hist[tid * 32], sh[tid]);
    }
}

// ---------------- fused tail ----------------
__global__ void __launch_bounds__(256, 4)
k_tail(const float* __restrict__ att_w,
       const float* __restrict__ tn_w, const float* __restrict__ tn_wb,
       const float* __restrict__ tn_bias,
       const float* __restrict__ fc1_w, const float* __restrict__ fc1_b,
       const float* __restrict__ fc2_w, const float* __restrict__ fc2_b,
       float* __restrict__ out) {
    int bid = blockIdx.x, tid = threadIdx.x;
    int z = bid >= (TAILB / 2);
    int lb = z ? bid - TAILB / 2 : bid;
    int lane = tid & 31;
    int wz = (lb * 256 + tid) >> 5;
    const int nwz = (TAILB / 2) * 256 / 32;
    const float* X = g_af[z];

    {
        float acc = 0.f;
        for (int n = wz; n < NN; n += nwz) acc += X[n * 32 + lane];
        atomicAdd(&g_meanraw[z][lane], acc);
    }
    gridbar(0);
    if (bid == 0 && tid < 64) {
        int g = tid >> 5, j = tid & 31;
        float acc = 0.f;
        const float invN = 1.0f / NN;
        for (int f = 0; f < 32; f++)
            acc += (g_meanraw[g][f] * invN) * att_w[f * 32 + j];
        g_gc[g][j] = tanhf(acc);
    }
    gridbar(1);
    {
        float gcv = g_gc[z][lane];
        float acc = 0.f;
        for (int n = wz; n < NN; n += nwz) {
            float x = X[n * 32 + lane];
            float p = x * gcv;
            for (int o = 16; o; o >>= 1) p += __shfl_xor_sync(0xffffffffu, p, o);
            float sig = 1.0f / (1.0f + expf(-p));
            acc += x * sig;
        }
        atomicAdd(&g_pool[z][lane], acc);
    }
    gridbar(2);
    if (bid == 0) {
        for (int t = tid; t < 1024; t += 256) {
            int slot = t >> 9, r = t & 511, f = r >> 4, k = r & 15;
            const float* e2 = g_pool[1 - slot];
            float acc = tn_wb[k * 64 + f];
            for (int gg = 0; gg < 32; gg++)
                acc += tn_w[f * 512 + gg * 16 + k] * e2[gg];
            g_A[slot][f * 16 + k] = acc;
        }
        if (tid < 32) {
            int sl = tid >> 4, kk = tid & 15;
            const float* e2b = g_pool[1 - sl];
            float cc = tn_bias[kk];
            for (int gg = 0; gg < 32; gg++)
                cc += tn_wb[kk * 64 + 32 + gg] * e2b[gg];
            g_c[sl][kk] = cc;
        }
        __syncthreads();
        if (tid < 16) {
            float a2 = g_c[0][tid];
            for (int f2 = 0; f2 < 32; f2++)
                a2 += g_pool[0][f2] * g_A[0][f2 * 16 + tid];
            g_s0[tid] = fmaxf(a2, 0.f);
        }
    }
    gridbar(3);
    {
        float acc = 0.f;
        for (int n = wz; n < NN; n += nwz) {
            float x = X[n * 32 + lane];
            float v = (lane < 16) ? g_c[z][lane] : 0.f;
#pragma unroll
            for (int f = 0; f < 32; f++) {
                float xf = __shfl_sync(0xffffffffu, x, f);
                if (lane < 16) v += xf * g_A[z][f * 16 + lane];
            }
            if (lane < 16) acc += fmaxf(v, 0.f);
        }
        if (lane < 16) atomicAdd(&g_sAcc[z][lane], acc);
    }
    gridbar(4);
    if (bid == 0 && tid == 0) {
        float sc[64];
        const float invN = 1.0f / NN;
        for (int k = 0; k < 16; k++) {
            sc[k]      = g_s0[k];
            sc[16 + k] = g_sAcc[0][k] * invN;
            sc[32 + k] = g_sAcc[1][k] * invN;
        }
        float hf[16], hsum = 0.f;
        for (int b = 0; b < 16; b++) {
            unsigned c = g_hist[b * 32];
            if (c > 16777216u) c = 16777216u;
            hf[b] = (float)c;
            hsum += hf[b];
        }
        for (int b = 0; b < 16; b++) sc[48 + b] = hf[b] / hsum;
        float o2 = fc2_b[0];
        for (int j = 0; j < 16; j++) {
            float a = fc1_b[j];
            for (int i = 0; i < 64; i++) a += sc[i] * fc1_w[i * 16 + j];
            a = fmaxf(a, 0.f);
            o2 += a * fc2_w[j];
        }
        out[0] = 1.0f / (1.0f + expf(-o2));
    }
}

// ---------------- host driver ----------------
extern "C" void kernel_launch(void* const* d_in, const int* in_sizes, int n_in,
                              void* d_out, int out_size) {
    const float* feat1 = (const float*)d_in[0];
    const float* feat2 = (const float*)d_in[1];
    const int* ei1 = (const int*)d_in[2];
    const int* ei2 = (const int*)d_in[3];
    const float* W1 = (const float*)d_in[4];
    const float* b1 = (const float*)d_in[5];
    const float* W2 = (const float*)d_in[6];
    const float* b2 = (const float*)d_in[7];
    const float* W3 = (const float*)d_in[8];
    const float* b3 = (const float*)d_in[9];
    const float* att_w = (const float*)d_in[10];
    const float* tn_w = (const float*)d_in[11];
    const float* tn_wb = (const float*)d_in[12];
    const float* tn_bias = (const float*)d_in[13];
    const float* fc1_w = (const float*)d_in[14];
    const float* fc1_b = (const float*)d_in[15];
    const float* fc2_w = (const float*)d_in[16];
    const float* fc2_b = (const float*)d_in[17];
    float* out = (float*)d_out;

    float *H0, *H1, *X0, *X1, *af0, *af1;
    cudaGetSymbolAddress((void**)&H0, g_H);   H1 = H0 + NN * 128;
    cudaGetSymbolAddress((void**)&X0, g_X);   X1 = X0 + NN * 128;
    cudaGetSymbolAddress((void**)&af0, g_af); af1 = af0 + NN * 32;

    dim3 ggrid((NN + 63) / 64, 1, 2);

    k_reset<<<1, 1024>>>();
    k_indeg<<<(EE + 255) / 256, 256>>>(ei1, ei2);
    k_scan<<<2, 1024>>>();
    k_tgemm<128, 128, 0><<<ggrid, 256>>>(feat1, feat2, W1, H0, H1);  // ncu slot
    k_fill<<<(EE + 255) / 256, 256>>>(ei1, ei2);
    {
        dim3 grid((NN * 32 + 255) / 256, 1, 2);
        k_gather<<<grid, 256>>>(H0, H1, b1, X0, X1, 128);
    }
    k_tgemm<64, 128, 1><<<ggrid, 256>>>(X0, X1, W2, H0, H1);
    {
        dim3 grid((NN * 16 + 255) / 256, 1, 2);
        k_gather<<<grid, 256>>>(H0, H1, b2, X0, X1, 64);
    }
    k_tgemm<32, 64, 1><<<ggrid, 256>>>(X0, X1, W3, H0, H1);
    {
        dim3 grid((NN * 8 + 255) / 256, 1, 2);
        k_gather<<<grid, 256>>>(H0, H1, b3, af0, af1, 32);
    }

    {
        int warps = MT_TILES * 4 + NT_TILES * 4;
        k_frag<<<(warps * 32 + 255) / 256, 256>>>();
    }

    dim3 hgrid((NN + 127) / 128, (NN + 127) / 128);
    k_simpass<<<hgrid, 256>>>(0);
    k_simpass<<<hgrid, 256>>>(1);

    k_tail<<<TAILB, 256>>>(att_w, tn_w, tn_wb, tn_bias,
                           fc1_w, fc1_b, fc2_w, fc2_b, out);
}

// round 9
// speedup vs baseline: 3.7219x; 1.0273x over previous
#include <cuda_runtime.h>
#include <cuda_fp16.h>
#include <math.h>

#define NN 10000
#define EE 320000
#define MT_TILES 632
#define NT_TILES 1264
#define TAILB 80
typedef unsigned long long u64;

// ---------------- device scratch ----------------
__device__ __half g_Hh[2][NN * 128];      // gemm output (fp16, gather input)
__device__ float g_X[2][NN * 128];
__device__ float g_af[2][NN * 32];
__device__ uint4 g_fA[MT_TILES * 4 * 32];
__device__ uint2 g_fB[NT_TILES * 4 * 32];
__device__ float g_dinv[2][NN];
__device__ int   g_indeg[2][NN];
__device__ int   g_rowstart[2][NN + 1];
__device__ int   g_lpos[2][EE];
__device__ int2  g_adjc[2][EE];
__device__ unsigned g_keymin, g_keymax;
__device__ unsigned g_hist[16 * 32];
__device__ unsigned g_barctr[8];
__device__ float g_meanraw[2][32];
__device__ float g_gc[2][32];
__device__ float g_pool[2][32];
__device__ float g_A[2][32 * 16];
__device__ float g_c[2][16];
__device__ float g_sAcc[2][16];
__device__ float g_s0[16];

// ---------------- helpers ----------------
__device__ __forceinline__ unsigned fkey(float f) {
    unsigned u = __float_as_uint(f);
    return (u & 0x80000000u) ? ~u : (u | 0x80000000u);
}
__device__ __forceinline__ float fdec(unsigned k) {
    return (k & 0x80000000u) ? __uint_as_float(k ^ 0x80000000u)
                             : __uint_as_float(~k);
}
__device__ __forceinline__ u64 dup2(float a) {
    u64 r;
    asm("mov.b64 %0, {%1, %1};" : "=l"(r) : "r"(__float_as_uint(a)));
    return r;
}
__device__ __forceinline__ void ffma2(u64& acc, u64 a, u64 b) {
    asm("fma.rn.f32x2 %0, %1, %2, %0;" : "+l"(acc) : "l"(a), "l"(b));
}
__device__ __forceinline__ void unpk(u64 v, float& lo, float& hi) {
    unsigned l, h;
    asm("mov.b64 {%0, %1}, %2;" : "=r"(l), "=r"(h) : "l"(v));
    lo = __uint_as_float(l); hi = __uint_as_float(h);
}
__device__ __forceinline__ unsigned totf32(float f) {
    unsigned r;
    asm("cvt.rna.tf32.f32 %0, %1;" : "=r"(r) : "f"(f));
    return r;
}
__device__ __forceinline__ void mma_tf32(float c[4], uint4 a, uint2 b) {
    asm("mma.sync.aligned.m16n8k8.row.col.f32.tf32.tf32.f32 "
        "{%0,%1,%2,%3}, {%4,%5,%6,%7}, {%8,%9}, {%0,%1,%2,%3};"
        : "+f"(c[0]), "+f"(c[1]), "+f"(c[2]), "+f"(c[3])
        : "r"(a.x), "r"(a.y), "r"(a.z), "r"(a.w), "r"(b.x), "r"(b.y));
}
__device__ __forceinline__ void gridbar(int ph) {
    __syncthreads();
    if (threadIdx.x == 0) {
        __threadfence();
        unsigned t = atomicAdd(&g_barctr[ph], 1u) + 1;
        if (t < TAILB) {
            while (((volatile unsigned*)g_barctr)[ph] < TAILB) { }
        }
        __threadfence();
    }
    __syncthreads();
}

// ---------------- reset ----------------
__global__ void k_reset() {
    int t = threadIdx.x;
    for (int i = t; i < 2 * NN; i += 1024)
        ((int*)g_indeg)[i] = 0;
    if (t < 16 * 32) g_hist[t] = 0u;
    if (t < 32) {
        g_meanraw[0][t] = 0.f; g_meanraw[1][t] = 0.f;
        g_pool[0][t] = 0.f;    g_pool[1][t] = 0.f;
    }
    if (t < 16) { g_sAcc[0][t] = 0.f; g_sAcc[1][t] = 0.f; }
    if (t < 8) g_barctr[t] = 0u;
    if (t == 0) { g_keymin = 0xFFFFFFFFu; g_keymax = 0u; }
}

// ---------------- CSR build ----------------
__global__ void k_indeg(const int* __restrict__ ei1, const int* __restrict__ ei2) {
    int t = blockIdx.x * 256 + threadIdx.x;
    if (t >= EE) return;
    int g = t >= (EE / 2);
    const int* ei = g ? ei2 : ei1;
    int e2 = (t - g * (EE / 2)) * 2;
    int2 d = *(const int2*)&ei[EE + e2];
    int p0 = atomicAdd(&g_indeg[g][d.x], 1);
    int p1 = atomicAdd(&g_indeg[g][d.y], 1);
    g_lpos[g][e2] = p0;
    g_lpos[g][e2 + 1] = p1;
}

__global__ void k_scan() {   // grid=2, block=1024
    int g = blockIdx.x, t = threadIdx.x;
    int lane = t & 31, w = t >> 5;
    __shared__ int warpsum[32];
    __shared__ int s_carry;
    if (t == 0) s_carry = 0;
    __syncthreads();
    for (int base = 0; base < NN; base += 1024) {
        int i = base + t;
        int v = (i < NN) ? g_indeg[g][i] : 0;
        int x = v;
#pragma unroll
        for (int o = 1; o < 32; o <<= 1) {
            int y = __shfl_up_sync(0xffffffffu, x, o);
            if (lane >= o) x += y;
        }
        if (lane == 31) warpsum[w] = x;
        __syncthreads();
        if (w == 0) {
            int ws = warpsum[lane];
#pragma unroll
            for (int o = 1; o < 32; o <<= 1) {
                int y = __shfl_up_sync(0xffffffffu, ws, o);
                if (lane >= o) ws += y;
            }
            warpsum[lane] = ws;
        }
        __syncthreads();
        int carry = s_carry;
        int excl = carry + (x - v) + (w ? warpsum[w - 1] : 0);
        if (i < NN) {
            g_rowstart[g][i] = excl;
            g_dinv[g][i] = rsqrtf((float)v + 1.0f);
        }
        int total = warpsum[31];
        __syncthreads();
        if (t == 0) s_carry = carry + total;
        __syncthreads();
    }
    if (t == 0) g_rowstart[g][NN] = s_carry;
}

__global__ void k_fill(const int* __restrict__ ei1, const int* __restrict__ ei2) {
    int t = blockIdx.x * 256 + threadIdx.x;
    if (t >= EE) return;
    int g = t >= (EE / 2);
    const int* ei = g ? ei2 : ei1;
    int e2 = (t - g * (EE / 2)) * 2;
    int2 s = *(const int2*)&ei[e2];
    int2 d = *(const int2*)&ei[EE + e2];
    int lp0 = g_lpos[g][e2], lp1 = g_lpos[g][e2 + 1];
    float c0 = g_dinv[g][s.x] * g_dinv[g][d.x];
    float c1 = g_dinv[g][s.y] * g_dinv[g][d.y];
    g_adjc[g][g_rowstart[g][d.x] + lp0] = make_int2(s.x, __float_as_int(c0));
    g_adjc[g][g_rowstart[g][d.y] + lp1] = make_int2(s.y, __float_as_int(c1));
}

// ---------------- tiled GEMM: 64x64 tiles, fp16 output ----------------
template <int FOUT, int KTOT, int RELU>
__global__ void __launch_bounds__(256, 4)
k_tgemm(const float* __restrict__ X0, const float* __restrict__ X1,
        const float* __restrict__ W,
        __half* __restrict__ H0, __half* __restrict__ H1) {
    constexpr int COLS = (FOUT >= 64) ? 64 : FOUT;
    constexpr int CPT = COLS / 32;
    __shared__ __align__(16) float As[32][68];
    __shared__ __align__(16) float Ws[32][COLS];
    int z = blockIdx.z;
    const float* X = z ? X1 : X0;
    __half* H = z ? H1 : H0;
    int tid = threadIdx.x;
    int i0 = blockIdx.x * 64;
    int cb = blockIdx.y * COLS;
    int tx = tid & 31, ty = tid >> 5;
    u64 acc2[4][CPT];
#pragma unroll
    for (int r = 0; r < 4; r++)
#pragma unroll
        for (int c = 0; c < CPT; c++) acc2[r][c] = 0ull;

    for (int k0 = 0; k0 < KTOT; k0 += 32) {
        for (int idx = tid; idx < 512; idx += 256) {
            int r = idx >> 3, k4 = idx & 7;
            int row = i0 + r;
            float4 v = make_float4(0.f, 0.f, 0.f, 0.f);
            if (row < NN) v = *(const float4*)&X[(size_t)row * KTOT + k0 + k4 * 4];
            if (RELU) {
                v.x = fmaxf(v.x, 0.f); v.y = fmaxf(v.y, 0.f);
                v.z = fmaxf(v.z, 0.f); v.w = fmaxf(v.w, 0.f);
            }
            As[k4 * 4 + 0][r] = v.x; As[k4 * 4 + 1][r] = v.y;
            As[k4 * 4 + 2][r] = v.z; As[k4 * 4 + 3][r] = v.w;
        }
        for (int idx = tid; idx < 8 * COLS; idx += 256) {
            int j4 = idx % (COLS / 4), kk = idx / (COLS / 4);
            float4 w = *(const float4*)&W[(size_t)(k0 + kk) * FOUT + cb + j4 * 4];
            Ws[kk][j4 * 4 + 0] = w.x; Ws[kk][j4 * 4 + 1] = w.y;
            Ws[kk][j4 * 4 + 2] = w.z; Ws[kk][j4 * 4 + 3] = w.w;
        }
        __syncthreads();
#pragma unroll 4
        for (int k = 0; k < 32; k++) {
            u64 aa[4];
            {
                const ulonglong2* ap = (const ulonglong2*)&As[k][ty * 8];
                ulonglong2 t0 = ap[0], t1 = ap[1];
                aa[0] = t0.x; aa[1] = t0.y; aa[2] = t1.x; aa[3] = t1.y;
            }
            u64 bd[CPT];
            if (CPT == 2) {
                float2 b = *(const float2*)&Ws[k][tx * 2];
                bd[0] = dup2(b.x); bd[1] = dup2(b.y);
            } else {
                bd[0] = dup2(Ws[k][tx]);
            }
#pragma unroll
            for (int r = 0; r < 4; r++)
#pragma unroll
                for (int c = 0; c < CPT; c++) ffma2(acc2[r][c], aa[r], bd[c]);
        }
        __syncthreads();
    }
#pragma unroll
    for (int rp = 0; rp < 4; rp++) {
        int r0 = i0 + ty * 8 + 2 * rp;
        float lo[CPT], hi[CPT];
#pragma unroll
        for (int c = 0; c < CPT; c++) unpk(acc2[rp][c], lo[c], hi[c]);
        if (r0 < NN) {
            if (CPT == 2)
                *(__half2*)&H[(size_t)r0 * FOUT + cb + tx * 2] = __floats2half2_rn(lo[0], lo[1]);
            else
                H[(size_t)r0 * FOUT + cb + tx] = __float2half_rn(lo[0]);
        }
        if (r0 + 1 < NN) {
            if (CPT == 2)
                *(__half2*)&H[(size_t)(r0 + 1) * FOUT + cb + tx * 2] = __floats2half2_rn(hi[0], hi[1]);
            else
                H[(size_t)(r0 + 1) * FOUT + cb + tx] = __float2half_rn(hi[0]);
        }
    }
}

// ---------------- gather: O[d] = H[d]/deg + b + sum coef*H[s]  (H fp16) ----------------
__global__ void k_gather(const __half* __restrict__ H0, const __half* __restrict__ H1,
                         const float* __restrict__ b,
                         float* __restrict__ O0, float* __restrict__ O1, int Fout) {
    int z = blockIdx.z;
    const __half* H = z ? H1 : H0;
    float* O = z ? O1 : O0;
    int gpf = Fout >> 2;
    int idx = blockIdx.x * 256 + threadIdx.x;
    int node = idx / gpf;
    int c = idx - node * gpf;
    if (node >= NN) return;
    int rs = g_rowstart[z][node], re = g_rowstart[z][node + 1];
    float invdeg = 1.0f / ((float)(re - rs) + 1.0f);
    __half2 h01, h23;
    {
        uint2 raw = *(const uint2*)((const __half*)(H + (size_t)node * Fout) + c * 4);
        h01 = *(__half2*)&raw.x; h23 = *(__half2*)&raw.y;
    }
    float2 f01 = __half22float2(h01), f23 = __half22float2(h23);
    float4 bb = ((const float4*)b)[c];
    float4 acc;
    acc.x = f01.x * invdeg + bb.x; acc.y = f01.y * invdeg + bb.y;
    acc.z = f23.x * invdeg + bb.z; acc.w = f23.y * invdeg + bb.w;
    const int2* __restrict__ adjc = g_adjc[z];
#pragma unroll 4
    for (int e = rs; e < re; e++) {
        int2 sc = __ldg(&adjc[e]);
        float coef = __int_as_float(sc.y);
        uint2 raw = __ldg((const uint2*)(H + (size_t)sc.x * Fout) + c);
        float2 v01 = __half22float2(*(__half2*)&raw.x);
        float2 v23 = __half22float2(*(__half2*)&raw.y);
        acc.x += coef * v01.x; acc.y += coef * v01.y;
        acc.z += coef * v23.x; acc.w += coef * v23.y;
    }
    ((float4*)(O + (size_t)node * Fout))[c] = acc;
}

// ---------------- fragment builder ----------------
__device__ __forceinline__ float afld(const float* af, int n, int k) {
    return (n < NN) ? af[n * 32 + k] : 0.f;
}
__global__ void k_frag() {
    int wg = (blockIdx.x * 256 + threadIdx.x) >> 5;
    int lane = threadIdx.x & 31;
    if (wg < MT_TILES * 4) {
        int mt = wg >> 2, ks = wg & 3;
        const float* af = g_af[0];
        int r0 = mt * 16 + (lane >> 2);
        int c0 = ks * 8 + (lane & 3);
        uint4 v;
        v.x = totf32(afld(af, r0,     c0));
        v.y = totf32(afld(af, r0 + 8, c0));
        v.z = totf32(afld(af, r0,     c0 + 4));
        v.w = totf32(afld(af, r0 + 8, c0 + 4));
        g_fA[(mt * 4 + ks) * 32 + lane] = v;
    } else if (wg < MT_TILES * 4 + NT_TILES * 4) {
        int w = wg - MT_TILES * 4;
        int nt = w >> 2, ks = w & 3;
        const float* af = g_af[1];
        int n = nt * 8 + (lane >> 2);
        int k = ks * 8 + (lane & 3);
        uint2 v;
        v.x = totf32(afld(af, n, k));
        v.y = totf32(afld(af, n, k + 4));
        g_fB[(nt * 4 + ks) * 32 + lane] = v;
    }
}

// ---------------- similarity passes via tf32 mma ----------------
__global__ void __launch_bounds__(256, 2)
k_simpass(int pass) {
    __shared__ __align__(16) uint2 shB[2048];
    __shared__ unsigned sh[16];
    int tid = threadIdx.x, lane = tid & 31, w = tid >> 5;
    int mt = blockIdx.y * 8 + w;
    int bx = blockIdx.x;
    {
        const uint4* src = (const uint4*)(g_fB + bx * 2048);
        uint4* dst = (uint4*)shB;
#pragma unroll
        for (int i = 0; i < 4; i++) dst[tid + 256 * i] = src[tid + 256 * i];
    }
    if (pass && tid < 16) sh[tid] = 0u;
    __syncthreads();
    uint4 afr[4];
#pragma unroll
    for (int ks = 0; ks < 4; ks++) afr[ks] = g_fA[(mt * 4 + ks) * 32 + lane];
    float c[16][4];
#pragma unroll
    for (int j = 0; j < 16; j++)
#pragma unroll
        for (int r = 0; r < 4; r++) c[j][r] = 0.f;
#pragma unroll
    for (int ks = 0; ks < 4; ks++) {
#pragma unroll
        for (int j = 0; j < 16; j++)
            mma_tf32(c[j], afr[ks], shB[(j * 4 + ks) * 32 + lane]);
    }
    int r_lo = mt * 16 + (lane >> 2);
    int r_hi = r_lo + 8;
    int cb = bx * 128 + 2 * (lane & 3);
    bool full = (mt < 625) && (bx < 78);
    if (pass == 0) {
        float lmin = 3.4e38f, lmax = -3.4e38f;
        if (full) {
#pragma unroll
            for (int j = 0; j < 16; j++)
#pragma unroll
                for (int r = 0; r < 4; r++) {
                    lmin = fminf(lmin, c[j][r]);
                    lmax = fmaxf(lmax, c[j][r]);
                }
        } else {
            bool vlo = r_lo < NN, vhi = r_hi < NN;
#pragma unroll
            for (int j = 0; j < 16; j++) {
                int c0 = cb + j * 8;
                bool v0 = c0 < NN, v1 = c0 + 1 < NN;
                if (vlo && v0) { lmin = fminf(lmin, c[j][0]); lmax = fmaxf(lmax, c[j][0]); }
                if (vlo && v1) { lmin = fminf(lmin, c[j][1]); lmax = fmaxf(lmax, c[j][1]); }
                if (vhi && v0) { lmin = fminf(lmin, c[j][2]); lmax = fmaxf(lmax, c[j][2]); }
                if (vhi && v1) { lmin = fminf(lmin, c[j][3]); lmax = fmaxf(lmax, c[j][3]); }
            }
        }
        for (int o = 16; o; o >>= 1) {
            lmin = fminf(lmin, __shfl_down_sync(0xffffffffu, lmin, o));
            lmax = fmaxf(lmax, __shfl_down_sync(0xffffffffu, lmax, o));
        }
        if (lane == 0) {
            atomicMin(&g_keymin, fkey(lmin));
            atomicMax(&g_keymax, fkey(lmax));
        }
    } else {
        float lo_r = fdec(g_keymin), hi_r = fdec(g_keymax);
        float s16 = 16.0f / ((hi_r - lo_r) + 1e-12f);
        float b16 = -lo_r * s16;
        u64 cl = 0ull, ch = 0ull;
        if (full) {
#pragma unroll
            for (int j = 0; j < 16; j++)
#pragma unroll
                for (int r = 0; r < 4; r++) {
                    int b = (int)fmaf(c[j][r], s16, b16);
                    b = min(max(b, 0), 15);
                    if (b < 8) cl += 1ull << (b * 8);
                    else       ch += 1ull << ((b - 8) * 8);
                }
        } else {
            bool vr[2] = {r_lo < NN, r_hi < NN};
#pragma unroll
            for (int j = 0; j < 16; j++) {
                int c0 = cb + j * 8;
                bool vc[2] = {c0 < NN, c0 + 1 < NN};
#pragma unroll
                for (int r = 0; r < 4; r++) {
                    if (!(vr[r >> 1] && vc[r & 1])) continue;
                    int b = (int)fmaf(c[j][r], s16, b16);
                    b = min(max(b, 0), 15);
                    if (b < 8) cl += 1ull << (b * 8);
                    else       ch += 1ull << ((b - 8) * 8);
                }
            }
        }
#pragma unroll
        for (int b = 0; b < 16; b++) {
            unsigned v = (unsigned)((b < 8 ? (cl >> (b * 8)) : (ch >> ((b - 8) * 8))) & 0xFFull);
            for (int o = 16; o; o >>= 1) v += __shfl_down_sync(0xffffffffu, v, o);
            if (lane == 0 && v) atomicAdd(&sh[b], v);
        }
        __syncthreads();
        if (tid < 16 && sh[tid]) atomicAdd(&g_hist[tid * 32], sh[tid]);
    }
}

// ---------------- fused tail ----------------
__global__ void __launch_bounds__(256, 4)
k_tail(const float* __restrict__ att_w,
       const float* __restrict__ tn_w, const float* __restrict__ tn_wb,
       const float* __restrict__ tn_bias,
       const float* __restrict__ fc1_w, const float* __restrict__ fc1_b,
       const float* __restrict__ fc2_w, const float* __restrict__ fc2_b,
       float* __restrict__ out) {
    int bid = blockIdx.x, tid = threadIdx.x;
    int z = bid >= (TAILB / 2);
    int lb = z ? bid - TAILB / 2 : bid;
    int lane = tid & 31;
    int wz = (lb * 256 + tid) >> 5;
    const int nwz = (TAILB / 2) * 256 / 32;
    const float* X = g_af[z];

    {
        float acc = 0.f;
        for (int n = wz; n < NN; n += nwz) acc += X[n * 32 + lane];
        atomicAdd(&g_meanraw[z][lane], acc);
    }
    gridbar(0);
    if (bid == 0 && tid < 64) {
        int g = tid >> 5, j = tid & 31;
        float acc = 0.f;
        const float invN = 1.0f / NN;
        for (int f = 0; f < 32; f++)
            acc += (g_meanraw[g][f] * invN) * att_w[f * 32 + j];
        g_gc[g][j] = tanhf(acc);
    }
    gridbar(1);
    {
        float gcv = g_gc[z][lane];
        float acc = 0.f;
        for (int n = wz; n < NN; n += nwz) {
            float x = X[n * 32 + lane];
            float p = x * gcv;
            for (int o = 16; o; o >>= 1) p += __shfl_xor_sync(0xffffffffu, p, o);
            float sig = 1.0f / (1.0f + expf(-p));
            acc += x * sig;
        }
        atomicAdd(&g_pool[z][lane], acc);
    }
    gridbar(2);
    if (bid == 0) {
        for (int t = tid; t < 1024; t += 256) {
            int slot = t >> 9, r = t & 511, f = r >> 4, k = r & 15;
            const float* e2 = g_pool[1 - slot];
            float acc = tn_wb[k * 64 + f];
            for (int gg = 0; gg < 32; gg++)
                acc += tn_w[f * 512 + gg * 16 + k] * e2[gg];
            g_A[slot][f * 16 + k] = acc;
        }
        if (tid < 32) {
            int sl = tid >> 4, kk = tid & 15;
            const float* e2b = g_pool[1 - sl];
            float cc = tn_bias[kk];
            for (int gg = 0; gg < 32; gg++)
                cc += tn_wb[kk * 64 + 32 + gg] * e2b[gg];
            g_c[sl][kk] = cc;
        }
        __syncthreads();
        if (tid < 16) {
            float a2 = g_c[0][tid];
            for (int f2 = 0; f2 < 32; f2++)
                a2 += g_pool[0][f2] * g_A[0][f2 * 16 + tid];
            g_s0[tid] = fmaxf(a2, 0.f);
        }
    }
    gridbar(3);
    {
        float acc = 0.f;
        for (int n = wz; n < NN; n += nwz) {
            float x = X[n * 32 + lane];
            float v = (lane < 16) ? g_c[z][lane] : 0.f;
#pragma unroll
            for (int f = 0; f < 32; f++) {
                float xf = __shfl_sync(0xffffffffu, x, f);
                if (lane < 16) v += xf * g_A[z][f * 16 + lane];
            }
            if (lane < 16) acc += fmaxf(v, 0.f);
        }
        if (lane < 16) atomicAdd(&g_sAcc[z][lane], acc);
    }
    gridbar(4);
    if (bid == 0 && tid == 0) {
        float sc[64];
        const float invN = 1.0f / NN;
        for (int k = 0; k < 16; k++) {
            sc[k]      = g_s0[k];
            sc[16 + k] = g_sAcc[0][k] * invN;
            sc[32 + k] = g_sAcc[1][k] * invN;
        }
        float hf[16], hsum = 0.f;
        for (int b = 0; b < 16; b++) {
            unsigned c = g_hist[b * 32];
            if (c > 16777216u) c = 16777216u;
            hf[b] = (float)c;
            hsum += hf[b];
        }
        for (int b = 0; b < 16; b++) sc[48 + b] = hf[b] / hsum;
        float o2 = fc2_b[0];
        for (int j = 0; j < 16; j++) {
            float a = fc1_b[j];
            for (int i = 0; i < 64; i++) a += sc[i] * fc1_w[i * 16 + j];
            a = fmaxf(a, 0.f);
            o2 += a * fc2_w[j];
        }
        out[0] = 1.0f / (1.0f + expf(-o2));
    }
}

// ---------------- host driver ----------------
extern "C" void kernel_launch(void* const* d_in, const int* in_sizes, int n_in,
                              void* d_out, int out_size) {
    const float* feat1 = (const float*)d_in[0];
    const float* feat2 = (const float*)d_in[1];
    const int* ei1 = (const int*)d_in[2];
    const int* ei2 = (const int*)d_in[3];
    const float* W1 = (const float*)d_in[4];
    const float* b1 = (const float*)d_in[5];
    const float* W2 = (const float*)d_in[6];
    const float* b2 = (const float*)d_in[7];
    const float* W3 = (const float*)d_in[8];
    const float* b3 = (const float*)d_in[9];
    const float* att_w = (const float*)d_in[10];
    const float* tn_w = (const float*)d_in[11];
    const float* tn_wb = (const float*)d_in[12];
    const float* tn_bias = (const float*)d_in[13];
    const float* fc1_w = (const float*)d_in[14];
    const float* fc1_b = (const float*)d_in[15];
    const float* fc2_w = (const float*)d_in[16];
    const float* fc2_b = (const float*)d_in[17];
    float* out = (float*)d_out;

    __half *H0, *H1;
    float *X0, *X1, *af0, *af1;
    cudaGetSymbolAddress((void**)&H0, g_Hh);  H1 = H0 + NN * 128;
    cudaGetSymbolAddress((void**)&X0, g_X);   X1 = X0 + NN * 128;
    cudaGetSymbolAddress((void**)&af0, g_af); af1 = af0 + NN * 32;

    k_reset<<<1, 1024>>>();
    k_indeg<<<(EE + 255) / 256, 256>>>(ei1, ei2);
    k_scan<<<2, 1024>>>();
    {
        dim3 g1((NN + 63) / 64, 2, 2);
        k_tgemm<128, 128, 0><<<g1, 256>>>(feat1, feat2, W1, H0, H1);  // ncu slot
    }
    k_fill<<<(EE + 255) / 256, 256>>>(ei1, ei2);
    {
        dim3 grid((NN * 32 + 255) / 256, 1, 2);
        k_gather<<<grid, 256>>>(H0, H1, b1, X0, X1, 128);
    }
    {
        dim3 g2((NN + 63) / 64, 1, 2);
        k_tgemm<64, 128, 1><<<g2, 256>>>(X0, X1, W2, H0, H1);
    }
    {
        dim3 grid((NN * 16 + 255) / 256, 1, 2);
        k_gather<<<grid, 256>>>(H0, H1, b2, X0, X1, 64);
    }
    {
        dim3 g3((NN + 63) / 64, 1, 2);
        k_tgemm<32, 64, 1><<<g3, 256>>>(X0, X1, W3, H0, H1);
    }
    {
        dim3 grid((NN * 8 + 255) / 256, 1, 2);
        k_gather<<<grid, 256>>>(H0, H1, b3, af0, af1, 32);
    }

    {
        int warps = MT_TILES * 4 + NT_TILES * 4;
        k_frag<<<(warps * 32 + 255) / 256, 256>>>();
    }

    dim3 hgrid((NN + 127) / 128, (NN + 127) / 128);
    k_simpass<<<hgrid, 256>>>(0);
    k_simpass<<<hgrid, 256>>>(1);

    k_tail<<<TAILB, 256>>>(att_w, tn_w, tn_wb, tn_bias,
                           fc1_w, fc1_b, fc2_w, fc2_b, out);
}

// round 10
// speedup vs baseline: 4.0042x; 1.0758x over previous
#include <cuda_runtime.h>
#include <cuda_fp16.h>
#include <math.h>

#define NN 10000
#define EE 320000
#define MT_TILES 632
#define NT_TILES 1264
#define TAILB 80
typedef unsigned long long u64;

// ---------------- device scratch ----------------
__device__ __half g_Hh[2][NN * 128];
__device__ float g_X[2][NN * 128];
__device__ float g_af[2][NN * 32];
__device__ uint4 g_fA[MT_TILES * 2 * 32];   // fp16 A-frags, [mt][ks][lane]
__device__ uint2 g_fB[NT_TILES * 2 * 32];   // fp16 B-frags, [nt][ks][lane]
__device__ float g_dinv[2][NN];
__device__ int   g_indeg[2][NN];
__device__ int   g_rowstart[2][NN + 1];
__device__ int   g_lpos[2][EE];
__device__ int2  g_adjc[2][EE];
__device__ unsigned g_keymin, g_keymax;
__device__ unsigned g_hist[16 * 32];
__device__ unsigned g_barctr[8];
__device__ float g_meanraw[2][32];
__device__ float g_gc[2][32];
__device__ float g_pool[2][32];
__device__ float g_A[2][32 * 16];
__device__ float g_c[2][16];
__device__ float g_sAcc[2][16];
__device__ float g_s0[16];

// ---------------- helpers ----------------
__device__ __forceinline__ unsigned fkey(float f) {
    unsigned u = __float_as_uint(f);
    return (u & 0x80000000u) ? ~u : (u | 0x80000000u);
}
__device__ __forceinline__ float fdec(unsigned k) {
    return (k & 0x80000000u) ? __uint_as_float(k ^ 0x80000000u)
                             : __uint_as_float(~k);
}
__device__ __forceinline__ u64 dup2(float a) {
    u64 r;
    asm("mov.b64 %0, {%1, %1};" : "=l"(r) : "r"(__float_as_uint(a)));
    return r;
}
__device__ __forceinline__ void ffma2(u64& acc, u64 a, u64 b) {
    asm("fma.rn.f32x2 %0, %1, %2, %0;" : "+l"(acc) : "l"(a), "l"(b));
}
__device__ __forceinline__ void unpk(u64 v, float& lo, float& hi) {
    unsigned l, h;
    asm("mov.b64 {%0, %1}, %2;" : "=r"(l), "=r"(h) : "l"(v));
    lo = __uint_as_float(l); hi = __uint_as_float(h);
}
__device__ __forceinline__ unsigned h2pack(float a, float b) {
    __half2 h = __floats2half2_rn(a, b);
    return *(unsigned*)&h;
}
__device__ __forceinline__ void mma_f16(float c[4], uint4 a, uint2 b) {
    asm("mma.sync.aligned.m16n8k16.row.col.f32.f16.f16.f32 "
        "{%0,%1,%2,%3}, {%4,%5,%6,%7}, {%8,%9}, {%0,%1,%2,%3};"
        : "+f"(c[0]), "+f"(c[1]), "+f"(c[2]), "+f"(c[3])
        : "r"(a.x), "r"(a.y), "r"(a.z), "r"(a.w), "r"(b.x), "r"(b.y));
}
__device__ __forceinline__ void gridbar(int ph) {
    __syncthreads();
    if (threadIdx.x == 0) {
        __threadfence();
        unsigned t = atomicAdd(&g_barctr[ph], 1u) + 1;
        if (t < TAILB) {
            while (((volatile unsigned*)g_barctr)[ph] < TAILB) { }
        }
        __threadfence();
    }
    __syncthreads();
}

// ---------------- reset ----------------
__global__ void k_reset() {
    int t = threadIdx.x;
    for (int i = t; i < 2 * NN; i += 1024)
        ((int*)g_indeg)[i] = 0;
    if (t < 16 * 32) g_hist[t] = 0u;
    if (t < 32) {
        g_meanraw[0][t] = 0.f; g_meanraw[1][t] = 0.f;
        g_pool[0][t] = 0.f;    g_pool[1][t] = 0.f;
    }
    if (t < 16) { g_sAcc[0][t] = 0.f; g_sAcc[1][t] = 0.f; }
    if (t < 8) g_barctr[t] = 0u;
    if (t == 0) { g_keymin = 0xFFFFFFFFu; g_keymax = 0u; }
}

// ---------------- CSR build ----------------
__global__ void k_indeg(const int* __restrict__ ei1, const int* __restrict__ ei2) {
    int t = blockIdx.x * 256 + threadIdx.x;
    if (t >= EE) return;
    int g = t >= (EE / 2);
    const int* ei = g ? ei2 : ei1;
    int e2 = (t - g * (EE / 2)) * 2;
    int2 d = *(const int2*)&ei[EE + e2];
    int p0 = atomicAdd(&g_indeg[g][d.x], 1);
    int p1 = atomicAdd(&g_indeg[g][d.y], 1);
    g_lpos[g][e2] = p0;
    g_lpos[g][e2 + 1] = p1;
}

__global__ void k_scan() {   // grid=2, block=1024
    int g = blockIdx.x, t = threadIdx.x;
    int lane = t & 31, w = t >> 5;
    __shared__ int warpsum[32];
    __shared__ int s_carry;
    if (t == 0) s_carry = 0;
    __syncthreads();
    for (int base = 0; base < NN; base += 1024) {
        int i = base + t;
        int v = (i < NN) ? g_indeg[g][i] : 0;
        int x = v;
#pragma unroll
        for (int o = 1; o < 32; o <<= 1) {
            int y = __shfl_up_sync(0xffffffffu, x, o);
            if (lane >= o) x += y;
        }
        if (lane == 31) warpsum[w] = x;
        __syncthreads();
        if (w == 0) {
            int ws = warpsum[lane];
#pragma unroll
            for (int o = 1; o < 32; o <<= 1) {
                int y = __shfl_up_sync(0xffffffffu, ws, o);
                if (lane >= o) ws += y;
            }
            warpsum[lane] = ws;
        }
        __syncthreads();
        int carry = s_carry;
        int excl = carry + (x - v) + (w ? warpsum[w - 1] : 0);
        if (i < NN) {
            g_rowstart[g][i] = excl;
            g_dinv[g][i] = rsqrtf((float)v + 1.0f);
        }
        int total = warpsum[31];
        __syncthreads();
        if (t == 0) s_carry = carry + total;
        __syncthreads();
    }
    if (t == 0) g_rowstart[g][NN] = s_carry;
}

__global__ void k_fill(const int* __restrict__ ei1, const int* __restrict__ ei2) {
    int t = blockIdx.x * 256 + threadIdx.x;
    if (t >= EE) return;
    int g = t >= (EE / 2);
    const int* ei = g ? ei2 : ei1;
    int e2 = (t - g * (EE / 2)) * 2;
    int2 s = *(const int2*)&ei[e2];
    int2 d = *(const int2*)&ei[EE + e2];
    int lp0 = g_lpos[g][e2], lp1 = g_lpos[g][e2 + 1];
    float c0 = g_dinv[g][s.x] * g_dinv[g][d.x];
    float c1 = g_dinv[g][s.y] * g_dinv[g][d.y];
    g_adjc[g][g_rowstart[g][d.x] + lp0] = make_int2(s.x, __float_as_int(c0));
    g_adjc[g][g_rowstart[g][d.y] + lp1] = make_int2(s.y, __float_as_int(c1));
}

// ---------------- tiled GEMM: 64x64 tiles, fp16 output ----------------
template <int FOUT, int KTOT, int RELU>
__global__ void __launch_bounds__(256, 4)
k_tgemm(const float* __restrict__ X0, const float* __restrict__ X1,
        const float* __restrict__ W,
        __half* __restrict__ H0, __half* __restrict__ H1) {
    constexpr int COLS = (FOUT >= 64) ? 64 : FOUT;
    constexpr int CPT = COLS / 32;
    __shared__ __align__(16) float As[32][68];
    __shared__ __align__(16) float Ws[32][COLS];
    int z = blockIdx.z;
    const float* X = z ? X1 : X0;
    __half* H = z ? H1 : H0;
    int tid = threadIdx.x;
    int i0 = blockIdx.x * 64;
    int cb = blockIdx.y * COLS;
    int tx = tid & 31, ty = tid >> 5;
    u64 acc2[4][CPT];
#pragma unroll
    for (int r = 0; r < 4; r++)
#pragma unroll
        for (int c = 0; c < CPT; c++) acc2[r][c] = 0ull;

    for (int k0 = 0; k0 < KTOT; k0 += 32) {
        for (int idx = tid; idx < 512; idx += 256) {
            int r = idx >> 3, k4 = idx & 7;
            int row = i0 + r;
            float4 v = make_float4(0.f, 0.f, 0.f, 0.f);
            if (row < NN) v = *(const float4*)&X[(size_t)row * KTOT + k0 + k4 * 4];
            if (RELU) {
                v.x = fmaxf(v.x, 0.f); v.y = fmaxf(v.y, 0.f);
                v.z = fmaxf(v.z, 0.f); v.w = fmaxf(v.w, 0.f);
            }
            As[k4 * 4 + 0][r] = v.x; As[k4 * 4 + 1][r] = v.y;
            As[k4 * 4 + 2][r] = v.z; As[k4 * 4 + 3][r] = v.w;
        }
        for (int idx = tid; idx < 8 * COLS; idx += 256) {
            int j4 = idx % (COLS / 4), kk = idx / (COLS / 4);
            float4 w = *(const float4*)&W[(size_t)(k0 + kk) * FOUT + cb + j4 * 4];
            Ws[kk][j4 * 4 + 0] = w.x; Ws[kk][j4 * 4 + 1] = w.y;
            Ws[kk][j4 * 4 + 2] = w.z; Ws[kk][j4 * 4 + 3] = w.w;
        }
        __syncthreads();
#pragma unroll 4
        for (int k = 0; k < 32; k++) {
            u64 aa[4];
            {
                const ulonglong2* ap = (const ulonglong2*)&As[k][ty * 8];
                ulonglong2 t0 = ap[0], t1 = ap[1];
                aa[0] = t0.x; aa[1] = t0.y; aa[2] = t1.x; aa[3] = t1.y;
            }
            u64 bd[CPT];
            if (CPT == 2) {
                float2 b = *(const float2*)&Ws[k][tx * 2];
                bd[0] = dup2(b.x); bd[1] = dup2(b.y);
            } else {
                bd[0] = dup2(Ws[k][tx]);
            }
#pragma unroll
            for (int r = 0; r < 4; r++)
#pragma unroll
                for (int c = 0; c < CPT; c++) ffma2(acc2[r][c], aa[r], bd[c]);
        }
        __syncthreads();
    }
#pragma unroll
    for (int rp = 0; rp < 4; rp++) {
        int r0 = i0 + ty * 8 + 2 * rp;
        float lo[CPT], hi[CPT];
#pragma unroll
        for (int c = 0; c < CPT; c++) unpk(acc2[rp][c], lo[c], hi[c]);
        if (r0 < NN) {
            if (CPT == 2)
                *(__half2*)&H[(size_t)r0 * FOUT + cb + tx * 2] = __floats2half2_rn(lo[0], lo[1]);
            else
                H[(size_t)r0 * FOUT + cb + tx] = __float2half_rn(lo[0]);
        }
        if (r0 + 1 < NN) {
            if (CPT == 2)
                *(__half2*)&H[(size_t)(r0 + 1) * FOUT + cb + tx * 2] = __floats2half2_rn(hi[0], hi[1]);
            else
                H[(size_t)(r0 + 1) * FOUT + cb + tx] = __float2half_rn(hi[0]);
        }
    }
}

// ---------------- gather (H fp16) ----------------
__global__ void k_gather(const __half* __restrict__ H0, const __half* __restrict__ H1,
                         const float* __restrict__ b,
                         float* __restrict__ O0, float* __restrict__ O1, int Fout) {
    int z = blockIdx.z;
    const __half* H = z ? H1 : H0;
    float* O = z ? O1 : O0;
    int gpf = Fout >> 2;
    int idx = blockIdx.x * 256 + threadIdx.x;
    int node = idx / gpf;
    int c = idx - node * gpf;
    if (node >= NN) return;
    int rs = g_rowstart[z][node], re = g_rowstart[z][node + 1];
    float invdeg = 1.0f / ((float)(re - rs) + 1.0f);
    __half2 h01, h23;
    {
        uint2 raw = *(const uint2*)((const __half*)(H + (size_t)node * Fout) + c * 4);
        h01 = *(__half2*)&raw.x; h23 = *(__half2*)&raw.y;
    }
    float2 f01 = __half22float2(h01), f23 = __half22float2(h23);
    float4 bb = ((const float4*)b)[c];
    float4 acc;
    acc.x = f01.x * invdeg + bb.x; acc.y = f01.y * invdeg + bb.y;
    acc.z = f23.x * invdeg + bb.z; acc.w = f23.y * invdeg + bb.w;
    const int2* __restrict__ adjc = g_adjc[z];
#pragma unroll 4
    for (int e = rs; e < re; e++) {
        int2 sc = __ldg(&adjc[e]);
        float coef = __int_as_float(sc.y);
        uint2 raw = __ldg((const uint2*)(H + (size_t)sc.x * Fout) + c);
        float2 v01 = __half22float2(*(__half2*)&raw.x);
        float2 v23 = __half22float2(*(__half2*)&raw.y);
        acc.x += coef * v01.x; acc.y += coef * v01.y;
        acc.z += coef * v23.x; acc.w += coef * v23.y;
    }
    ((float4*)(O + (size_t)node * Fout))[c] = acc;
}

// ---------------- fp16 fragment builder (m16n8k16 layouts) ----------------
__device__ __forceinline__ float afld(const float* af, int n, int k) {
    return (n < NN) ? af[n * 32 + k] : 0.f;
}
__global__ void k_frag() {
    int wg = (blockIdx.x * 256 + threadIdx.x) >> 5;
    int lane = threadIdx.x & 31;
    if (wg < MT_TILES * 2) {
        int mt = wg >> 1, ks = wg & 1;
        const float* af = g_af[0];
        int r = mt * 16 + (lane >> 2);
        int kb = ks * 16 + (lane & 3) * 2;
        uint4 v;
        v.x = h2pack(afld(af, r,     kb),     afld(af, r,     kb + 1));
        v.y = h2pack(afld(af, r + 8, kb),     afld(af, r + 8, kb + 1));
        v.z = h2pack(afld(af, r,     kb + 8), afld(af, r,     kb + 9));
        v.w = h2pack(afld(af, r + 8, kb + 8), afld(af, r + 8, kb + 9));
        g_fA[(mt * 2 + ks) * 32 + lane] = v;
    } else if (wg < MT_TILES * 2 + NT_TILES * 2) {
        int w = wg - MT_TILES * 2;
        int nt = w >> 1, ks = w & 1;
        const float* af = g_af[1];
        int n = nt * 8 + (lane >> 2);
        int kb = ks * 16 + (lane & 3) * 2;
        uint2 v;
        v.x = h2pack(afld(af, n, kb),     afld(af, n, kb + 1));
        v.y = h2pack(afld(af, n, kb + 8), afld(af, n, kb + 9));
        g_fB[(nt * 2 + ks) * 32 + lane] = v;
    }
}

// ---------------- similarity passes via fp16 mma (m16n8k16) ----------------
__global__ void __launch_bounds__(256, 2)
k_simpass(int pass) {
    __shared__ __align__(16) uint2 shB[1024];   // 8 KB: B-frags for this bx
    __shared__ unsigned sh[16];
    int tid = threadIdx.x, lane = tid & 31, w = tid >> 5;
    int mt = blockIdx.y * 8 + w;
    int bx = blockIdx.x;
    {
        const uint4* src = (const uint4*)(g_fB + bx * 1024);
        uint4* dst = (uint4*)shB;
#pragma unroll
        for (int i = 0; i < 2; i++) dst[tid + 256 * i] = src[tid + 256 * i];
    }
    if (pass && tid < 16) sh[tid] = 0u;
    __syncthreads();
    uint4 afr[2];
#pragma unroll
    for (int ks = 0; ks < 2; ks++) afr[ks] = g_fA[(mt * 2 + ks) * 32 + lane];
    float c[16][4];
#pragma unroll
    for (int j = 0; j < 16; j++)
#pragma unroll
        for (int r = 0; r < 4; r++) c[j][r] = 0.f;
#pragma unroll
    for (int ks = 0; ks < 2; ks++) {
#pragma unroll
        for (int j = 0; j < 16; j++)
            mma_f16(c[j], afr[ks], shB[(j * 2 + ks) * 32 + lane]);
    }
    int r_lo = mt * 16 + (lane >> 2);
    int r_hi = r_lo + 8;
    int cb = bx * 128 + 2 * (lane & 3);
    bool full = (mt < 625) && (bx < 78);
    if (pass == 0) {
        float lmin = 3.4e38f, lmax = -3.4e38f;
        if (full) {
#pragma unroll
            for (int j = 0; j < 16; j++)
#pragma unroll
                for (int r = 0; r < 4; r++) {
                    lmin = fminf(lmin, c[j][r]);
                    lmax = fmaxf(lmax, c[j][r]);
                }
        } else {
            bool vlo = r_lo < NN, vhi = r_hi < NN;
#pragma unroll
            for (int j = 0; j < 16; j++) {
                int c0 = cb + j * 8;
                bool v0 = c0 < NN, v1 = c0 + 1 < NN;
                if (vlo && v0) { lmin = fminf(lmin, c[j][0]); lmax = fmaxf(lmax, c[j][0]); }
                if (vlo && v1) { lmin = fminf(lmin, c[j][1]); lmax = fmaxf(lmax, c[j][1]); }
                if (vhi && v0) { lmin = fminf(lmin, c[j][2]); lmax = fmaxf(lmax, c[j][2]); }
                if (vhi && v1) { lmin = fminf(lmin, c[j][3]); lmax = fmaxf(lmax, c[j][3]); }
            }
        }
        for (int o = 16; o; o >>= 1) {
            lmin = fminf(lmin, __shfl_down_sync(0xffffffffu, lmin, o));
            lmax = fmaxf(lmax, __shfl_down_sync(0xffffffffu, lmax, o));
        }
        if (lane == 0) {
            atomicMin(&g_keymin, fkey(lmin));
            atomicMax(&g_keymax, fkey(lmax));
        }
    } else {
        float lo_r = fdec(g_keymin), hi_r = fdec(g_keymax);
        float s16 = 16.0f / ((hi_r - lo_r) + 1e-12f);
        float b16 = -lo_r * s16;
        u64 cl = 0ull, ch = 0ull;
        if (full) {
#pragma unroll
            for (int j = 0; j < 16; j++)
#pragma unroll
                for (int r = 0; r < 4; r++) {
                    int b = (int)fmaf(c[j][r], s16, b16);
                    b = min(max(b, 0), 15);
                    if (b < 8) cl += 1ull << (b * 8);
                    else       ch += 1ull << ((b - 8) * 8);
                }
        } else {
            bool vr[2] = {r_lo < NN, r_hi < NN};
#pragma unroll
            for (int j = 0; j < 16; j++) {
                int c0 = cb + j * 8;
                bool vc[2] = {c0 < NN, c0 + 1 < NN};
#pragma unroll
                for (int r = 0; r < 4; r++) {
                    if (!(vr[r >> 1] && vc[r & 1])) continue;
                    int b = (int)fmaf(c[j][r], s16, b16);
                    b = min(max(b, 0), 15);
                    if (b < 8) cl += 1ull << (b * 8);
                    else       ch += 1ull << ((b - 8) * 8);
                }
            }
        }
#pragma unroll
        for (int b = 0; b < 16; b++) {
            unsigned v = (unsigned)((b < 8 ? (cl >> (b * 8)) : (ch >> ((b - 8) * 8))) & 0xFFull);
            for (int o = 16; o; o >>= 1) v += __shfl_down_sync(0xffffffffu, v, o);
            if (lane == 0 && v) atomicAdd(&sh[b], v);
        }
        __syncthreads();
        if (tid < 16 && sh[tid]) atomicAdd(&g_hist[tid * 32], sh[tid]);
    }
}

// ---------------- fused tail ----------------
__global__ void __launch_bounds__(256, 4)
k_tail(const float* __restrict__ att_w,
       const float* __restrict__ tn_w, const float* __restrict__ tn_wb,
       const float* __restrict__ tn_bias,
       const float* __restrict__ fc1_w, const float* __restrict__ fc1_b,
       const float* __restrict__ fc2_w, const float* __restrict__ fc2_b,
       float* __restrict__ out) {
    int bid = blockIdx.x, tid = threadIdx.x;
    int z = bid >= (TAILB / 2);
    int lb = z ? bid - TAILB / 2 : bid;
    int lane = tid & 31;
    int wz = (lb * 256 + tid) >> 5;
    const int nwz = (TAILB / 2) * 256 / 32;
    const float* X = g_af[z];

    {
        float acc = 0.f;
        for (int n = wz; n < NN; n += nwz) acc += X[n * 32 + lane];
        atomicAdd(&g_meanraw[z][lane], acc);
    }
    gridbar(0);
    if (bid == 0 && tid < 64) {
        int g = tid >> 5, j = tid & 31;
        float acc = 0.f;
        const float invN = 1.0f / NN;
        for (int f = 0; f < 32; f++)
            acc += (g_meanraw[g][f] * invN) * att_w[f * 32 + j];
        g_gc[g][j] = tanhf(acc);
    }
    gridbar(1);
    {
        float gcv = g_gc[z][lane];
        float acc = 0.f;
        for (int n = wz; n < NN; n += nwz) {
            float x = X[n * 32 + lane];
            float p = x * gcv;
            for (int o = 16; o; o >>= 1) p += __shfl_xor_sync(0xffffffffu, p, o);
            float sig = 1.0f / (1.0f + expf(-p));
            acc += x * sig;
        }
        atomicAdd(&g_pool[z][lane], acc);
    }
    gridbar(2);
    if (bid == 0) {
        for (int t = tid; t < 1024; t += 256) {
            int slot = t >> 9, r = t & 511, f = r >> 4, k = r & 15;
            const float* e2 = g_pool[1 - slot];
            float acc = tn_wb[k * 64 + f];
            for (int gg = 0; gg < 32; gg++)
                acc += tn_w[f * 512 + gg * 16 + k] * e2[gg];
            g_A[slot][f * 16 + k] = acc;
        }
        if (tid < 32) {
            int sl = tid >> 4, kk = tid & 15;
            const float* e2b = g_pool[1 - sl];
            float cc = tn_bias[kk];
            for (int gg = 0; gg < 32; gg++)
                cc += tn_wb[kk * 64 + 32 + gg] * e2b[gg];
            g_c[sl][kk] = cc;
        }
        __syncthreads();
        if (tid < 16) {
            float a2 = g_c[0][tid];
            for (int f2 = 0; f2 < 32; f2++)
                a2 += g_pool[0][f2] * g_A[0][f2 * 16 + tid];
            g_s0[tid] = fmaxf(a2, 0.f);
        }
    }
    gridbar(3);
    {
        float acc = 0.f;
        for (int n = wz; n < NN; n += nwz) {
            float x = X[n * 32 + lane];
            float v = (lane < 16) ? g_c[z][lane] : 0.f;
#pragma unroll
            for (int f = 0; f < 32; f++) {
                float xf = __shfl_sync(0xffffffffu, x, f);
                if (lane < 16) v += xf * g_A[z][f * 16 + lane];
            }
            if (lane < 16) acc += fmaxf(v, 0.f);
        }
        if (lane < 16) atomicAdd(&g_sAcc[z][lane], acc);
    }
    gridbar(4);
    if (bid == 0 && tid == 0) {
        float sc[64];
        const float invN = 1.0f / NN;
        for (int k = 0; k < 16; k++) {
            sc[k]      = g_s0[k];
            sc[16 + k] = g_sAcc[0][k] * invN;
            sc[32 + k] = g_sAcc[1][k] * invN;
        }
        float hf[16], hsum = 0.f;
        for (int b = 0; b < 16; b++) {
            unsigned c = g_hist[b * 32];
            if (c > 16777216u) c = 16777216u;
            hf[b] = (float)c;
            hsum += hf[b];
        }
        for (int b = 0; b < 16; b++) sc[48 + b] = hf[b] / hsum;
        float o2 = fc2_b[0];
        for (int j = 0; j < 16; j++) {
            float a = fc1_b[j];
            for (int i = 0; i < 64; i++) a += sc[i] * fc1_w[i * 16 + j];
            a = fmaxf(a, 0.f);
            o2 += a * fc2_w[j];
        }
        out[0] = 1.0f / (1.0f + expf(-o2));
    }
}

// ---------------- host driver ----------------
extern "C" void kernel_launch(void* const* d_in, const int* in_sizes, int n_in,
                              void* d_out, int out_size) {
    const float* feat1 = (const float*)d_in[0];
    const float* feat2 = (const float*)d_in[1];
    const int* ei1 = (const int*)d_in[2];
    const int* ei2 = (const int*)d_in[3];
    const float* W1 = (const float*)d_in[4];
    const float* b1 = (const float*)d_in[5];
    const float* W2 = (const float*)d_in[6];
    const float* b2 = (const float*)d_in[7];
    const float* W3 = (const float*)d_in[8];
    const float* b3 = (const float*)d_in[9];
    const float* att_w = (const float*)d_in[10];
    const float* tn_w = (const float*)d_in[11];
    const float* tn_wb = (const float*)d_in[12];
    const float* tn_bias = (const float*)d_in[13];
    const float* fc1_w = (const float*)d_in[14];
    const float* fc1_b = (const float*)d_in[15];
    const float* fc2_w = (const float*)d_in[16];
    const float* fc2_b = (const float*)d_in[17];
    float* out = (float*)d_out;

    __half *H0, *H1;
    float *X0, *X1, *af0, *af1;
    cudaGetSymbolAddress((void**)&H0, g_Hh);  H1 = H0 + NN * 128;
    cudaGetSymbolAddress((void**)&X0, g_X);   X1 = X0 + NN * 128;
    cudaGetSymbolAddress((void**)&af0, g_af); af1 = af0 + NN * 32;

    k_reset<<<1, 1024>>>();
    k_indeg<<<(EE + 255) / 256, 256>>>(ei1, ei2);
    k_scan<<<2, 1024>>>();
    {
        dim3 g1((NN + 63) / 64, 2, 2);
        k_tgemm<128, 128, 0><<<g1, 256>>>(feat1, feat2, W1, H0, H1);
    }
    k_fill<<<(EE + 255) / 256, 256>>>(ei1, ei2);
    {
        dim3 grid((NN * 32 + 255) / 256, 1, 2);
        k_gather<<<grid, 256>>>(H0, H1, b1, X0, X1, 128);
    }
    {
        dim3 g2((NN + 63) / 64, 1, 2);
        k_tgemm<64, 128, 1><<<g2, 256>>>(X0, X1, W2, H0, H1);
    }
    {
        dim3 grid((NN * 16 + 255) / 256, 1, 2);
        k_gather<<<grid, 256>>>(H0, H1, b2, X0, X1, 64);
    }
    {
        dim3 g3((NN + 63) / 64, 1, 2);
        k_tgemm<32, 64, 1><<<g3, 256>>>(X0, X1, W3, H0, H1);
    }
    {
        dim3 grid((NN * 8 + 255) / 256, 1, 2);
        k_gather<<<grid, 256>>>(H0, H1, b3, af0, af1, 32);
    }

    {
        int warps = MT_TILES * 2 + NT_TILES * 2;
        k_frag<<<(warps * 32 + 255) / 256, 256>>>();
    }

    dim3 hgrid((NN + 127) / 128, (NN + 127) / 128);
    k_simpass<<<hgrid, 256>>>(0);
    k_simpass<<<hgrid, 256>>>(1);

    k_tail<<<TAILB, 256>>>(att_w, tn_w, tn_wb, tn_bias,
                           fc1_w, fc1_b, fc2_w, fc2_b, out);
}

// round 11
// speedup vs baseline: 4.5126x; 1.1270x over previous
#include <cuda_runtime.h>
#include <cuda_fp16.h>
#include <math.h>

#define NN 10000
#define EE 320000
#define MT_TILES 632
#define NT_TILES 1264
#define TAILB 80
typedef unsigned long long u64;

// ---------------- device scratch ----------------
__device__ __half g_Hh[2][NN * 128];
__device__ __half g_Xh[2][NN * 128];       // fp16 activations (layers 2/3 input)
__device__ float g_af[2][NN * 32];
__device__ uint4 g_fA[MT_TILES * 2 * 32];
__device__ uint2 g_fB[NT_TILES * 2 * 32];
__device__ float g_dinv[2][NN];
__device__ int   g_indeg[2][NN];
__device__ int   g_rowstart[2][NN + 1];
__device__ int   g_lpos[2][EE];
__device__ int2  g_adjc[2][EE];
__device__ unsigned g_keymin, g_keymax;
__device__ unsigned g_hist[16 * 32];
__device__ unsigned g_barctr[8];
__device__ float g_meanraw[2][32];
__device__ float g_gc[2][32];
__device__ float g_pool[2][32];
__device__ float g_A[2][32 * 16];
__device__ float g_c[2][16];
__device__ float g_sAcc[2][16];
__device__ float g_s0[16];

// ---------------- helpers ----------------
__device__ __forceinline__ unsigned fkey(float f) {
    unsigned u = __float_as_uint(f);
    return (u & 0x80000000u) ? ~u : (u | 0x80000000u);
}
__device__ __forceinline__ float fdec(unsigned k) {
    return (k & 0x80000000u) ? __uint_as_float(k ^ 0x80000000u)
                             : __uint_as_float(~k);
}
__device__ __forceinline__ u64 dup2(float a) {
    u64 r;
    asm("mov.b64 %0, {%1, %1};" : "=l"(r) : "r"(__float_as_uint(a)));
    return r;
}
__device__ __forceinline__ void ffma2(u64& acc, u64 a, u64 b) {
    asm("fma.rn.f32x2 %0, %1, %2, %0;" : "+l"(acc) : "l"(a), "l"(b));
}
__device__ __forceinline__ void unpk(u64 v, float& lo, float& hi) {
    unsigned l, h;
    asm("mov.b64 {%0, %1}, %2;" : "=r"(l), "=r"(h) : "l"(v));
    lo = __uint_as_float(l); hi = __uint_as_float(h);
}
__device__ __forceinline__ unsigned h2pack(float a, float b) {
    __half2 h = __floats2half2_rn(a, b);
    return *(unsigned*)&h;
}
__device__ __forceinline__ void mma_f16(float c[4], uint4 a, uint2 b) {
    asm("mma.sync.aligned.m16n8k16.row.col.f32.f16.f16.f32 "
        "{%0,%1,%2,%3}, {%4,%5,%6,%7}, {%8,%9}, {%0,%1,%2,%3};"
        : "+f"(c[0]), "+f"(c[1]), "+f"(c[2]), "+f"(c[3])
        : "r"(a.x), "r"(a.y), "r"(a.z), "r"(a.w), "r"(b.x), "r"(b.y));
}
__device__ __forceinline__ void gridbar(int ph) {
    __syncthreads();
    if (threadIdx.x == 0) {
        __threadfence();
        unsigned t = atomicAdd(&g_barctr[ph], 1u) + 1;
        if (t < TAILB) {
            while (((volatile unsigned*)g_barctr)[ph] < TAILB) { }
        }
        __threadfence();
    }
    __syncthreads();
}

// ---------------- reset ----------------
__global__ void k_reset() {
    int t = threadIdx.x;
    for (int i = t; i < 2 * NN; i += 1024)
        ((int*)g_indeg)[i] = 0;
    if (t < 16 * 32) g_hist[t] = 0u;
    if (t < 32) {
        g_meanraw[0][t] = 0.f; g_meanraw[1][t] = 0.f;
        g_pool[0][t] = 0.f;    g_pool[1][t] = 0.f;
    }
    if (t < 16) { g_sAcc[0][t] = 0.f; g_sAcc[1][t] = 0.f; }
    if (t < 8) g_barctr[t] = 0u;
    if (t == 0) { g_keymin = 0xFFFFFFFFu; g_keymax = 0u; }
}

// ---------------- CSR build ----------------
__global__ void k_indeg(const int* __restrict__ ei1, const int* __restrict__ ei2) {
    int t = blockIdx.x * 256 + threadIdx.x;
    if (t >= EE) return;
    int g = t >= (EE / 2);
    const int* ei = g ? ei2 : ei1;
    int e2 = (t - g * (EE / 2)) * 2;
    int2 d = *(const int2*)&ei[EE + e2];
    int p0 = atomicAdd(&g_indeg[g][d.x], 1);
    int p1 = atomicAdd(&g_indeg[g][d.y], 1);
    g_lpos[g][e2] = p0;
    g_lpos[g][e2 + 1] = p1;
}

__global__ void k_scan() {   // grid=2, block=1024
    int g = blockIdx.x, t = threadIdx.x;
    int lane = t & 31, w = t >> 5;
    __shared__ int warpsum[32];
    __shared__ int s_carry;
    if (t == 0) s_carry = 0;
    __syncthreads();
    for (int base = 0; base < NN; base += 1024) {
        int i = base + t;
        int v = (i < NN) ? g_indeg[g][i] : 0;
        int x = v;
#pragma unroll
        for (int o = 1; o < 32; o <<= 1) {
            int y = __shfl_up_sync(0xffffffffu, x, o);
            if (lane >= o) x += y;
        }
        if (lane == 31) warpsum[w] = x;
        __syncthreads();
        if (w == 0) {
            int ws = warpsum[lane];
#pragma unroll
            for (int o = 1; o < 32; o <<= 1) {
                int y = __shfl_up_sync(0xffffffffu, ws, o);
                if (lane >= o) ws += y;
            }
            warpsum[lane] = ws;
        }
        __syncthreads();
        int carry = s_carry;
        int excl = carry + (x - v) + (w ? warpsum[w - 1] : 0);
        if (i < NN) {
            g_rowstart[g][i] = excl;
            g_dinv[g][i] = rsqrtf((float)v + 1.0f);
        }
        int total = warpsum[31];
        __syncthreads();
        if (t == 0) s_carry = carry + total;
        __syncthreads();
    }
    if (t == 0) g_rowstart[g][NN] = s_carry;
}

__global__ void k_fill(const int* __restrict__ ei1, const int* __restrict__ ei2) {
    int t = blockIdx.x * 256 + threadIdx.x;
    if (t >= EE) return;
    int g = t >= (EE / 2);
    const int* ei = g ? ei2 : ei1;
    int e2 = (t - g * (EE / 2)) * 2;
    int2 s = *(const int2*)&ei[e2];
    int2 d = *(const int2*)&ei[EE + e2];
    int lp0 = g_lpos[g][e2], lp1 = g_lpos[g][e2 + 1];
    float c0 = g_dinv[g][s.x] * g_dinv[g][d.x];
    float c1 = g_dinv[g][s.y] * g_dinv[g][d.y];
    g_adjc[g][g_rowstart[g][d.x] + lp0] = make_int2(s.x, __float_as_int(c0));
    g_adjc[g][g_rowstart[g][d.y] + lp1] = make_int2(s.y, __float_as_int(c1));
}

// ---------------- tiled GEMM: 64x64 tiles, fp16 in (optional) / fp16 out ----------------
template <int FOUT, int KTOT, int RELU, int INHALF>
__global__ void __launch_bounds__(256, 4)
k_tgemm(const void* __restrict__ X0v, const void* __restrict__ X1v,
        const float* __restrict__ W,
        __half* __restrict__ H0, __half* __restrict__ H1) {
    constexpr int COLS = (FOUT >= 64) ? 64 : FOUT;
    constexpr int CPT = COLS / 32;
    __shared__ __align__(16) float As[32][68];
    __shared__ __align__(16) float Ws[32][COLS];
    int z = blockIdx.z;
    const void* Xv = z ? X1v : X0v;
    __half* H = z ? H1 : H0;
    int tid = threadIdx.x;
    int i0 = blockIdx.x * 64;
    int cb = blockIdx.y * COLS;
    int tx = tid & 31, ty = tid >> 5;
    u64 acc2[4][CPT];
#pragma unroll
    for (int r = 0; r < 4; r++)
#pragma unroll
        for (int c = 0; c < CPT; c++) acc2[r][c] = 0ull;

    for (int k0 = 0; k0 < KTOT; k0 += 32) {
        for (int idx = tid; idx < 512; idx += 256) {
            int r = idx >> 3, k4 = idx & 7;
            int row = i0 + r;
            float4 v = make_float4(0.f, 0.f, 0.f, 0.f);
            if (row < NN) {
                if (INHALF) {
                    uint2 raw = *(const uint2*)((const __half*)Xv + (size_t)row * KTOT + k0 + k4 * 4);
                    float2 a = __half22float2(*(__half2*)&raw.x);
                    float2 b = __half22float2(*(__half2*)&raw.y);
                    v = make_float4(a.x, a.y, b.x, b.y);
                } else {
                    v = *(const float4*)((const float*)Xv + (size_t)row * KTOT + k0 + k4 * 4);
                }
            }
            if (RELU) {
                v.x = fmaxf(v.x, 0.f); v.y = fmaxf(v.y, 0.f);
                v.z = fmaxf(v.z, 0.f); v.w = fmaxf(v.w, 0.f);
            }
            As[k4 * 4 + 0][r] = v.x; As[k4 * 4 + 1][r] = v.y;
            As[k4 * 4 + 2][r] = v.z; As[k4 * 4 + 3][r] = v.w;
        }
        for (int idx = tid; idx < 8 * COLS; idx += 256) {
            int j4 = idx % (COLS / 4), kk = idx / (COLS / 4);
            float4 w = *(const float4*)&W[(size_t)(k0 + kk) * FOUT + cb + j4 * 4];
            Ws[kk][j4 * 4 + 0] = w.x; Ws[kk][j4 * 4 + 1] = w.y;
            Ws[kk][j4 * 4 + 2] = w.z; Ws[kk][j4 * 4 + 3] = w.w;
        }
        __syncthreads();
#pragma unroll 4
        for (int k = 0; k < 32; k++) {
            u64 aa[4];
            {
                const ulonglong2* ap = (const ulonglong2*)&As[k][ty * 8];
                ulonglong2 t0 = ap[0], t1 = ap[1];
                aa[0] = t0.x; aa[1] = t0.y; aa[2] = t1.x; aa[3] = t1.y;
            }
            u64 bd[CPT];
            if (CPT == 2) {
                float2 b = *(const float2*)&Ws[k][tx * 2];
                bd[0] = dup2(b.x); bd[1] = dup2(b.y);
            } else {
                bd[0] = dup2(Ws[k][tx]);
            }
#pragma unroll
            for (int r = 0; r < 4; r++)
#pragma unroll
                for (int c = 0; c < CPT; c++) ffma2(acc2[r][c], aa[r], bd[c]);
        }
        __syncthreads();
    }
#pragma unroll
    for (int rp = 0; rp < 4; rp++) {
        int r0 = i0 + ty * 8 + 2 * rp;
        float lo[CPT], hi[CPT];
#pragma unroll
        for (int c = 0; c < CPT; c++) unpk(acc2[rp][c], lo[c], hi[c]);
        if (r0 < NN) {
            if (CPT == 2)
                *(__half2*)&H[(size_t)r0 * FOUT + cb + tx * 2] = __floats2half2_rn(lo[0], lo[1]);
            else
                H[(size_t)r0 * FOUT + cb + tx] = __float2half_rn(lo[0]);
        }
        if (r0 + 1 < NN) {
            if (CPT == 2)
                *(__half2*)&H[(size_t)(r0 + 1) * FOUT + cb + tx * 2] = __floats2half2_rn(hi[0], hi[1]);
            else
                H[(size_t)(r0 + 1) * FOUT + cb + tx] = __float2half_rn(hi[0]);
        }
    }
}

// ---------------- gather (H fp16, output fp16 or fp32) ----------------
template <int OUTHALF>
__global__ void k_gather(const __half* __restrict__ H0, const __half* __restrict__ H1,
                         const float* __restrict__ b,
                         void* __restrict__ O0v, void* __restrict__ O1v, int Fout) {
    int z = blockIdx.z;
    const __half* H = z ? H1 : H0;
    int gpf = Fout >> 2;
    int idx = blockIdx.x * 256 + threadIdx.x;
    int node = idx / gpf;
    int c = idx - node * gpf;
    if (node >= NN) return;
    int rs = g_rowstart[z][node], re = g_rowstart[z][node + 1];
    float invdeg = 1.0f / ((float)(re - rs) + 1.0f);
    __half2 h01, h23;
    {
        uint2 raw = *(const uint2*)((const __half*)(H + (size_t)node * Fout) + c * 4);
        h01 = *(__half2*)&raw.x; h23 = *(__half2*)&raw.y;
    }
    float2 f01 = __half22float2(h01), f23 = __half22float2(h23);
    float4 bb = ((const float4*)b)[c];
    float4 acc;
    acc.x = f01.x * invdeg + bb.x; acc.y = f01.y * invdeg + bb.y;
    acc.z = f23.x * invdeg + bb.z; acc.w = f23.y * invdeg + bb.w;
    const int2* __restrict__ adjc = g_adjc[z];
#pragma unroll 4
    for (int e = rs; e < re; e++) {
        int2 sc = __ldg(&adjc[e]);
        float coef = __int_as_float(sc.y);
        uint2 raw = __ldg((const uint2*)(H + (size_t)sc.x * Fout) + c);
        float2 v01 = __half22float2(*(__half2*)&raw.x);
        float2 v23 = __half22float2(*(__half2*)&raw.y);
        acc.x += coef * v01.x; acc.y += coef * v01.y;
        acc.z += coef * v23.x; acc.w += coef * v23.y;
    }
    if (OUTHALF) {
        __half* O = (__half*)(z ? O1v : O0v);
        __half2 h0 = __floats2half2_rn(acc.x, acc.y);
        __half2 h1 = __floats2half2_rn(acc.z, acc.w);
        uint2 o;
        o.x = *(unsigned*)&h0; o.y = *(unsigned*)&h1;
        *(uint2*)(O + (size_t)node * Fout + c * 4) = o;
    } else {
        float* O = (float*)(z ? O1v : O0v);
        ((float4*)(O + (size_t)node * Fout))[c] = acc;
    }
}

// ---------------- fp16 fragment builder ----------------
__device__ __forceinline__ float afld(const float* af, int n, int k) {
    return (n < NN) ? af[n * 32 + k] : 0.f;
}
__global__ void k_frag() {
    int wg = (blockIdx.x * 256 + threadIdx.x) >> 5;
    int lane = threadIdx.x & 31;
    if (wg < MT_TILES * 2) {
        int mt = wg >> 1, ks = wg & 1;
        const float* af = g_af[0];
        int r = mt * 16 + (lane >> 2);
        int kb = ks * 16 + (lane & 3) * 2;
        uint4 v;
        v.x = h2pack(afld(af, r,     kb),     afld(af, r,     kb + 1));
        v.y = h2pack(afld(af, r + 8, kb),     afld(af, r + 8, kb + 1));
        v.z = h2pack(afld(af, r,     kb + 8), afld(af, r,     kb + 9));
        v.w = h2pack(afld(af, r + 8, kb + 8), afld(af, r + 8, kb + 9));
        g_fA[(mt * 2 + ks) * 32 + lane] = v;
    } else if (wg < MT_TILES * 2 + NT_TILES * 2) {
        int w = wg - MT_TILES * 2;
        int nt = w >> 1, ks = w & 1;
        const float* af = g_af[1];
        int n = nt * 8 + (lane >> 2);
        int kb = ks * 16 + (lane & 3) * 2;
        uint2 v;
        v.x = h2pack(afld(af, n, kb),     afld(af, n, kb + 1));
        v.y = h2pack(afld(af, n, kb + 8), afld(af, n, kb + 9));
        g_fB[(nt * 2 + ks) * 32 + lane] = v;
    }
}

// ---------------- similarity passes via fp16 mma ----------------
__global__ void __launch_bounds__(256, 2)
k_simpass(int pass) {
    __shared__ __align__(16) uint2 shB[1024];
    __shared__ unsigned sh[16];
    int tid = threadIdx.x, lane = tid & 31, w = tid >> 5;
    int mt = blockIdx.y * 8 + w;
    int bx = blockIdx.x;
    {
        const uint4* src = (const uint4*)(g_fB + bx * 1024);
        uint4* dst = (uint4*)shB;
#pragma unroll
        for (int i = 0; i < 2; i++) dst[tid + 256 * i] = src[tid + 256 * i];
    }
    if (pass && tid < 16) sh[tid] = 0u;
    __syncthreads();
    uint4 afr[2];
#pragma unroll
    for (int ks = 0; ks < 2; ks++) afr[ks] = g_fA[(mt * 2 + ks) * 32 + lane];
    float c[16][4];
#pragma unroll
    for (int j = 0; j < 16; j++)
#pragma unroll
        for (int r = 0; r < 4; r++) c[j][r] = 0.f;
#pragma unroll
    for (int ks = 0; ks < 2; ks++) {
#pragma unroll
        for (int j = 0; j < 16; j++)
            mma_f16(c[j], afr[ks], shB[(j * 2 + ks) * 32 + lane]);
    }
    int r_lo = mt * 16 + (lane >> 2);
    int r_hi = r_lo + 8;
    int cb = bx * 128 + 2 * (lane & 3);
    bool full = (mt < 625) && (bx < 78);
    if (pass == 0) {
        float lmin = 3.4e38f, lmax = -3.4e38f;
        if (full) {
#pragma unroll
            for (int j = 0; j < 16; j++)
#pragma unroll
                for (int r = 0; r < 4; r++) {
                    lmin = fminf(lmin, c[j][r]);
                    lmax = fmaxf(lmax, c[j][r]);
                }
        } else {
            bool vlo = r_lo < NN, vhi = r_hi < NN;
#pragma unroll
            for (int j = 0; j < 16; j++) {
                int c0 = cb + j * 8;
                bool v0 = c0 < NN, v1 = c0 + 1 < NN;
                if (vlo && v0) { lmin = fminf(lmin, c[j][0]); lmax = fmaxf(lmax, c[j][0]); }
                if (vlo && v1) { lmin = fminf(lmin, c[j][1]); lmax = fmaxf(lmax, c[j][1]); }
                if (vhi && v0) { lmin = fminf(lmin, c[j][2]); lmax = fmaxf(lmax, c[j][2]); }
                if (vhi && v1) { lmin = fminf(lmin, c[j][3]); lmax = fmaxf(lmax, c[j][3]); }
            }
        }
        for (int o = 16; o; o >>= 1) {
            lmin = fminf(lmin, __shfl_down_sync(0xffffffffu, lmin, o));
            lmax = fmaxf(lmax, __shfl_down_sync(0xffffffffu, lmax, o));
        }
        if (lane == 0) {
            atomicMin(&g_keymin, fkey(lmin));
            atomicMax(&g_keymax, fkey(lmax));
        }
    } else {
        float lo_r = fdec(g_keymin), hi_r = fdec(g_keymax);
        float s16 = 16.0f / ((hi_r - lo_r) + 1e-12f);
        float b16 = -lo_r * s16;
        u64 cl = 0ull, ch = 0ull;
        if (full) {
#pragma unroll
            for (int j = 0; j < 16; j++)
#pragma unroll
                for (int r = 0; r < 4; r++) {
                    int b = (int)fmaf(c[j][r], s16, b16);
                    b = min(max(b, 0), 15);
                    if (b < 8) cl += 1ull << (b * 8);
                    else       ch += 1ull << ((b - 8) * 8);
                }
        } else {
            bool vr[2] = {r_lo < NN, r_hi < NN};
#pragma unroll
            for (int j = 0; j < 16; j++) {
                int c0 = cb + j * 8;
                bool vc[2] = {c0 < NN, c0 + 1 < NN};
#pragma unroll
                for (int r = 0; r < 4; r++) {
                    if (!(vr[r >> 1] && vc[r & 1])) continue;
                    int b = (int)fmaf(c[j][r], s16, b16);
                    b = min(max(b, 0), 15);
                    if (b < 8) cl += 1ull << (b * 8);
                    else       ch += 1ull << ((b - 8) * 8);
                }
            }
        }
#pragma unroll
        for (int b = 0; b < 16; b++) {
            unsigned v = (unsigned)((b < 8 ? (cl >> (b * 8)) : (ch >> ((b - 8) * 8))) & 0xFFull);
            for (int o = 16; o; o >>= 1) v += __shfl_down_sync(0xffffffffu, v, o);
            if (lane == 0 && v) atomicAdd(&sh[b], v);
        }
        __syncthreads();
        if (tid < 16 && sh[tid]) atomicAdd(&g_hist[tid * 32], sh[tid]);
    }
}

// ---------------- fused tail (attention + TN; no head) ----------------
__global__ void __launch_bounds__(256, 4)
k_tail(const float* __restrict__ att_w,
       const float* __restrict__ tn_w, const float* __restrict__ tn_wb,
       const float* __restrict__ tn_bias) {
    int bid = blockIdx.x, tid = threadIdx.x;
    int z = bid >= (TAILB / 2);
    int lb = z ? bid - TAILB / 2 : bid;
    int lane = tid & 31;
    int wz = (lb * 256 + tid) >> 5;
    const int nwz = (TAILB / 2) * 256 / 32;
    const float* X = g_af[z];

    {
        float acc = 0.f;
        for (int n = wz; n < NN; n += nwz) acc += X[n * 32 + lane];
        atomicAdd(&g_meanraw[z][lane], acc);
    }
    gridbar(0);
    if (bid == 0 && tid < 64) {
        int g = tid >> 5, j = tid & 31;
        float acc = 0.f;
        const float invN = 1.0f / NN;
        for (int f = 0; f < 32; f++)
            acc += (g_meanraw[g][f] * invN) * att_w[f * 32 + j];
        g_gc[g][j] = tanhf(acc);
    }
    gridbar(1);
    {
        float gcv = g_gc[z][lane];
        float acc = 0.f;
        for (int n = wz; n < NN; n += nwz) {
            float x = X[n * 32 + lane];
            float p = x * gcv;
            for (int o = 16; o; o >>= 1) p += __shfl_xor_sync(0xffffffffu, p, o);
            float sig = 1.0f / (1.0f + expf(-p));
            acc += x * sig;
        }
        atomicAdd(&g_pool[z][lane], acc);
    }
    gridbar(2);
    if (bid == 0) {
        for (int t = tid; t < 1024; t += 256) {
            int slot = t >> 9, r = t & 511, f = r >> 4, k = r & 15;
            const float* e2 = g_pool[1 - slot];
            float acc = tn_wb[k * 64 + f];
            for (int gg = 0; gg < 32; gg++)
                acc += tn_w[f * 512 + gg * 16 + k] * e2[gg];
            g_A[slot][f * 16 + k] = acc;
        }
        if (tid < 32) {
            int sl = tid >> 4, kk = tid & 15;
            const float* e2b = g_pool[1 - sl];
            float cc = tn_bias[kk];
            for (int gg = 0; gg < 32; gg++)
                cc += tn_wb[kk * 64 + 32 + gg] * e2b[gg];
            g_c[sl][kk] = cc;
        }
        __syncthreads();
        if (tid < 16) {
            float a2 = g_c[0][tid];
            for (int f2 = 0; f2 < 32; f2++)
                a2 += g_pool[0][f2] * g_A[0][f2 * 16 + tid];
            g_s0[tid] = fmaxf(a2, 0.f);
        }
    }
    gridbar(3);
    {
        float acc = 0.f;
        for (int n = wz; n < NN; n += nwz) {
            float x = X[n * 32 + lane];
            float v = (lane < 16) ? g_c[z][lane] : 0.f;
#pragma unroll
            for (int f = 0; f < 32; f++) {
                float xf = __shfl_sync(0xffffffffu, x, f);
                if (lane < 16) v += xf * g_A[z][f * 16 + lane];
            }
            if (lane < 16) acc += fmaxf(v, 0.f);
        }
        if (lane < 16) atomicAdd(&g_sAcc[z][lane], acc);
    }
}

// ---------------- final head (joins tail + simpass) ----------------
__global__ void k_head(const float* __restrict__ fc1_w, const float* __restrict__ fc1_b,
                       const float* __restrict__ fc2_w, const float* __restrict__ fc2_b,
                       float* __restrict__ out) {
    if (threadIdx.x != 0) return;
    float sc[64];
    const float invN = 1.0f / NN;
    for (int k = 0; k < 16; k++) {
        sc[k]      = g_s0[k];
        sc[16 + k] = g_sAcc[0][k] * invN;
        sc[32 + k] = g_sAcc[1][k] * invN;
    }
    float hf[16], hsum = 0.f;
    for (int b = 0; b < 16; b++) {
        unsigned c = g_hist[b * 32];
        if (c > 16777216u) c = 16777216u;
        hf[b] = (float)c;
        hsum += hf[b];
    }
    for (int b = 0; b < 16; b++) sc[48 + b] = hf[b] / hsum;
    float o2 = fc2_b[0];
    for (int j = 0; j < 16; j++) {
        float a = fc1_b[j];
        for (int i = 0; i < 64; i++) a += sc[i] * fc1_w[i * 16 + j];
        a = fmaxf(a, 0.f);
        o2 += a * fc2_w[j];
    }
    out[0] = 1.0f / (1.0f + expf(-o2));
}

// ---------------- host driver (fork/join via second stream) ----------------
extern "C" void kernel_launch(void* const* d_in, const int* in_sizes, int n_in,
                              void* d_out, int out_size) {
    const float* feat1 = (const float*)d_in[0];
    const float* feat2 = (const float*)d_in[1];
    const int* ei1 = (const int*)d_in[2];
    const int* ei2 = (const int*)d_in[3];
    const float* W1 = (const float*)d_in[4];
    const float* b1 = (const float*)d_in[5];
    const float* W2 = (const float*)d_in[6];
    const float* b2 = (const float*)d_in[7];
    const float* W3 = (const float*)d_in[8];
    const float* b3 = (const float*)d_in[9];
    const float* att_w = (const float*)d_in[10];
    const float* tn_w = (const float*)d_in[11];
    const float* tn_wb = (const float*)d_in[12];
    const float* tn_bias = (const float*)d_in[13];
    const float* fc1_w = (const float*)d_in[14];
    const float* fc1_b = (const float*)d_in[15];
    const float* fc2_w = (const float*)d_in[16];
    const float* fc2_b = (const float*)d_in[17];
    float* out = (float*)d_out;

    __half *H0, *H1, *X0, *X1;
    float *af0, *af1;
    cudaGetSymbolAddress((void**)&H0, g_Hh);  H1 = H0 + NN * 128;
    cudaGetSymbolAddress((void**)&X0, g_Xh);  X1 = X0 + NN * 128;
    cudaGetSymbolAddress((void**)&af0, g_af); af1 = af0 + NN * 32;

    static cudaStream_t sB = nullptr;
    static cudaEvent_t evStart, evT1, evG3, evTail;
    if (!sB) {
        cudaStreamCreateWithFlags(&sB, cudaStreamNonBlocking);
        cudaEventCreateWithFlags(&evStart, cudaEventDisableTiming);
        cudaEventCreateWithFlags(&evT1, cudaEventDisableTiming);
        cudaEventCreateWithFlags(&evG3, cudaEventDisableTiming);
        cudaEventCreateWithFlags(&evTail, cudaEventDisableTiming);
    }

    // fork: layer-1 GEMM on sB, CSR build on main stream
    cudaEventRecord(evStart, 0);
    cudaStreamWaitEvent(sB, evStart, 0);
    {
        dim3 g1((NN + 63) / 64, 2, 2);
        k_tgemm<128, 128, 0, 0><<<g1, 256, 0, sB>>>(feat1, feat2, W1, H0, H1);
    }
    cudaEventRecord(evT1, sB);

    k_reset<<<1, 1024>>>();
    k_indeg<<<(EE + 255) / 256, 256>>>(ei1, ei2);
    k_scan<<<2, 1024>>>();
    k_fill<<<(EE + 255) / 256, 256>>>(ei1, ei2);

    cudaStreamWaitEvent(0, evT1, 0);
    {
        dim3 grid((NN * 32 + 255) / 256, 1, 2);
        k_gather<1><<<grid, 256>>>(H0, H1, b1, X0, X1, 128);
    }
    {
        dim3 g2((NN + 63) / 64, 1, 2);
        k_tgemm<64, 128, 1, 1><<<g2, 256>>>(X0, X1, W2, H0, H1);
    }
    {
        dim3 grid((NN * 16 + 255) / 256, 1, 2);
        k_gather<1><<<grid, 256>>>(H0, H1, b2, X0, X1, 64);
    }
    {
        dim3 g3((NN + 63) / 64, 1, 2);
        k_tgemm<32, 64, 1, 1><<<g3, 256>>>(X0, X1, W3, H0, H1);
    }
    {
        dim3 grid((NN * 8 + 255) / 256, 1, 2);
        k_gather<0><<<grid, 256>>>(H0, H1, b3, af0, af1, 32);
    }

    // fork: tail (attention+TN) on sB, frag+simpass on main stream
    cudaEventRecord(evG3, 0);
    cudaStreamWaitEvent(sB, evG3, 0);
    k_tail<<<TAILB, 256, 0, sB>>>(att_w, tn_w, tn_wb, tn_bias);
    cudaEventRecord(evTail, sB);

    {
        int warps = MT_TILES * 2 + NT_TILES * 2;
        k_frag<<<(warps * 32 + 255) / 256, 256>>>();
    }
    dim3 hgrid((NN + 127) / 128, (NN + 127) / 128);
    k_simpass<<<hgrid, 256>>>(0);
    k_simpass<<<hgrid, 256>>>(1);

    // join
    cudaStreamWaitEvent(0, evTail, 0);
    k_head<<<1, 32>>>(fc1_w, fc1_b, fc2_w, fc2_b, out);
}

// round 12
// speedup vs baseline: 4.8639x; 1.0778x over previous
#include <cuda_runtime.h>
#include <cuda_fp16.h>
#include <math.h>

#define NN 10000
#define EE 320000
#define MT_TILES 632
#define NT_TILES 1264
#define TAILB 80
typedef unsigned long long u64;

// ---------------- device scratch ----------------
__device__ __half g_Hh[2][NN * 128];
__device__ __half g_Xh[2][NN * 128];
__device__ float g_af[2][NN * 32];
__device__ uint4 g_fA[MT_TILES * 2 * 32];
__device__ uint2 g_fB[NT_TILES * 2 * 32];
__device__ float g_dinv[2][NN];
__device__ int   g_indeg[2][NN];
__device__ int   g_rowstart[2][NN + 1];
__device__ int   g_blocksum[2][16];
__device__ int   g_lpos[2][EE];
__device__ int2  g_adjc[2][EE];
__device__ unsigned g_keymin, g_keymax;
__device__ unsigned g_hist[16 * 32];
__device__ unsigned g_barctr[8];
__device__ float g_meanraw[2][32];
__device__ float g_gc[2][32];
__device__ float g_pool[2][32];
__device__ float g_A[2][32 * 16];
__device__ float g_c[2][16];
__device__ float g_sAcc[2][16];
__device__ float g_s0[16];

// ---------------- helpers ----------------
__device__ __forceinline__ unsigned fkey(float f) {
    unsigned u = __float_as_uint(f);
    return (u & 0x80000000u) ? ~u : (u | 0x80000000u);
}
__device__ __forceinline__ float fdec(unsigned k) {
    return (k & 0x80000000u) ? __uint_as_float(k ^ 0x80000000u)
                             : __uint_as_float(~k);
}
__device__ __forceinline__ u64 dup2(float a) {
    u64 r;
    asm("mov.b64 %0, {%1, %1};" : "=l"(r) : "r"(__float_as_uint(a)));
    return r;
}
__device__ __forceinline__ void ffma2(u64& acc, u64 a, u64 b) {
    asm("fma.rn.f32x2 %0, %1, %2, %0;" : "+l"(acc) : "l"(a), "l"(b));
}
__device__ __forceinline__ void unpk(u64 v, float& lo, float& hi) {
    unsigned l, h;
    asm("mov.b64 {%0, %1}, %2;" : "=r"(l), "=r"(h) : "l"(v));
    lo = __uint_as_float(l); hi = __uint_as_float(h);
}
__device__ __forceinline__ unsigned h2pack(float a, float b) {
    __half2 h = __floats2half2_rn(a, b);
    return *(unsigned*)&h;
}
__device__ __forceinline__ void mma_f16(float c[4], uint4 a, uint2 b) {
    asm("mma.sync.aligned.m16n8k16.row.col.f32.f16.f16.f32 "
        "{%0,%1,%2,%3}, {%4,%5,%6,%7}, {%8,%9}, {%0,%1,%2,%3};"
        : "+f"(c[0]), "+f"(c[1]), "+f"(c[2]), "+f"(c[3])
        : "r"(a.x), "r"(a.y), "r"(a.z), "r"(a.w), "r"(b.x), "r"(b.y));
}
__device__ __forceinline__ void gridbar(int ph) {
    __syncthreads();
    if (threadIdx.x == 0) {
        __threadfence();
        unsigned t = atomicAdd(&g_barctr[ph], 1u) + 1;
        if (t < TAILB) {
            while (((volatile unsigned*)g_barctr)[ph] < TAILB) { }
        }
        __threadfence();
    }
    __syncthreads();
}

// ---------------- reset ----------------
__global__ void k_reset() {
    int t = threadIdx.x;
    for (int i = t; i < 2 * NN; i += 1024)
        ((int*)g_indeg)[i] = 0;
    if (t < 16 * 32) g_hist[t] = 0u;
    if (t < 32) {
        g_meanraw[0][t] = 0.f; g_meanraw[1][t] = 0.f;
        g_pool[0][t] = 0.f;    g_pool[1][t] = 0.f;
    }
    if (t < 16) { g_sAcc[0][t] = 0.f; g_sAcc[1][t] = 0.f; }
    if (t < 8) g_barctr[t] = 0u;
    if (t == 0) { g_keymin = 0xFFFFFFFFu; g_keymax = 0u; }
}

// ---------------- CSR build ----------------
__global__ void k_indeg(const int* __restrict__ ei1, const int* __restrict__ ei2) {
    int t = blockIdx.x * 256 + threadIdx.x;
    if (t >= EE) return;
    int g = t >= (EE / 2);
    const int* ei = g ? ei2 : ei1;
    int e2 = (t - g * (EE / 2)) * 2;
    int2 d = *(const int2*)&ei[EE + e2];
    int p0 = atomicAdd(&g_indeg[g][d.x], 1);
    int p1 = atomicAdd(&g_indeg[g][d.y], 1);
    g_lpos[g][e2] = p0;
    g_lpos[g][e2 + 1] = p1;
}

// chunked scan phase A: per-chunk local scan + chunk totals + dinv
__global__ void k_scanA() {        // grid (10, 2), block 1024
    int cx = blockIdx.x, g = blockIdx.y, t = threadIdx.x;
    int lane = t & 31, w = t >> 5;
    __shared__ int warpsum[32];
    int i = cx * 1024 + t;
    int v = (i < NN) ? g_indeg[g][i] : 0;
    int x = v;
#pragma unroll
    for (int o = 1; o < 32; o <<= 1) {
        int y = __shfl_up_sync(0xffffffffu, x, o);
        if (lane >= o) x += y;
    }
    if (lane == 31) warpsum[w] = x;
    __syncthreads();
    if (w == 0) {
        int ws = warpsum[lane];
#pragma unroll
        for (int o = 1; o < 32; o <<= 1) {
            int y = __shfl_up_sync(0xffffffffu, ws, o);
            if (lane >= o) ws += y;
        }
        warpsum[lane] = ws;
    }
    __syncthreads();
    int excl = (x - v) + (w ? warpsum[w - 1] : 0);
    if (i < NN) {
        g_rowstart[g][i] = excl;      // local (pre-offset)
        g_dinv[g][i] = rsqrtf((float)v + 1.0f);
    }
    if (t == 1023) g_blocksum[g][cx] = excl + v;
}

// phase B+C: scan chunk totals, add offsets
__global__ void k_scanBC() {       // grid 2, block 1024
    int g = blockIdx.x, t = threadIdx.x;
    __shared__ int choff[11];
    if (t == 0) {
        int run = 0;
        for (int c = 0; c < 10; c++) { choff[c] = run; run += g_blocksum[g][c]; }
        choff[10] = run;
        g_rowstart[g][NN] = run;
    }
    __syncthreads();
#pragma unroll
    for (int c = 0; c < 10; c++) {
        int i = c * 1024 + t;
        if (i < NN) g_rowstart[g][i] += choff[c];
    }
}

__global__ void k_fill(const int* __restrict__ ei1, const int* __restrict__ ei2) {
    int t = blockIdx.x * 256 + threadIdx.x;
    if (t >= EE) return;
    int g = t >= (EE / 2);
    const int* ei = g ? ei2 : ei1;
    int e2 = (t - g * (EE / 2)) * 2;
    int2 s = *(const int2*)&ei[e2];
    int2 d = *(const int2*)&ei[EE + e2];
    int lp0 = g_lpos[g][e2], lp1 = g_lpos[g][e2 + 1];
    float c0 = g_dinv[g][s.x] * g_dinv[g][d.x];
    float c1 = g_dinv[g][s.y] * g_dinv[g][d.y];
    g_adjc[g][g_rowstart[g][d.x] + lp0] = make_int2(s.x, __float_as_int(c0));
    g_adjc[g][g_rowstart[g][d.y] + lp1] = make_int2(s.y, __float_as_int(c1));
}

// ---------------- tiled GEMM ----------------
template <int FOUT, int KTOT, int RELU, int INHALF>
__global__ void __launch_bounds__(256, 4)
k_tgemm(const void* __restrict__ X0v, const void* __restrict__ X1v,
        const float* __restrict__ W,
        __half* __restrict__ H0, __half* __restrict__ H1) {
    constexpr int COLS = (FOUT >= 64) ? 64 : FOUT;
    constexpr int CPT = COLS / 32;
    __shared__ __align__(16) float As[32][68];
    __shared__ __align__(16) float Ws[32][COLS];
    int z = blockIdx.z;
    const void* Xv = z ? X1v : X0v;
    __half* H = z ? H1 : H0;
    int tid = threadIdx.x;
    int i0 = blockIdx.x * 64;
    int cb = blockIdx.y * COLS;
    int tx = tid & 31, ty = tid >> 5;
    u64 acc2[4][CPT];
#pragma unroll
    for (int r = 0; r < 4; r++)
#pragma unroll
        for (int c = 0; c < CPT; c++) acc2[r][c] = 0ull;

    for (int k0 = 0; k0 < KTOT; k0 += 32) {
        for (int idx = tid; idx < 512; idx += 256) {
            int r = idx >> 3, k4 = idx & 7;
            int row = i0 + r;
            float4 v = make_float4(0.f, 0.f, 0.f, 0.f);
            if (row < NN) {
                if (INHALF) {
                    uint2 raw = *(const uint2*)((const __half*)Xv + (size_t)row * KTOT + k0 + k4 * 4);
                    float2 a = __half22float2(*(__half2*)&raw.x);
                    float2 b = __half22float2(*(__half2*)&raw.y);
                    v = make_float4(a.x, a.y, b.x, b.y);
                } else {
                    v = *(const float4*)((const float*)Xv + (size_t)row * KTOT + k0 + k4 * 4);
                }
            }
            if (RELU) {
                v.x = fmaxf(v.x, 0.f); v.y = fmaxf(v.y, 0.f);
                v.z = fmaxf(v.z, 0.f); v.w = fmaxf(v.w, 0.f);
            }
            As[k4 * 4 + 0][r] = v.x; As[k4 * 4 + 1][r] = v.y;
            As[k4 * 4 + 2][r] = v.z; As[k4 * 4 + 3][r] = v.w;
        }
        for (int idx = tid; idx < 8 * COLS; idx += 256) {
            int j4 = idx % (COLS / 4), kk = idx / (COLS / 4);
            float4 w = *(const float4*)&W[(size_t)(k0 + kk) * FOUT + cb + j4 * 4];
            Ws[kk][j4 * 4 + 0] = w.x; Ws[kk][j4 * 4 + 1] = w.y;
            Ws[kk][j4 * 4 + 2] = w.z; Ws[kk][j4 * 4 + 3] = w.w;
        }
        __syncthreads();
#pragma unroll 4
        for (int k = 0; k < 32; k++) {
            u64 aa[4];
            {
                const ulonglong2* ap = (const ulonglong2*)&As[k][ty * 8];
                ulonglong2 t0 = ap[0], t1 = ap[1];
                aa[0] = t0.x; aa[1] = t0.y; aa[2] = t1.x; aa[3] = t1.y;
            }
            u64 bd[CPT];
            if (CPT == 2) {
                float2 b = *(const float2*)&Ws[k][tx * 2];
                bd[0] = dup2(b.x); bd[1] = dup2(b.y);
            } else {
                bd[0] = dup2(Ws[k][tx]);
            }
#pragma unroll
            for (int r = 0; r < 4; r++)
#pragma unroll
                for (int c = 0; c < CPT; c++) ffma2(acc2[r][c], aa[r], bd[c]);
        }
        __syncthreads();
    }
#pragma unroll
    for (int rp = 0; rp < 4; rp++) {
        int r0 = i0 + ty * 8 + 2 * rp;
        float lo[CPT], hi[CPT];
#pragma unroll
        for (int c = 0; c < CPT; c++) unpk(acc2[rp][c], lo[c], hi[c]);
        if (r0 < NN) {
            if (CPT == 2)
                *(__half2*)&H[(size_t)r0 * FOUT + cb + tx * 2] = __floats2half2_rn(lo[0], lo[1]);
            else
                H[(size_t)r0 * FOUT + cb + tx] = __float2half_rn(lo[0]);
        }
        if (r0 + 1 < NN) {
            if (CPT == 2)
                *(__half2*)&H[(size_t)(r0 + 1) * FOUT + cb + tx * 2] = __floats2half2_rn(hi[0], hi[1]);
            else
                H[(size_t)(r0 + 1) * FOUT + cb + tx] = __float2half_rn(hi[0]);
        }
    }
}

// ---------------- gather ----------------
template <int OUTHALF>
__global__ void k_gather(const __half* __restrict__ H0, const __half* __restrict__ H1,
                         const float* __restrict__ b,
                         void* __restrict__ O0v, void* __restrict__ O1v, int Fout) {
    int z = blockIdx.z;
    const __half* H = z ? H1 : H0;
    int gpf = Fout >> 2;
    int idx = blockIdx.x * 256 + threadIdx.x;
    int node = idx / gpf;
    int c = idx - node * gpf;
    if (node >= NN) return;
    int rs = g_rowstart[z][node], re = g_rowstart[z][node + 1];
    float invdeg = 1.0f / ((float)(re - rs) + 1.0f);
    __half2 h01, h23;
    {
        uint2 raw = *(const uint2*)((const __half*)(H + (size_t)node * Fout) + c * 4);
        h01 = *(__half2*)&raw.x; h23 = *(__half2*)&raw.y;
    }
    float2 f01 = __half22float2(h01), f23 = __half22float2(h23);
    float4 bb = ((const float4*)b)[c];
    float4 acc;
    acc.x = f01.x * invdeg + bb.x; acc.y = f01.y * invdeg + bb.y;
    acc.z = f23.x * invdeg + bb.z; acc.w = f23.y * invdeg + bb.w;
    const int2* __restrict__ adjc = g_adjc[z];
#pragma unroll 4
    for (int e = rs; e < re; e++) {
        int2 sc = __ldg(&adjc[e]);
        float coef = __int_as_float(sc.y);
        uint2 raw = __ldg((const uint2*)(H + (size_t)sc.x * Fout) + c);
        float2 v01 = __half22float2(*(__half2*)&raw.x);
        float2 v23 = __half22float2(*(__half2*)&raw.y);
        acc.x += coef * v01.x; acc.y += coef * v01.y;
        acc.z += coef * v23.x; acc.w += coef * v23.y;
    }
    if (OUTHALF) {
        __half* O = (__half*)(z ? O1v : O0v);
        __half2 h0 = __floats2half2_rn(acc.x, acc.y);
        __half2 h1 = __floats2half2_rn(acc.z, acc.w);
        uint2 o;
        o.x = *(unsigned*)&h0; o.y = *(unsigned*)&h1;
        *(uint2*)(O + (size_t)node * Fout + c * 4) = o;
    } else {
        float* O = (float*)(z ? O1v : O0v);
        ((float4*)(O + (size_t)node * Fout))[c] = acc;
    }
}

// ---------------- fp16 fragment builder ----------------
__device__ __forceinline__ float afld(const float* af, int n, int k) {
    return (n < NN) ? af[n * 32 + k] : 0.f;
}
__global__ void k_frag() {
    int wg = (blockIdx.x * 256 + threadIdx.x) >> 5;
    int lane = threadIdx.x & 31;
    if (wg < MT_TILES * 2) {
        int mt = wg >> 1, ks = wg & 1;
        const float* af = g_af[0];
        int r = mt * 16 + (lane >> 2);
        int kb = ks * 16 + (lane & 3) * 2;
        uint4 v;
        v.x = h2pack(afld(af, r,     kb),     afld(af, r,     kb + 1));
        v.y = h2pack(afld(af, r + 8, kb),     afld(af, r + 8, kb + 1));
        v.z = h2pack(afld(af, r,     kb + 8), afld(af, r,     kb + 9));
        v.w = h2pack(afld(af, r + 8, kb + 8), afld(af, r + 8, kb + 9));
        g_fA[(mt * 2 + ks) * 32 + lane] = v;
    } else if (wg < MT_TILES * 2 + NT_TILES * 2) {
        int w = wg - MT_TILES * 2;
        int nt = w >> 1, ks = w & 1;
        const float* af = g_af[1];
        int n = nt * 8 + (lane >> 2);
        int kb = ks * 16 + (lane & 3) * 2;
        uint2 v;
        v.x = h2pack(afld(af, n, kb),     afld(af, n, kb + 1));
        v.y = h2pack(afld(af, n, kb + 8), afld(af, n, kb + 9));
        g_fB[(nt * 2 + ks) * 32 + lane] = v;
    }
}

// ---------------- similarity passes via fp16 mma ----------------
__global__ void __launch_bounds__(256, 2)
k_simpass(int pass) {
    __shared__ __align__(16) uint2 shB[1024];
    __shared__ unsigned sh[16];
    int tid = threadIdx.x, lane = tid & 31, w = tid >> 5;
    int mt = blockIdx.y * 8 + w;
    int bx = blockIdx.x;
    {
        const uint4* src = (const uint4*)(g_fB + bx * 1024);
        uint4* dst = (uint4*)shB;
#pragma unroll
        for (int i = 0; i < 2; i++) dst[tid + 256 * i] = src[tid + 256 * i];
    }
    if (pass && tid < 16) sh[tid] = 0u;
    __syncthreads();
    uint4 afr[2];
#pragma unroll
    for (int ks = 0; ks < 2; ks++) afr[ks] = g_fA[(mt * 2 + ks) * 32 + lane];
    float c[16][4];
#pragma unroll
    for (int j = 0; j < 16; j++)
#pragma unroll
        for (int r = 0; r < 4; r++) c[j][r] = 0.f;
#pragma unroll
    for (int ks = 0; ks < 2; ks++) {
#pragma unroll
        for (int j = 0; j < 16; j++)
            mma_f16(c[j], afr[ks], shB[(j * 2 + ks) * 32 + lane]);
    }
    int r_lo = mt * 16 + (lane >> 2);
    int r_hi = r_lo + 8;
    int cb = bx * 128 + 2 * (lane & 3);
    bool full = (mt < 625) && (bx < 78);
    if (pass == 0) {
        float lmin = 3.4e38f, lmax = -3.4e38f;
        if (full) {
#pragma unroll
            for (int j = 0; j < 16; j++)
#pragma unroll
                for (int r = 0; r < 4; r++) {
                    lmin = fminf(lmin, c[j][r]);
                    lmax = fmaxf(lmax, c[j][r]);
                }
        } else {
            bool vlo = r_lo < NN, vhi = r_hi < NN;
#pragma unroll
            for (int j = 0; j < 16; j++) {
                int c0 = cb + j * 8;
                bool v0 = c0 < NN, v1 = c0 + 1 < NN;
                if (vlo && v0) { lmin = fminf(lmin, c[j][0]); lmax = fmaxf(lmax, c[j][0]); }
                if (vlo && v1) { lmin = fminf(lmin, c[j][1]); lmax = fmaxf(lmax, c[j][1]); }
                if (vhi && v0) { lmin = fminf(lmin, c[j][2]); lmax = fmaxf(lmax, c[j][2]); }
                if (vhi && v1) { lmin = fminf(lmin, c[j][3]); lmax = fmaxf(lmax, c[j][3]); }
            }
        }
        for (int o = 16; o; o >>= 1) {
            lmin = fminf(lmin, __shfl_down_sync(0xffffffffu, lmin, o));
            lmax = fmaxf(lmax, __shfl_down_sync(0xffffffffu, lmax, o));
        }
        if (lane == 0) {
            atomicMin(&g_keymin, fkey(lmin));
            atomicMax(&g_keymax, fkey(lmax));
        }
    } else {
        float lo_r = fdec(g_keymin), hi_r = fdec(g_keymax);
        float s16 = 16.0f / ((hi_r - lo_r) + 1e-12f);
        float b16 = -lo_r * s16;
        u64 cl = 0ull, ch = 0ull;
        if (full) {
#pragma unroll
            for (int j = 0; j < 16; j++)
#pragma unroll
                for (int r = 0; r < 4; r++) {
                    int b = (int)fmaf(c[j][r], s16, b16);
                    b = min(max(b, 0), 15);
                    if (b < 8) cl += 1ull << (b * 8);
                    else       ch += 1ull << ((b - 8) * 8);
                }
        } else {
            bool vr[2] = {r_lo < NN, r_hi < NN};
#pragma unroll
            for (int j = 0; j < 16; j++) {
                int c0 = cb + j * 8;
                bool vc[2] = {c0 < NN, c0 + 1 < NN};
#pragma unroll
                for (int r = 0; r < 4; r++) {
                    if (!(vr[r >> 1] && vc[r & 1])) continue;
                    int b = (int)fmaf(c[j][r], s16, b16);
                    b = min(max(b, 0), 15);
                    if (b < 8) cl += 1ull << (b * 8);
                    else       ch += 1ull << ((b - 8) * 8);
                }
            }
        }
        // u16-field SIMD reduce: bytes -> u16 fields, 4 u64 shuffle-sums
        const u64 M = 0x00FF00FF00FF00FFull;
        u64 e0 = cl & M, e1 = (cl >> 8) & M;
        u64 e2 = ch & M, e3 = (ch >> 8) & M;
#pragma unroll
        for (int o = 16; o; o >>= 1) {
            e0 += __shfl_down_sync(0xffffffffu, e0, o);
            e1 += __shfl_down_sync(0xffffffffu, e1, o);
            e2 += __shfl_down_sync(0xffffffffu, e2, o);
            e3 += __shfl_down_sync(0xffffffffu, e3, o);
        }
        if (lane == 0) {
            // e0 fields: bins 0,2,4,6 ; e1: 1,3,5,7 ; e2: 8,10,12,14 ; e3: 9,11,13,15
#pragma unroll
            for (int i = 0; i < 4; i++) {
                unsigned v0 = (unsigned)((e0 >> (16 * i)) & 0xFFFFull);
                unsigned v1 = (unsigned)((e1 >> (16 * i)) & 0xFFFFull);
                unsigned v2 = (unsigned)((e2 >> (16 * i)) & 0xFFFFull);
                unsigned v3 = (unsigned)((e3 >> (16 * i)) & 0xFFFFull);
                if (v0) atomicAdd(&sh[2 * i], v0);
                if (v1) atomicAdd(&sh[2 * i + 1], v1);
                if (v2) atomicAdd(&sh[8 + 2 * i], v2);
                if (v3) atomicAdd(&sh[9 + 2 * i], v3);
            }
        }
        __syncthreads();
        if (tid < 16 && sh[tid]) atomicAdd(&g_hist[tid * 32], sh[tid]);
    }
}

// ---------------- fused tail (attention + TN) ----------------
__global__ void __launch_bounds__(256, 4)
k_tail(const float* __restrict__ att_w,
       const float* __restrict__ tn_w, const float* __restrict__ tn_wb,
       const float* __restrict__ tn_bias) {
    int bid = blockIdx.x, tid = threadIdx.x;
    int z = bid >= (TAILB / 2);
    int lb = z ? bid - TAILB / 2 : bid;
    int lane = tid & 31;
    int wz = (lb * 256 + tid) >> 5;
    const int nwz = (TAILB / 2) * 256 / 32;
    const float* X = g_af[z];

    {
        float acc = 0.f;
        for (int n = wz; n < NN; n += nwz) acc += X[n * 32 + lane];
        atomicAdd(&g_meanraw[z][lane], acc);
    }
    gridbar(0);
    if (bid == 0 && tid < 64) {
        int g = tid >> 5, j = tid & 31;
        float acc = 0.f;
        const float invN = 1.0f / NN;
        for (int f = 0; f < 32; f++)
            acc += (g_meanraw[g][f] * invN) * att_w[f * 32 + j];
        g_gc[g][j] = tanhf(acc);
    }
    gridbar(1);
    {
        float gcv = g_gc[z][lane];
        float acc = 0.f;
        for (int n = wz; n < NN; n += nwz) {
            float x = X[n * 32 + lane];
            float p = x * gcv;
            for (int o = 16; o; o >>= 1) p += __shfl_xor_sync(0xffffffffu, p, o);
            float sig = 1.0f / (1.0f + expf(-p));
            acc += x * sig;
        }
        atomicAdd(&g_pool[z][lane], acc);
    }
    gridbar(2);
    if (bid == 0) {
        for (int t = tid; t < 1024; t += 256) {
            int slot = t >> 9, r = t & 511, f = r >> 4, k = r & 15;
            const float* e2 = g_pool[1 - slot];
            float acc = tn_wb[k * 64 + f];
            for (int gg = 0; gg < 32; gg++)
                acc += tn_w[f * 512 + gg * 16 + k] * e2[gg];
            g_A[slot][f * 16 + k] = acc;
        }
        if (tid < 32) {
            int sl = tid >> 4, kk = tid & 15;
            const float* e2b = g_pool[1 - sl];
            float cc = tn_bias[kk];
            for (int gg = 0; gg < 32; gg++)
                cc += tn_wb[kk * 64 + 32 + gg] * e2b[gg];
            g_c[sl][kk] = cc;
        }
        __syncthreads();
        if (tid < 16) {
            float a2 = g_c[0][tid];
            for (int f2 = 0; f2 < 32; f2++)
                a2 += g_pool[0][f2] * g_A[0][f2 * 16 + tid];
            g_s0[tid] = fmaxf(a2, 0.f);
        }
    }
    gridbar(3);
    {
        float acc = 0.f;
        for (int n = wz; n < NN; n += nwz) {
            float x = X[n * 32 + lane];
            float v = (lane < 16) ? g_c[z][lane] : 0.f;
#pragma unroll
            for (int f = 0; f < 32; f++) {
                float xf = __shfl_sync(0xffffffffu, x, f);
                if (lane < 16) v += xf * g_A[z][f * 16 + lane];
            }
            if (lane < 16) acc += fmaxf(v, 0.f);
        }
        if (lane < 16) atomicAdd(&g_sAcc[z][lane], acc);
    }
}

// ---------------- final head ----------------
__global__ void k_head(const float* __restrict__ fc1_w, const float* __restrict__ fc1_b,
                       const float* __restrict__ fc2_w, const float* __restrict__ fc2_b,
                       float* __restrict__ out) {
    if (threadIdx.x != 0) return;
    float sc[64];
    const float invN = 1.0f / NN;
    for (int k = 0; k < 16; k++) {
        sc[k]      = g_s0[k];
        sc[16 + k] = g_sAcc[0][k] * invN;
        sc[32 + k] = g_sAcc[1][k] * invN;
    }
    float hf[16], hsum = 0.f;
    for (int b = 0; b < 16; b++) {
        unsigned c = g_hist[b * 32];
        if (c > 16777216u) c = 16777216u;
        hf[b] = (float)c;
        hsum += hf[b];
    }
    for (int b = 0; b < 16; b++) sc[48 + b] = hf[b] / hsum;
    float o2 = fc2_b[0];
    for (int j = 0; j < 16; j++) {
        float a = fc1_b[j];
        for (int i = 0; i < 64; i++) a += sc[i] * fc1_w[i * 16 + j];
        a = fmaxf(a, 0.f);
        o2 += a * fc2_w[j];
    }
    out[0] = 1.0f / (1.0f + expf(-o2));
}

// ---------------- host driver ----------------
extern "C" void kernel_launch(void* const* d_in, const int* in_sizes, int n_in,
                              void* d_out, int out_size) {
    const float* feat1 = (const float*)d_in[0];
    const float* feat2 = (const float*)d_in[1];
    const int* ei1 = (const int*)d_in[2];
    const int* ei2 = (const int*)d_in[3];
    const float* W1 = (const float*)d_in[4];
    const float* b1 = (const float*)d_in[5];
    const float* W2 = (const float*)d_in[6];
    const float* b2 = (const float*)d_in[7];
    const float* W3 = (const float*)d_in[8];
    const float* b3 = (const float*)d_in[9];
    const float* att_w = (const float*)d_in[10];
    const float* tn_w = (const float*)d_in[11];
    const float* tn_wb = (const float*)d_in[12];
    const float* tn_bias = (const float*)d_in[13];
    const float* fc1_w = (const float*)d_in[14];
    const float* fc1_b = (const float*)d_in[15];
    const float* fc2_w = (const float*)d_in[16];
    const float* fc2_b = (const float*)d_in[17];
    float* out = (float*)d_out;

    __half *H0, *H1, *X0, *X1;
    float *af0, *af1;
    cudaGetSymbolAddress((void**)&H0, g_Hh);  H1 = H0 + NN * 128;
    cudaGetSymbolAddress((void**)&X0, g_Xh);  X1 = X0 + NN * 128;
    cudaGetSymbolAddress((void**)&af0, g_af); af1 = af0 + NN * 32;

    static cudaStream_t sB = nullptr;
    static cudaEvent_t evStart, evT1, evG3, evTail;
    if (!sB) {
        cudaStreamCreateWithFlags(&sB, cudaStreamNonBlocking);
        cudaEventCreateWithFlags(&evStart, cudaEventDisableTiming);
        cudaEventCreateWithFlags(&evT1, cudaEventDisableTiming);
        cudaEventCreateWithFlags(&evG3, cudaEventDisableTiming);
        cudaEventCreateWithFlags(&evTail, cudaEventDisableTiming);
    }

    // fork: layer-1 GEMM on sB, CSR build on main stream
    cudaEventRecord(evStart, 0);
    cudaStreamWaitEvent(sB, evStart, 0);
    {
        dim3 g1((NN + 63) / 64, 2, 2);
        k_tgemm<128, 128, 0, 0><<<g1, 256, 0, sB>>>(feat1, feat2, W1, H0, H1);
    }
    cudaEventRecord(evT1, sB);

    k_reset<<<1, 1024>>>();
    k_indeg<<<(EE + 255) / 256, 256>>>(ei1, ei2);
    {
        dim3 sg(10, 2);
        k_scanA<<<sg, 1024>>>();
    }
    k_scanBC<<<2, 1024>>>();
    k_fill<<<(EE + 255) / 256, 256>>>(ei1, ei2);

    cudaStreamWaitEvent(0, evT1, 0);
    {
        dim3 grid((NN * 32 + 255) / 256, 1, 2);
        k_gather<1><<<grid, 256>>>(H0, H1, b1, X0, X1, 128);
    }
    {
        dim3 g2((NN + 63) / 64, 1, 2);
        k_tgemm<64, 128, 1, 1><<<g2, 256>>>(X0, X1, W2, H0, H1);
    }
    {
        dim3 grid((NN * 16 + 255) / 256, 1, 2);
        k_gather<1><<<grid, 256>>>(H0, H1, b2, X0, X1, 64);
    }
    {
        dim3 g3((NN + 63) / 64, 1, 2);
        k_tgemm<32, 64, 1, 1><<<g3, 256>>>(X0, X1, W3, H0, H1);
    }
    {
        dim3 grid((NN * 8 + 255) / 256, 1, 2);
        k_gather<0><<<grid, 256>>>(H0, H1, b3, af0, af1, 32);
    }

    // fork: tail on sB, frag+simpass on main stream
    cudaEventRecord(evG3, 0);
    cudaStreamWaitEvent(sB, evG3, 0);
    k_tail<<<TAILB, 256, 0, sB>>>(att_w, tn_w, tn_wb, tn_bias);
    cudaEventRecord(evTail, sB);

    {
        int warps = MT_TILES * 2 + NT_TILES * 2;
        k_frag<<<(warps * 32 + 255) / 256, 256>>>();
    }
    dim3 hgrid((NN + 127) / 128, (NN + 127) / 128);
    k_simpass<<<hgrid, 256>>>(0);
    k_simpass<<<hgrid, 256>>>(1);

    // join
    cudaStreamWaitEvent(0, evTail, 0);
    k_head<<<1, 32>>>(fc1_w, fc1_b, fc2_w, fc2_b, out);
}

// round 13
// speedup vs baseline: 4.8855x; 1.0044x over previous
#include <cuda_runtime.h>
#include <cuda_fp16.h>
#include <math.h>

#define NN 10000
#define EE 320000
#define MT_TILES 632
#define NT_TILES 1264
#define TAILB 80
typedef unsigned long long u64;

// ---------------- device scratch ----------------
__device__ __half g_Hh[2][NN * 128];
__device__ __half g_Xh[2][NN * 128];
__device__ float g_af[2][NN * 32];
__device__ uint4 g_fA[MT_TILES * 2 * 32];
__device__ uint2 g_fB[NT_TILES * 2 * 32];
__device__ float g_dinv[2][NN];
__device__ int   g_indeg[2][NN];
__device__ int   g_rowstart[2][NN + 1];
__device__ int   g_blocksum[2][16];
__device__ int   g_lpos[2][EE];
__device__ int2  g_adjc[2][EE];
__device__ unsigned g_keymin, g_keymax;
__device__ unsigned g_hist[16 * 32];
__device__ unsigned g_barctr[8];
__device__ float g_meanraw[2][32];
__device__ float g_gc[2][32];
__device__ float g_pool[2][32];
__device__ float g_A[2][32 * 16];
__device__ float g_c[2][16];
__device__ float g_sAcc[2][16];
__device__ float g_s0[16];

// ---------------- helpers ----------------
__device__ __forceinline__ unsigned fkey(float f) {
    unsigned u = __float_as_uint(f);
    return (u & 0x80000000u) ? ~u : (u | 0x80000000u);
}
__device__ __forceinline__ float fdec(unsigned k) {
    return (k & 0x80000000u) ? __uint_as_float(k ^ 0x80000000u)
                             : __uint_as_float(~k);
}
__device__ __forceinline__ u64 dup2(float a) {
    u64 r;
    asm("mov.b64 %0, {%1, %1};" : "=l"(r) : "r"(__float_as_uint(a)));
    return r;
}
__device__ __forceinline__ void ffma2(u64& acc, u64 a, u64 b) {
    asm("fma.rn.f32x2 %0, %1, %2, %0;" : "+l"(acc) : "l"(a), "l"(b));
}
__device__ __forceinline__ void unpk(u64 v, float& lo, float& hi) {
    unsigned l, h;
    asm("mov.b64 {%0, %1}, %2;" : "=r"(l), "=r"(h) : "l"(v));
    lo = __uint_as_float(l); hi = __uint_as_float(h);
}
__device__ __forceinline__ unsigned h2pack(float a, float b) {
    __half2 h = __floats2half2_rn(a, b);
    return *(unsigned*)&h;
}
__device__ __forceinline__ void mma_f16(float c[4], uint4 a, uint2 b) {
    asm("mma.sync.aligned.m16n8k16.row.col.f32.f16.f16.f32 "
        "{%0,%1,%2,%3}, {%4,%5,%6,%7}, {%8,%9}, {%0,%1,%2,%3};"
        : "+f"(c[0]), "+f"(c[1]), "+f"(c[2]), "+f"(c[3])
        : "r"(a.x), "r"(a.y), "r"(a.z), "r"(a.w), "r"(b.x), "r"(b.y));
}
__device__ __forceinline__ void gridbar(int ph) {
    __syncthreads();
    if (threadIdx.x == 0) {
        __threadfence();
        unsigned t = atomicAdd(&g_barctr[ph], 1u) + 1;
        if (t < TAILB) {
            while (((volatile unsigned*)g_barctr)[ph] < TAILB) { }
        }
        __threadfence();
    }
    __syncthreads();
}

// ---------------- reset ----------------
__global__ void k_reset() {
    int t = threadIdx.x;
    for (int i = t; i < 2 * NN; i += 1024)
        ((int*)g_indeg)[i] = 0;
    if (t < 16 * 32) g_hist[t] = 0u;
    if (t < 32) {
        g_meanraw[0][t] = 0.f; g_meanraw[1][t] = 0.f;
        g_pool[0][t] = 0.f;    g_pool[1][t] = 0.f;
    }
    if (t < 16) { g_sAcc[0][t] = 0.f; g_sAcc[1][t] = 0.f; }
    if (t < 8) g_barctr[t] = 0u;
    if (t == 0) { g_keymin = 0xFFFFFFFFu; g_keymax = 0u; }
}

// ---------------- CSR build ----------------
__global__ void k_indeg(const int* __restrict__ ei1, const int* __restrict__ ei2) {
    int t = blockIdx.x * 256 + threadIdx.x;
    if (t >= EE) return;
    int g = t >= (EE / 2);
    const int* ei = g ? ei2 : ei1;
    int e2 = (t - g * (EE / 2)) * 2;
    int2 d = *(const int2*)&ei[EE + e2];
    int p0 = atomicAdd(&g_indeg[g][d.x], 1);
    int p1 = atomicAdd(&g_indeg[g][d.y], 1);
    g_lpos[g][e2] = p0;
    g_lpos[g][e2 + 1] = p1;
}

__global__ void k_scanA() {        // grid (10, 2), block 1024
    int cx = blockIdx.x, g = blockIdx.y, t = threadIdx.x;
    int lane = t & 31, w = t >> 5;
    __shared__ int warpsum[32];
    int i = cx * 1024 + t;
    int v = (i < NN) ? g_indeg[g][i] : 0;
    int x = v;
#pragma unroll
    for (int o = 1; o < 32; o <<= 1) {
        int y = __shfl_up_sync(0xffffffffu, x, o);
        if (lane >= o) x += y;
    }
    if (lane == 31) warpsum[w] = x;
    __syncthreads();
    if (w == 0) {
        int ws = warpsum[lane];
#pragma unroll
        for (int o = 1; o < 32; o <<= 1) {
            int y = __shfl_up_sync(0xffffffffu, ws, o);
            if (lane >= o) ws += y;
        }
        warpsum[lane] = ws;
    }
    __syncthreads();
    int excl = (x - v) + (w ? warpsum[w - 1] : 0);
    if (i < NN) {
        g_rowstart[g][i] = excl;
        g_dinv[g][i] = rsqrtf((float)v + 1.0f);
    }
    if (t == 1023) g_blocksum[g][cx] = excl + v;
}

__global__ void k_scanBC() {       // grid 2, block 1024
    int g = blockIdx.x, t = threadIdx.x;
    __shared__ int choff[11];
    if (t == 0) {
        int run = 0;
        for (int c = 0; c < 10; c++) { choff[c] = run; run += g_blocksum[g][c]; }
        choff[10] = run;
        g_rowstart[g][NN] = run;
    }
    __syncthreads();
#pragma unroll
    for (int c = 0; c < 10; c++) {
        int i = c * 1024 + t;
        if (i < NN) g_rowstart[g][i] += choff[c];
    }
}

__global__ void k_fill(const int* __restrict__ ei1, const int* __restrict__ ei2) {
    int t = blockIdx.x * 256 + threadIdx.x;
    if (t >= EE) return;
    int g = t >= (EE / 2);
    const int* ei = g ? ei2 : ei1;
    int e2 = (t - g * (EE / 2)) * 2;
    int2 s = *(const int2*)&ei[e2];
    int2 d = *(const int2*)&ei[EE + e2];
    int lp0 = g_lpos[g][e2], lp1 = g_lpos[g][e2 + 1];
    float c0 = g_dinv[g][s.x] * g_dinv[g][d.x];
    float c1 = g_dinv[g][s.y] * g_dinv[g][d.y];
    g_adjc[g][g_rowstart[g][d.x] + lp0] = make_int2(s.x, __float_as_int(c0));
    g_adjc[g][g_rowstart[g][d.y] + lp1] = make_int2(s.y, __float_as_int(c1));
}

// ---------------- tiled GEMM (zoff selects graph) ----------------
template <int FOUT, int KTOT, int RELU, int INHALF>
__global__ void __launch_bounds__(256, 4)
k_tgemm(const void* __restrict__ X0v, const void* __restrict__ X1v,
        const float* __restrict__ W,
        __half* __restrict__ H0, __half* __restrict__ H1, int zoff) {
    constexpr int COLS = (FOUT >= 64) ? 64 : FOUT;
    constexpr int CPT = COLS / 32;
    __shared__ __align__(16) float As[32][68];
    __shared__ __align__(16) float Ws[32][COLS];
    int z = blockIdx.z + zoff;
    const void* Xv = z ? X1v : X0v;
    __half* H = z ? H1 : H0;
    int tid = threadIdx.x;
    int i0 = blockIdx.x * 64;
    int cb = blockIdx.y * COLS;
    int tx = tid & 31, ty = tid >> 5;
    u64 acc2[4][CPT];
#pragma unroll
    for (int r = 0; r < 4; r++)
#pragma unroll
        for (int c = 0; c < CPT; c++) acc2[r][c] = 0ull;

    for (int k0 = 0; k0 < KTOT; k0 += 32) {
        for (int idx = tid; idx < 512; idx += 256) {
            int r = idx >> 3, k4 = idx & 7;
            int row = i0 + r;
            float4 v = make_float4(0.f, 0.f, 0.f, 0.f);
            if (row < NN) {
                if (INHALF) {
                    uint2 raw = *(const uint2*)((const __half*)Xv + (size_t)row * KTOT + k0 + k4 * 4);
                    float2 a = __half22float2(*(__half2*)&raw.x);
                    float2 b = __half22float2(*(__half2*)&raw.y);
                    v = make_float4(a.x, a.y, b.x, b.y);
                } else {
                    v = *(const float4*)((const float*)Xv + (size_t)row * KTOT + k0 + k4 * 4);
                }
            }
            if (RELU) {
                v.x = fmaxf(v.x, 0.f); v.y = fmaxf(v.y, 0.f);
                v.z = fmaxf(v.z, 0.f); v.w = fmaxf(v.w, 0.f);
            }
            As[k4 * 4 + 0][r] = v.x; As[k4 * 4 + 1][r] = v.y;
            As[k4 * 4 + 2][r] = v.z; As[k4 * 4 + 3][r] = v.w;
        }
        for (int idx = tid; idx < 8 * COLS; idx += 256) {
            int j4 = idx % (COLS / 4), kk = idx / (COLS / 4);
            float4 w = *(const float4*)&W[(size_t)(k0 + kk) * FOUT + cb + j4 * 4];
            Ws[kk][j4 * 4 + 0] = w.x; Ws[kk][j4 * 4 + 1] = w.y;
            Ws[kk][j4 * 4 + 2] = w.z; Ws[kk][j4 * 4 + 3] = w.w;
        }
        __syncthreads();
#pragma unroll 4
        for (int k = 0; k < 32; k++) {
            u64 aa[4];
            {
                const ulonglong2* ap = (const ulonglong2*)&As[k][ty * 8];
                ulonglong2 t0 = ap[0], t1 = ap[1];
                aa[0] = t0.x; aa[1] = t0.y; aa[2] = t1.x; aa[3] = t1.y;
            }
            u64 bd[CPT];
            if (CPT == 2) {
                float2 b = *(const float2*)&Ws[k][tx * 2];
                bd[0] = dup2(b.x); bd[1] = dup2(b.y);
            } else {
                bd[0] = dup2(Ws[k][tx]);
            }
#pragma unroll
            for (int r = 0; r < 4; r++)
#pragma unroll
                for (int c = 0; c < CPT; c++) ffma2(acc2[r][c], aa[r], bd[c]);
        }
        __syncthreads();
    }
#pragma unroll
    for (int rp = 0; rp < 4; rp++) {
        int r0 = i0 + ty * 8 + 2 * rp;
        float lo[CPT], hi[CPT];
#pragma unroll
        for (int c = 0; c < CPT; c++) unpk(acc2[rp][c], lo[c], hi[c]);
        if (r0 < NN) {
            if (CPT == 2)
                *(__half2*)&H[(size_t)r0 * FOUT + cb + tx * 2] = __floats2half2_rn(lo[0], lo[1]);
            else
                H[(size_t)r0 * FOUT + cb + tx] = __float2half_rn(lo[0]);
        }
        if (r0 + 1 < NN) {
            if (CPT == 2)
                *(__half2*)&H[(size_t)(r0 + 1) * FOUT + cb + tx * 2] = __floats2half2_rn(hi[0], hi[1]);
            else
                H[(size_t)(r0 + 1) * FOUT + cb + tx] = __float2half_rn(hi[0]);
        }
    }
}

// ---------------- gather (zoff selects graph) ----------------
template <int OUTHALF>
__global__ void k_gather(const __half* __restrict__ H0, const __half* __restrict__ H1,
                         const float* __restrict__ b,
                         void* __restrict__ O0v, void* __restrict__ O1v, int Fout,
                         int zoff) {
    int z = blockIdx.z + zoff;
    const __half* H = z ? H1 : H0;
    int gpf = Fout >> 2;
    int idx = blockIdx.x * 256 + threadIdx.x;
    int node = idx / gpf;
    int c = idx - node * gpf;
    if (node >= NN) return;
    int rs = g_rowstart[z][node], re = g_rowstart[z][node + 1];
    float invdeg = 1.0f / ((float)(re - rs) + 1.0f);
    __half2 h01, h23;
    {
        uint2 raw = *(const uint2*)((const __half*)(H + (size_t)node * Fout) + c * 4);
        h01 = *(__half2*)&raw.x; h23 = *(__half2*)&raw.y;
    }
    float2 f01 = __half22float2(h01), f23 = __half22float2(h23);
    float4 bb = ((const float4*)b)[c];
    float4 acc;
    acc.x = f01.x * invdeg + bb.x; acc.y = f01.y * invdeg + bb.y;
    acc.z = f23.x * invdeg + bb.z; acc.w = f23.y * invdeg + bb.w;
    const int2* __restrict__ adjc = g_adjc[z];
#pragma unroll 4
    for (int e = rs; e < re; e++) {
        int2 sc = __ldg(&adjc[e]);
        float coef = __int_as_float(sc.y);
        uint2 raw = __ldg((const uint2*)(H + (size_t)sc.x * Fout) + c);
        float2 v01 = __half22float2(*(__half2*)&raw.x);
        float2 v23 = __half22float2(*(__half2*)&raw.y);
        acc.x += coef * v01.x; acc.y += coef * v01.y;
        acc.z += coef * v23.x; acc.w += coef * v23.y;
    }
    if (OUTHALF) {
        __half* O = (__half*)(z ? O1v : O0v);
        __half2 h0 = __floats2half2_rn(acc.x, acc.y);
        __half2 h1 = __floats2half2_rn(acc.z, acc.w);
        uint2 o;
        o.x = *(unsigned*)&h0; o.y = *(unsigned*)&h1;
        *(uint2*)(O + (size_t)node * Fout + c * 4) = o;
    } else {
        float* O = (float*)(z ? O1v : O0v);
        ((float4*)(O + (size_t)node * Fout))[c] = acc;
    }
}

// ---------------- fp16 fragment builders (per graph) ----------------
__device__ __forceinline__ float afld(const float* af, int n, int k) {
    return (n < NN) ? af[n * 32 + k] : 0.f;
}
__global__ void k_fragA() {
    int wg = (blockIdx.x * 256 + threadIdx.x) >> 5;
    int lane = threadIdx.x & 31;
    if (wg >= MT_TILES * 2) return;
    int mt = wg >> 1, ks = wg & 1;
    const float* af = g_af[0];
    int r = mt * 16 + (lane >> 2);
    int kb = ks * 16 + (lane & 3) * 2;
    uint4 v;
    v.x = h2pack(afld(af, r,     kb),     afld(af, r,     kb + 1));
    v.y = h2pack(afld(af, r + 8, kb),     afld(af, r + 8, kb + 1));
    v.z = h2pack(afld(af, r,     kb + 8), afld(af, r,     kb + 9));
    v.w = h2pack(afld(af, r + 8, kb + 8), afld(af, r + 8, kb + 9));
    g_fA[(mt * 2 + ks) * 32 + lane] = v;
}
__global__ void k_fragB() {
    int wg = (blockIdx.x * 256 + threadIdx.x) >> 5;
    int lane = threadIdx.x & 31;
    if (wg >= NT_TILES * 2) return;
    int nt = wg >> 1, ks = wg & 1;
    const float* af = g_af[1];
    int n = nt * 8 + (lane >> 2);
    int kb = ks * 16 + (lane & 3) * 2;
    uint2 v;
    v.x = h2pack(afld(af, n, kb),     afld(af, n, kb + 1));
    v.y = h2pack(afld(af, n, kb + 8), afld(af, n, kb + 9));
    g_fB[(nt * 2 + ks) * 32 + lane] = v;
}

// ---------------- similarity passes via fp16 mma ----------------
__global__ void __launch_bounds__(256, 2)
k_simpass(int pass) {
    __shared__ __align__(16) uint2 shB[1024];
    __shared__ unsigned sh[16];
    int tid = threadIdx.x, lane = tid & 31, w = tid >> 5;
    int mt = blockIdx.y * 8 + w;
    int bx = blockIdx.x;
    {
        const uint4* src = (const uint4*)(g_fB + bx * 1024);
        uint4* dst = (uint4*)shB;
#pragma unroll
        for (int i = 0; i < 2; i++) dst[tid + 256 * i] = src[tid + 256 * i];
    }
    if (pass && tid < 16) sh[tid] = 0u;
    __syncthreads();
    uint4 afr[2];
#pragma unroll
    for (int ks = 0; ks < 2; ks++) afr[ks] = g_fA[(mt * 2 + ks) * 32 + lane];
    float c[16][4];
#pragma unroll
    for (int j = 0; j < 16; j++)
#pragma unroll
        for (int r = 0; r < 4; r++) c[j][r] = 0.f;
#pragma unroll
    for (int ks = 0; ks < 2; ks++) {
#pragma unroll
        for (int j = 0; j < 16; j++)
            mma_f16(c[j], afr[ks], shB[(j * 2 + ks) * 32 + lane]);
    }
    int r_lo = mt * 16 + (lane >> 2);
    int r_hi = r_lo + 8;
    int cb = bx * 128 + 2 * (lane & 3);
    bool full = (mt < 625) && (bx < 78);
    if (pass == 0) {
        float lmin = 3.4e38f, lmax = -3.4e38f;
        if (full) {
#pragma unroll
            for (int j = 0; j < 16; j++)
#pragma unroll
                for (int r = 0; r < 4; r++) {
                    lmin = fminf(lmin, c[j][r]);
                    lmax = fmaxf(lmax, c[j][r]);
                }
        } else {
            bool vlo = r_lo < NN, vhi = r_hi < NN;
#pragma unroll
            for (int j = 0; j < 16; j++) {
                int c0 = cb + j * 8;
                bool v0 = c0 < NN, v1 = c0 + 1 < NN;
                if (vlo && v0) { lmin = fminf(lmin, c[j][0]); lmax = fmaxf(lmax, c[j][0]); }
                if (vlo && v1) { lmin = fminf(lmin, c[j][1]); lmax = fmaxf(lmax, c[j][1]); }
                if (vhi && v0) { lmin = fminf(lmin, c[j][2]); lmax = fmaxf(lmax, c[j][2]); }
                if (vhi && v1) { lmin = fminf(lmin, c[j][3]); lmax = fmaxf(lmax, c[j][3]); }
            }
        }
        for (int o = 16; o; o >>= 1) {
            lmin = fminf(lmin, __shfl_down_sync(0xffffffffu, lmin, o));
            lmax = fmaxf(lmax, __shfl_down_sync(0xffffffffu, lmax, o));
        }
        if (lane == 0) {
            atomicMin(&g_keymin, fkey(lmin));
            atomicMax(&g_keymax, fkey(lmax));
        }
    } else {
        float lo_r = fdec(g_keymin), hi_r = fdec(g_keymax);
        float s16 = 16.0f / ((hi_r - lo_r) + 1e-12f);
        float b16 = -lo_r * s16;
        u64 cl = 0ull, ch = 0ull;
        if (full) {
#pragma unroll
            for (int j = 0; j < 16; j++)
#pragma unroll
                for (int r = 0; r < 4; r++) {
                    int b = (int)fmaf(c[j][r], s16, b16);
                    b = min(max(b, 0), 15);
                    if (b < 8) cl += 1ull << (b * 8);
                    else       ch += 1ull << ((b - 8) * 8);
                }
        } else {
            bool vr[2] = {r_lo < NN, r_hi < NN};
#pragma unroll
            for (int j = 0; j < 16; j++) {
                int c0 = cb + j * 8;
                bool vc[2] = {c0 < NN, c0 + 1 < NN};
#pragma unroll
                for (int r = 0; r < 4; r++) {
                    if (!(vr[r >> 1] && vc[r & 1])) continue;
                    int b = (int)fmaf(c[j][r], s16, b16);
                    b = min(max(b, 0), 15);
                    if (b < 8) cl += 1ull << (b * 8);
                    else       ch += 1ull << ((b - 8) * 8);
                }
            }
        }
        const u64 M = 0x00FF00FF00FF00FFull;
        u64 e0 = cl & M, e1 = (cl >> 8) & M;
        u64 e2 = ch & M, e3 = (ch >> 8) & M;
#pragma unroll
        for (int o = 16; o; o >>= 1) {
            e0 += __shfl_down_sync(0xffffffffu, e0, o);
            e1 += __shfl_down_sync(0xffffffffu, e1, o);
            e2 += __shfl_down_sync(0xffffffffu, e2, o);
            e3 += __shfl_down_sync(0xffffffffu, e3, o);
        }
        if (lane == 0) {
#pragma unroll
            for (int i = 0; i < 4; i++) {
                unsigned v0 = (unsigned)((e0 >> (16 * i)) & 0xFFFFull);
                unsigned v1 = (unsigned)((e1 >> (16 * i)) & 0xFFFFull);
                unsigned v2 = (unsigned)((e2 >> (16 * i)) & 0xFFFFull);
                unsigned v3 = (unsigned)((e3 >> (16 * i)) & 0xFFFFull);
                if (v0) atomicAdd(&sh[2 * i], v0);
                if (v1) atomicAdd(&sh[2 * i + 1], v1);
                if (v2) atomicAdd(&sh[8 + 2 * i], v2);
                if (v3) atomicAdd(&sh[9 + 2 * i], v3);
            }
        }
        __syncthreads();
        if (tid < 16 && sh[tid]) atomicAdd(&g_hist[tid * 32], sh[tid]);
    }
}

// ---------------- fused tail (attention + TN) ----------------
__global__ void __launch_bounds__(256, 4)
k_tail(const float* __restrict__ att_w,
       const float* __restrict__ tn_w, const float* __restrict__ tn_wb,
       const float* __restrict__ tn_bias) {
    int bid = blockIdx.x, tid = threadIdx.x;
    int z = bid >= (TAILB / 2);
    int lb = z ? bid - TAILB / 2 : bid;
    int lane = tid & 31;
    int wz = (lb * 256 + tid) >> 5;
    const int nwz = (TAILB / 2) * 256 / 32;
    const float* X = g_af[z];

    {
        float acc = 0.f;
        for (int n = wz; n < NN; n += nwz) acc += X[n * 32 + lane];
        atomicAdd(&g_meanraw[z][lane], acc);
    }
    gridbar(0);
    if (bid == 0 && tid < 64) {
        int g = tid >> 5, j = tid & 31;
        float acc = 0.f;
        const float invN = 1.0f / NN;
        for (int f = 0; f < 32; f++)
            acc += (g_meanraw[g][f] * invN) * att_w[f * 32 + j];
        g_gc[g][j] = tanhf(acc);
    }
    gridbar(1);
    {
        float gcv = g_gc[z][lane];
        float acc = 0.f;
        for (int n = wz; n < NN; n += nwz) {
            float x = X[n * 32 + lane];
            float p = x * gcv;
            for (int o = 16; o; o >>= 1) p += __shfl_xor_sync(0xffffffffu, p, o);
            float sig = 1.0f / (1.0f + expf(-p));
            acc += x * sig;
        }
        atomicAdd(&g_pool[z][lane], acc);
    }
    gridbar(2);
    if (bid == 0) {
        for (int t = tid; t < 1024; t += 256) {
            int slot = t >> 9, r = t & 511, f = r >> 4, k = r & 15;
            const float* e2 = g_pool[1 - slot];
            float acc = tn_wb[k * 64 + f];
            for (int gg = 0; gg < 32; gg++)
                acc += tn_w[f * 512 + gg * 16 + k] * e2[gg];
            g_A[slot][f * 16 + k] = acc;
        }
        if (tid < 32) {
            int sl = tid >> 4, kk = tid & 15;
            const float* e2b = g_pool[1 - sl];
            float cc = tn_bias[kk];
            for (int gg = 0; gg < 32; gg++)
                cc += tn_wb[kk * 64 + 32 + gg] * e2b[gg];
            g_c[sl][kk] = cc;
        }
        __syncthreads();
        if (tid < 16) {
            float a2 = g_c[0][tid];
            for (int f2 = 0; f2 < 32; f2++)
                a2 += g_pool[0][f2] * g_A[0][f2 * 16 + tid];
            g_s0[tid] = fmaxf(a2, 0.f);
        }
    }
    gridbar(3);
    {
        float acc = 0.f;
        for (int n = wz; n < NN; n += nwz) {
            float x = X[n * 32 + lane];
            float v = (lane < 16) ? g_c[z][lane] : 0.f;
#pragma unroll
            for (int f = 0; f < 32; f++) {
                float xf = __shfl_sync(0xffffffffu, x, f);
                if (lane < 16) v += xf * g_A[z][f * 16 + lane];
            }
            if (lane < 16) acc += fmaxf(v, 0.f);
        }
        if (lane < 16) atomicAdd(&g_sAcc[z][lane], acc);
    }
}

// ---------------- final head ----------------
__global__ void k_head(const float* __restrict__ fc1_w, const float* __restrict__ fc1_b,
                       const float* __restrict__ fc2_w, const float* __restrict__ fc2_b,
                       float* __restrict__ out) {
    if (threadIdx.x != 0) return;
    float sc[64];
    const float invN = 1.0f / NN;
    for (int k = 0; k < 16; k++) {
        sc[k]      = g_s0[k];
        sc[16 + k] = g_sAcc[0][k] * invN;
        sc[32 + k] = g_sAcc[1][k] * invN;
    }
    float hf[16], hsum = 0.f;
    for (int b = 0; b < 16; b++) {
        unsigned c = g_hist[b * 32];
        if (c > 16777216u) c = 16777216u;
        hf[b] = (float)c;
        hsum += hf[b];
    }
    for (int b = 0; b < 16; b++) sc[48 + b] = hf[b] / hsum;
    float o2 = fc2_b[0];
    for (int j = 0; j < 16; j++) {
        float a = fc1_b[j];
        for (int i = 0; i < 64; i++) a += sc[i] * fc1_w[i * 16 + j];
        a = fmaxf(a, 0.f);
        o2 += a * fc2_w[j];
    }
    out[0] = 1.0f / (1.0f + expf(-o2));
}

// ---------------- host driver (dual-stream per-graph chains) ----------------
extern "C" void kernel_launch(void* const* d_in, const int* in_sizes, int n_in,
                              void* d_out, int out_size) {
    const float* feat1 = (const float*)d_in[0];
    const float* feat2 = (const float*)d_in[1];
    const int* ei1 = (const int*)d_in[2];
    const int* ei2 = (const int*)d_in[3];
    const float* W1 = (const float*)d_in[4];
    const float* b1 = (const float*)d_in[5];
    const float* W2 = (const float*)d_in[6];
    const float* b2 = (const float*)d_in[7];
    const float* W3 = (const float*)d_in[8];
    const float* b3 = (const float*)d_in[9];
    const float* att_w = (const float*)d_in[10];
    const float* tn_w = (const float*)d_in[11];
    const float* tn_wb = (const float*)d_in[12];
    const float* tn_bias = (const float*)d_in[13];
    const float* fc1_w = (const float*)d_in[14];
    const float* fc1_b = (const float*)d_in[15];
    const float* fc2_w = (const float*)d_in[16];
    const float* fc2_b = (const float*)d_in[17];
    float* out = (float*)d_out;

    __half *H0, *H1, *X0, *X1;
    float *af0, *af1;
    cudaGetSymbolAddress((void**)&H0, g_Hh);  H1 = H0 + NN * 128;
    cudaGetSymbolAddress((void**)&X0, g_Xh);  X1 = X0 + NN * 128;
    cudaGetSymbolAddress((void**)&af0, g_af); af1 = af0 + NN * 32;

    static cudaStream_t sB = nullptr;
    static cudaEvent_t evStart, evT1, evCSR, evG0af, evFragB, evTail;
    if (!sB) {
        cudaStreamCreateWithFlags(&sB, cudaStreamNonBlocking);
        cudaEventCreateWithFlags(&evStart, cudaEventDisableTiming);
        cudaEventCreateWithFlags(&evT1, cudaEventDisableTiming);
        cudaEventCreateWithFlags(&evCSR, cudaEventDisableTiming);
        cudaEventCreateWithFlags(&evG0af, cudaEventDisableTiming);
        cudaEventCreateWithFlags(&evFragB, cudaEventDisableTiming);
        cudaEventCreateWithFlags(&evTail, cudaEventDisableTiming);
    }

    dim3 gGemm1((NN + 63) / 64, 2, 2);   // layer-1, both graphs
    dim3 gGemm2((NN + 63) / 64, 1, 1);   // per-graph
    dim3 gGath1((NN * 32 + 255) / 256, 1, 1);
    dim3 gGath2((NN * 16 + 255) / 256, 1, 1);
    dim3 gGath3((NN * 8 + 255) / 256, 1, 1);

    // fork 1: layer-1 GEMM (both graphs) on sB, CSR on main
    cudaEventRecord(evStart, 0);
    cudaStreamWaitEvent(sB, evStart, 0);
    k_tgemm<128, 128, 0, 0><<<gGemm1, 256, 0, sB>>>(feat1, feat2, W1, H0, H1, 0);
    cudaEventRecord(evT1, sB);

    k_reset<<<1, 1024>>>();
    k_indeg<<<(EE + 255) / 256, 256>>>(ei1, ei2);
    {
        dim3 sg(10, 2);
        k_scanA<<<sg, 1024>>>();
    }
    k_scanBC<<<2, 1024>>>();
    k_fill<<<(EE + 255) / 256, 256>>>(ei1, ei2);
    cudaEventRecord(evCSR, 0);

    // graph-0 chain on main (needs tgemm1 done)
    cudaStreamWaitEvent(0, evT1, 0);
    k_gather<1><<<gGath1, 256>>>(H0, H1, b1, X0, X1, 128, 0);
    k_tgemm<64, 128, 1, 1><<<gGemm2, 256>>>(X0, X1, W2, H0, H1, 0);
    k_gather<1><<<gGath2, 256>>>(H0, H1, b2, X0, X1, 64, 0);
    k_tgemm<32, 64, 1, 1><<<gGemm2, 256>>>(X0, X1, W3, H0, H1, 0);
    k_gather<0><<<gGath3, 256>>>(H0, H1, b3, af0, af1, 32, 0);
    cudaEventRecord(evG0af, 0);
    k_fragA<<<(MT_TILES * 2 * 32 + 255) / 256, 256>>>();

    // graph-1 chain on sB (needs CSR done; tgemm1 already on sB)
    cudaStreamWaitEvent(sB, evCSR, 0);
    k_gather<1><<<gGath1, 256, 0, sB>>>(H0, H1, b1, X0, X1, 128, 1);
    k_tgemm<64, 128, 1, 1><<<gGemm2, 256, 0, sB>>>(X0, X1, W2, H0, H1, 1);
    k_gather<1><<<gGath2, 256, 0, sB>>>(H0, H1, b2, X0, X1, 64, 1);
    k_tgemm<32, 64, 1, 1><<<gGemm2, 256, 0, sB>>>(X0, X1, W3, H0, H1, 1);
    k_gather<0><<<gGath3, 256, 0, sB>>>(H0, H1, b3, af0, af1, 32, 1);
    k_fragB<<<(NT_TILES * 2 * 32 + 255) / 256, 256, 0, sB>>>();
    cudaEventRecord(evFragB, sB);

    // tail on sB (needs af0 + af1)
    cudaStreamWaitEvent(sB, evG0af, 0);
    k_tail<<<TAILB, 256, 0, sB>>>(att_w, tn_w, tn_wb, tn_bias);
    cudaEventRecord(evTail, sB);

    // simpass on main (needs fragA [main] + fragB [sB])
    cudaStreamWaitEvent(0, evFragB, 0);
    dim3 hgrid((NN + 127) / 128, (NN + 127) / 128);
    k_simpass<<<hgrid, 256>>>(0);
    k_simpass<<<hgrid, 256>>>(1);

    // join
    cudaStreamWaitEvent(0, evTail, 0);
    k_head<<<1, 32>>>(fc1_w, fc1_b, fc2_w, fc2_b, out);
}